// round 1
// baseline (speedup 1.0000x reference)
#include <cuda_runtime.h>
#include <cstdint>
#include <math.h>

// Problem constants
#define NQ    512
#define TQ    48
#define TS    49        // T+1 steps
#define VOCAB 32000
#define EMBED 1024
#define HID   1024
#define IMG   4096
#define G4    4096      // 4*HID

// Scratch (device globals: no allocation allowed)
__device__ float g_X[TS * NQ * EMBED];            // [49,512,1024] input sequence
__device__ float g_Xg[TS * NQ * G4];              // [49,512,4096] x@W_ih^T + biases
__device__ float g_gates[NQ * G4];                // per-step gates
__device__ float g_h[NQ * HID];
__device__ float g_c[NQ * HID];

// ---------- packed f32x2 helpers (FFMA2) ----------
__device__ __forceinline__ unsigned long long pk2(float x, float y) {
    unsigned long long r;
    asm("mov.b64 %0, {%1, %2};" : "=l"(r) : "f"(x), "f"(y));
    return r;
}
__device__ __forceinline__ void ffma2(unsigned long long &c, unsigned long long a,
                                      unsigned long long b) {
    asm("fma.rn.f32x2 %0, %1, %2, %0;" : "+l"(c) : "l"(a), "l"(b));
}
__device__ __forceinline__ float2 unpk2(unsigned long long v) {
    float lo, hi;
    asm("mov.b64 {%0, %1}, %2;" : "=f"(lo), "=f"(hi) : "l"(v));
    return make_float2(lo, hi);
}

// ----------------------------------------------------------------------------
// SGEMM: C[M,N] = A[M,K] @ B[N,K]^T (+Cin +bias1[N] +bias2[N])
// Both A and B are K-major (contiguous along K). Requires M%128==0, N%128==0,
// K%16==0 (true for all call sites here).
// 128x128 block tile, BK=16, 256 threads, 8x8 per thread, f32x2 packed FMA.
// ----------------------------------------------------------------------------
__global__ __launch_bounds__(256) void sgemm128(
    const float* __restrict__ A, const float* __restrict__ B, float* __restrict__ C,
    int M, int N, int K,
    const float* __restrict__ Cin,
    const float* __restrict__ bias1, const float* __restrict__ bias2)
{
    const int BM = 128, BN = 128, BK = 16;
    __shared__ __align__(16) float As[BK][BM];
    __shared__ __align__(16) float Bs[BK][BN];

    const int bm  = blockIdx.y * BM;
    const int bn  = blockIdx.x * BN;
    const int tid = threadIdx.x;
    const int ty  = tid >> 4;    // 0..15 -> row group
    const int tx  = tid & 15;    // 0..15 -> col group

    // global-load mapping: 512 float4 per operand tile, 2 per thread
    const int f0  = tid;
    const int f1  = tid + 256;
    const int ar0 = f0 >> 2, ac0 = (f0 & 3) * 4;
    const int ar1 = f1 >> 2, ac1 = (f1 & 3) * 4;

    const float* Ab = A + (size_t)bm * K;
    const float* Bb = B + (size_t)bn * K;

    float4 pa0 = *(const float4*)(Ab + (size_t)ar0 * K + ac0);
    float4 pa1 = *(const float4*)(Ab + (size_t)ar1 * K + ac1);
    float4 pb0 = *(const float4*)(Bb + (size_t)ar0 * K + ac0);
    float4 pb1 = *(const float4*)(Bb + (size_t)ar1 * K + ac1);

    unsigned long long acc[8][4];
#pragma unroll
    for (int i = 0; i < 8; i++)
#pragma unroll
        for (int j = 0; j < 4; j++) acc[i][j] = 0ull;

    for (int k0 = 0; k0 < K; k0 += BK) {
        // scatter (transpose) into smem
        As[ac0 + 0][ar0] = pa0.x; As[ac0 + 1][ar0] = pa0.y;
        As[ac0 + 2][ar0] = pa0.z; As[ac0 + 3][ar0] = pa0.w;
        As[ac1 + 0][ar1] = pa1.x; As[ac1 + 1][ar1] = pa1.y;
        As[ac1 + 2][ar1] = pa1.z; As[ac1 + 3][ar1] = pa1.w;
        Bs[ac0 + 0][ar0] = pb0.x; Bs[ac0 + 1][ar0] = pb0.y;
        Bs[ac0 + 2][ar0] = pb0.z; Bs[ac0 + 3][ar0] = pb0.w;
        Bs[ac1 + 0][ar1] = pb1.x; Bs[ac1 + 1][ar1] = pb1.y;
        Bs[ac1 + 2][ar1] = pb1.z; Bs[ac1 + 3][ar1] = pb1.w;
        __syncthreads();

        if (k0 + BK < K) {  // prefetch next tile into registers
            pa0 = *(const float4*)(Ab + (size_t)ar0 * K + (k0 + BK + ac0));
            pa1 = *(const float4*)(Ab + (size_t)ar1 * K + (k0 + BK + ac1));
            pb0 = *(const float4*)(Bb + (size_t)ar0 * K + (k0 + BK + ac0));
            pb1 = *(const float4*)(Bb + (size_t)ar1 * K + (k0 + BK + ac1));
        }

#pragma unroll
        for (int kk = 0; kk < BK; kk++) {
            float4 a0 = *(const float4*)&As[kk][ty * 8];
            float4 a1 = *(const float4*)&As[kk][ty * 8 + 4];
            float4 b0 = *(const float4*)&Bs[kk][tx * 8];
            float4 b1 = *(const float4*)&Bs[kk][tx * 8 + 4];
            unsigned long long bb[4] = { pk2(b0.x, b0.y), pk2(b0.z, b0.w),
                                         pk2(b1.x, b1.y), pk2(b1.z, b1.w) };
            float av[8] = { a0.x, a0.y, a0.z, a0.w, a1.x, a1.y, a1.z, a1.w };
#pragma unroll
            for (int i = 0; i < 8; i++) {
                unsigned long long aa = pk2(av[i], av[i]);
#pragma unroll
                for (int j = 0; j < 4; j++) ffma2(acc[i][j], aa, bb[j]);
            }
        }
        __syncthreads();
    }

    // epilogue
    const int row0 = bm + ty * 8;
    const int col0 = bn + tx * 8;
#pragma unroll
    for (int i = 0; i < 8; i++) {
        size_t rbase = (size_t)(row0 + i) * N + col0;
#pragma unroll
        for (int j = 0; j < 4; j++) {
            float2 v = unpk2(acc[i][j]);
            if (Cin) {
                float2 ci = *(const float2*)&Cin[rbase + 2 * j];
                v.x += ci.x; v.y += ci.y;
            }
            if (bias1) { v.x += bias1[col0 + 2 * j]; v.y += bias1[col0 + 2 * j + 1]; }
            if (bias2) { v.x += bias2[col0 + 2 * j]; v.y += bias2[col0 + 2 * j + 1]; }
            *(float2*)&C[rbase + 2 * j] = v;
        }
    }
}

// Gather embedding rows into X[t] for t=1..48 (X[0] is filled by the img GEMM)
__global__ void gather_emb(const int* __restrict__ q, const float* __restrict__ emb)
{
    int row = blockIdx.x;              // 0 .. 48*512-1
    int t = row / NQ + 1;
    int n = row % NQ;
    int qi = q[n * TQ + (t - 1)];
    const float4* src = (const float4*)(emb + (size_t)qi * EMBED);
    float4* dst = (float4*)(g_X + ((size_t)t * NQ + n) * EMBED);
    dst[threadIdx.x] = src[threadIdx.x];   // 256 threads * float4 = 1024 floats
}

__global__ void zero_hc()
{
    int i = blockIdx.x * blockDim.x + threadIdx.x;   // < 512*1024
    g_h[i] = 0.f;
    g_c[i] = 0.f;
}

// LSTM cell elementwise: gates -> (c,h), store h to hidden_states output
__global__ void lstm_cell(float* __restrict__ hs_out, int t)
{
    int idx = blockIdx.x * blockDim.x + threadIdx.x;   // < 512*1024
    int n = idx >> 10;
    int k = idx & 1023;
    const float* g = g_gates + (size_t)n * G4;
    float gi = g[k];
    float gf = g[HID + k];
    float gg = g[2 * HID + k];
    float go = g[3 * HID + k];
    float i = 1.f / (1.f + expf(-gi));
    float f = 1.f / (1.f + expf(-gf));
    float gt = tanhf(gg);
    float o = 1.f / (1.f + expf(-go));
    float c = f * g_c[idx] + i * gt;
    g_c[idx] = c;
    float h = o * tanhf(c);
    g_h[idx] = h;
    hs_out[((size_t)n * TS + t) * HID + k] = h;   // [N, T+1, H]
}

extern "C" void kernel_launch(void* const* d_in, const int* in_sizes, int n_in,
                              void* d_out, int out_size)
{
    (void)in_sizes; (void)n_in; (void)out_size;
    const int*   questions = (const int*)  d_in[0];
    const float* img       = (const float*)d_in[1];
    const float* emb       = (const float*)d_in[2];
    const float* W_img     = (const float*)d_in[3];
    const float* b_img     = (const float*)d_in[4];
    const float* W_ih      = (const float*)d_in[5];
    const float* W_hh      = (const float*)d_in[6];
    const float* b_ih      = (const float*)d_in[7];
    const float* b_hh      = (const float*)d_in[8];
    const float* W_out     = (const float*)d_in[9];
    const float* b_out     = (const float*)d_in[10];
    // d_in[11] = first_words (always 1 per dataset)

    float* out_logits = (float*)d_out;                        // [512, 32000]
    float* out_hs     = out_logits + (size_t)NQ * VOCAB;      // [512, 49, 1024]

    float *X, *Xg, *gates, *h;
    cudaGetSymbolAddress((void**)&X,     g_X);
    cudaGetSymbolAddress((void**)&Xg,    g_Xg);
    cudaGetSymbolAddress((void**)&gates, g_gates);
    cudaGetSymbolAddress((void**)&h,     g_h);

    // 1. X[1..48] = emb[questions]
    gather_emb<<<TQ * NQ, 256>>>(questions, emb);

    // 2. X[0] = emb_i = img @ W_img^T + b_img      (M=512, N=1024, K=4096)
    {
        dim3 grid(EMBED / 128, NQ / 128);
        sgemm128<<<grid, 256>>>(img, W_img, X, NQ, EMBED, IMG,
                                nullptr, b_img, nullptr);
    }

    // 3. Xg = X @ W_ih^T + b_ih + b_hh             (M=25088, N=4096, K=1024)
    {
        dim3 grid(G4 / 128, (TS * NQ) / 128);
        sgemm128<<<grid, 256>>>(X, W_ih, Xg, TS * NQ, G4, EMBED,
                                nullptr, b_ih, b_hh);
    }

    // 4. h = c = 0
    zero_hc<<<(NQ * HID) / 256, 256>>>();

    // 5. recurrence
    {
        dim3 grid(G4 / 128, NQ / 128);   // (32, 4) = 128 CTAs, one wave
        for (int t = 0; t < TS; t++) {
            sgemm128<<<grid, 256>>>(h, W_hh, gates, NQ, G4, HID,
                                    Xg + (size_t)t * NQ * G4, nullptr, nullptr);
            lstm_cell<<<(NQ * HID) / 256, 256>>>(out_hs, t);
        }
    }

    // 6. logits = h_last @ W_out^T + b_out         (M=512, N=32000, K=1024)
    {
        dim3 grid(VOCAB / 128, NQ / 128);
        sgemm128<<<grid, 256>>>(h, W_out, out_logits, NQ, VOCAB, HID,
                                nullptr, b_out, nullptr);
    }
}

// round 6
// speedup vs baseline: 2.4894x; 2.4894x over previous
#include <cuda_runtime.h>
#include <cstdint>
#include <math.h>

typedef unsigned short u16;
typedef unsigned int   u32;
typedef unsigned long long u64;

// Problem constants
#define NQ    512
#define TQ    48
#define TS    49        // T+1 steps
#define VOCAB 32000
#define EMBED 1024
#define HID   1024
#define IMG   4096
#define G4    4096      // 4*HID

// ===================== scratch (device globals; no allocs allowed) ==========
__device__ u16  g_Xhi [TS * NQ * EMBED];     // split-bf16 input sequence
__device__ u16  g_Xlo [TS * NQ * EMBED];
__device__ u16  g_imgh[NQ * IMG],    g_imgl[NQ * IMG];
__device__ u16  g_Wimgh[HID * IMG],  g_Wimgl[HID * IMG];
__device__ u16  g_Wihh[G4 * EMBED],  g_Wihl[G4 * EMBED];
__device__ u16  g_Whhh[G4 * HID],    g_Whhl[G4 * HID];
__device__ u16  g_Wouth[VOCAB * HID], g_Woutl[VOCAB * HID];
__device__ u16  g_hh[NQ * HID],      g_hl[NQ * HID];
__device__ float g_Xg[TS * NQ * G4];         // x@W_ih^T + b_ih + b_hh
__device__ float g_gates[NQ * G4];
__device__ float g_c[NQ * HID];

// ===================== PTX helpers =====================
__device__ __forceinline__ u32 smem_to_u32(const void* p) {
    u32 a;
    asm("{ .reg .u64 t; cvta.to.shared.u64 t, %1; cvt.u32.u64 %0, t; }"
        : "=r"(a) : "l"(p));
    return a;
}

#define CP16(dst, src) \
    asm volatile("cp.async.cg.shared.global [%0], [%1], 16;" \
        :: "r"(dst), "l"(src) : "memory")
#define CP_COMMIT() asm volatile("cp.async.commit_group;" ::: "memory")
#define CP_WAIT2()  asm volatile("cp.async.wait_group 2;" ::: "memory")

#define LDSM4(r, addr) \
    asm volatile("ldmatrix.sync.aligned.m8n8.x4.shared.b16 {%0,%1,%2,%3}, [%4];" \
        : "=r"((r)[0]), "=r"((r)[1]), "=r"((r)[2]), "=r"((r)[3]) : "r"(addr))

#define MMA_BF16(d, a, b0, b1) \
    asm volatile("mma.sync.aligned.m16n8k16.row.col.f32.bf16.bf16.f32 " \
        "{%0,%1,%2,%3}, {%4,%5,%6,%7}, {%8,%9}, {%0,%1,%2,%3};" \
        : "+f"((d)[0]), "+f"((d)[1]), "+f"((d)[2]), "+f"((d)[3]) \
        : "r"((a)[0]), "r"((a)[1]), "r"((a)[2]), "r"((a)[3]), "r"(b0), "r"(b1))

// split helpers: hi = truncated top-16 bits (exact), lo = rn_bf16(x - hi)
__device__ __forceinline__ u32 hi_pack(float x, float y) {
    u32 bx = __float_as_uint(x), by = __float_as_uint(y), h;
    asm("prmt.b32 %0, %1, %2, 0x7632;" : "=r"(h) : "r"(bx), "r"(by));
    return h;  // (hi(y)<<16)|hi(x)
}
__device__ __forceinline__ u32 lo_pack(float x, float y) {
    float lx = x - __uint_as_float(__float_as_uint(x) & 0xFFFF0000u);
    float ly = y - __uint_as_float(__float_as_uint(y) & 0xFFFF0000u);
    u32 l;
    asm("cvt.rn.bf16x2.f32 %0, %1, %2;" : "=r"(l) : "f"(ly), "f"(lx));
    return l;
}

// ============================================================================
// bf16 split GEMM: C[M,N] = A[M,K] @ B[N,K]^T (+Cin +bias1 +bias2)
//   A given as Ahi/Alo bf16 [M][K], B as Bhi/Blo bf16 [N][K] (K-major).
//   3 MMAs: Ah*Bh + Ah*Bl + Al*Bh (fp32 accum). M%128==0, N%128==0, K%64==0.
//   Optionally also emits split-bf16 of the result (Chi/Clo) for chained GEMMs.
// 128x128 tile, BK=64, 256 threads (8 warps, each 64x32), 3-stage cp.async.
// SMEM per stage (64KB): Ahi,Alo,Bhi,Blo each 128 rows x 128B, SW128-swizzled.
// ============================================================================
#define TG_SMEM (3 * 4 * 16384)

__global__ __launch_bounds__(256) void tgemm(
    const u16* __restrict__ Ahi, const u16* __restrict__ Alo,
    const u16* __restrict__ Bhi, const u16* __restrict__ Blo,
    float* __restrict__ C, u16* __restrict__ Chi, u16* __restrict__ Clo,
    int M, int N, int K,
    const float* __restrict__ Cin,
    const float* __restrict__ bias1, const float* __restrict__ bias2)
{
    extern __shared__ char smem[];
    const u32 sb = smem_to_u32(smem);
    const int tid = threadIdx.x;
    const int wid = tid >> 5;
    const int lid = tid & 31;
    const int warp_m = wid & 1;     // 2 warps over M
    const int warp_n = wid >> 1;    // 4 warps over N
    const int bm = blockIdx.y * 128;
    const int bn = blockIdx.x * 128;

    // per-lane ldmatrix constants
    const int lrow8 = (lid & 7) + ((lid >> 3) & 1) * 8;  // row within 16-tile
    const u32 kl = ((lid >> 4) & 1) * 16;                // k-byte lane offset
    u32 aoff[4], axor[4], boff[2], bxor[2];
#pragma unroll
    for (int mt = 0; mt < 4; mt++) {
        int r = warp_m * 64 + mt * 16 + lrow8;
        aoff[mt] = (u32)r * 128;
        axor[mt] = (u32)(r & 7) << 4;
    }
#pragma unroll
    for (int p = 0; p < 2; p++) {
        int r = warp_n * 32 + p * 16 + lrow8;
        boff[p] = (u32)r * 128;
        bxor[p] = (u32)(r & 7) << 4;
    }

    float acc[4][4][4];
#pragma unroll
    for (int i = 0; i < 4; i++)
#pragma unroll
        for (int j = 0; j < 4; j++)
#pragma unroll
            for (int k = 0; k < 4; k++) acc[i][j][k] = 0.f;

    // async loader for one stage
    auto issue = [&](int buf, int c) {
        const u32 s0 = sb + (u32)buf * 65536;
        const int k0 = c * 64;
#pragma unroll
        for (int p = 0; p < 4; p++) {
            int ch  = tid + p * 256;         // 0..1023
            int row = ch >> 3;
            int seg = ch & 7;
            u32 doff = (u32)row * 128 + (((u32)seg * 16) ^ ((u32)(row & 7) << 4));
            size_t ai = (size_t)(bm + row) * K + k0 + seg * 8;
            size_t bi = (size_t)(bn + row) * K + k0 + seg * 8;
            CP16(s0 +         doff, Ahi + ai);
            CP16(s0 + 16384 + doff, Alo + ai);
            CP16(s0 + 32768 + doff, Bhi + bi);
            CP16(s0 + 49152 + doff, Blo + bi);
        }
    };

    const int nch = K >> 6;
    issue(0, 0); CP_COMMIT();
    issue(1, 1); CP_COMMIT();

    for (int c = 0; c < nch; c++) {
        if (c + 2 < nch) issue((c + 2) % 3, c + 2);
        CP_COMMIT();
        CP_WAIT2();
        __syncthreads();

        const u32 s0  = sb + (u32)(c % 3) * 65536;
        const u32 sAh = s0, sAl = s0 + 16384, sBh = s0 + 32768, sBl = s0 + 49152;
#pragma unroll
        for (int ks = 0; ks < 4; ks++) {
            const u32 kb = (u32)ks * 32 + kl;
            u32 Ah[4][4], Al[4][4];
#pragma unroll
            for (int mt = 0; mt < 4; mt++) {
                u32 o = aoff[mt] + (kb ^ axor[mt]);
                LDSM4(Ah[mt], sAh + o);
                LDSM4(Al[mt], sAl + o);
            }
            u32 Bh[2][4], Bl[2][4];
#pragma unroll
            for (int p = 0; p < 2; p++) {
                u32 o = boff[p] + (kb ^ bxor[p]);
                LDSM4(Bh[p], sBh + o);
                LDSM4(Bl[p], sBl + o);
            }
#pragma unroll
            for (int mt = 0; mt < 4; mt++)
#pragma unroll
                for (int nt = 0; nt < 4; nt++) {
                    const int p = nt >> 1, q = nt & 1;
                    MMA_BF16(acc[mt][nt], Ah[mt], Bh[p][q], Bh[p][q + 2]);
                    MMA_BF16(acc[mt][nt], Ah[mt], Bl[p][q], Bl[p][q + 2]);
                    MMA_BF16(acc[mt][nt], Al[mt], Bh[p][q], Bh[p][q + 2]);
                }
        }
        __syncthreads();   // guard stage buffer reuse by next issue()
    }

    // ---------------- epilogue (register -> global) ----------------
    const int rl = lid >> 2;            // 0..7
    const int cl = (lid & 3) * 2;       // 0,2,4,6
#pragma unroll
    for (int mt = 0; mt < 4; mt++) {
#pragma unroll
        for (int nt = 0; nt < 4; nt++) {
            const int row0 = bm + warp_m * 64 + mt * 16 + rl;
            const int col  = bn + warp_n * 32 + nt * 8 + cl;
#pragma unroll
            for (int half = 0; half < 2; half++) {
                const int row = row0 + half * 8;
                float vx = acc[mt][nt][half * 2];
                float vy = acc[mt][nt][half * 2 + 1];
                const size_t gi = (size_t)row * N + col;
                if (Cin) { float2 c2 = *(const float2*)(Cin + gi); vx += c2.x; vy += c2.y; }
                if (bias1) { float2 b2 = *(const float2*)(bias1 + col); vx += b2.x; vy += b2.y; }
                if (bias2) { float2 b2 = *(const float2*)(bias2 + col); vx += b2.x; vy += b2.y; }
                if (C) *(float2*)(C + gi) = make_float2(vx, vy);
                if (Chi) {
                    *(u32*)(Chi + gi) = hi_pack(vx, vy);
                    *(u32*)(Clo + gi) = lo_pack(vx, vy);
                }
            }
        }
    }
}

// ===================== small kernels =====================
// generic fp32 -> (hi,lo) bf16 split; n must be a multiple of 4
__global__ void conv_split(const float* __restrict__ x, u16* __restrict__ hi,
                           u16* __restrict__ lo, int n4)
{
    int i = blockIdx.x * blockDim.x + threadIdx.x;
    if (i >= n4) return;
    float4 v = ((const float4*)x)[i];
    ((uint2*)hi)[i] = make_uint2(hi_pack(v.x, v.y), hi_pack(v.z, v.w));
    ((uint2*)lo)[i] = make_uint2(lo_pack(v.x, v.y), lo_pack(v.z, v.w));
}

// gather embedding rows, splitting to bf16 hi/lo, for t = 1..48
__global__ void gather_emb(const int* __restrict__ q, const float* __restrict__ emb)
{
    int row = blockIdx.x;              // 0 .. 48*512-1
    int t = row / NQ + 1;
    int n = row % NQ;
    int qi = q[n * TQ + (t - 1)];
    float4 v = ((const float4*)(emb + (size_t)qi * EMBED))[threadIdx.x];
    size_t base4 = ((size_t)t * NQ + n) * (EMBED / 4) + threadIdx.x;
    ((uint2*)g_Xhi)[base4] = make_uint2(hi_pack(v.x, v.y), hi_pack(v.z, v.w));
    ((uint2*)g_Xlo)[base4] = make_uint2(lo_pack(v.x, v.y), lo_pack(v.z, v.w));
}

__global__ void zero_hc()
{
    int i = blockIdx.x * blockDim.x + threadIdx.x;   // < 512*1024
    g_c[i] = 0.f;
    g_hh[i] = 0;
    g_hl[i] = 0;
}

// LSTM cell elementwise: gates -> (c,h); h written fp32 (hidden_states output)
// and as split-bf16 (next GEMM's A operand).
__global__ void lstm_cell(float* __restrict__ hs_out, int t)
{
    int idx = blockIdx.x * blockDim.x + threadIdx.x;   // < 512*1024
    int n = idx >> 10;
    int k = idx & 1023;
    const float* g = g_gates + (size_t)n * G4;
    float gi = g[k];
    float gf = g[HID + k];
    float gg = g[2 * HID + k];
    float go = g[3 * HID + k];
    float i = 1.f / (1.f + expf(-gi));
    float f = 1.f / (1.f + expf(-gf));
    float gt = tanhf(gg);
    float o = 1.f / (1.f + expf(-go));
    float c = f * g_c[idx] + i * gt;
    g_c[idx] = c;
    float h = o * tanhf(c);
    hs_out[((size_t)n * TS + t) * HID + k] = h;   // [N, T+1, H]
    u32 hb = __float_as_uint(h);
    g_hh[idx] = (u16)(hb >> 16);
    float lof = h - __uint_as_float(hb & 0xFFFF0000u);
    u32 lp;
    asm("cvt.rn.bf16x2.f32 %0, %1, %2;" : "=r"(lp) : "f"(lof), "f"(lof));
    g_hl[idx] = (u16)(lp & 0xFFFF);
}

// ===================== host =====================
extern "C" void kernel_launch(void* const* d_in, const int* in_sizes, int n_in,
                              void* d_out, int out_size)
{
    (void)in_sizes; (void)n_in; (void)out_size;
    const int*   questions = (const int*)  d_in[0];
    const float* img       = (const float*)d_in[1];
    const float* emb       = (const float*)d_in[2];
    const float* W_img     = (const float*)d_in[3];
    const float* b_img     = (const float*)d_in[4];
    const float* W_ih      = (const float*)d_in[5];
    const float* W_hh      = (const float*)d_in[6];
    const float* b_ih      = (const float*)d_in[7];
    const float* b_hh      = (const float*)d_in[8];
    const float* W_out     = (const float*)d_in[9];
    const float* b_out     = (const float*)d_in[10];

    float* out_logits = (float*)d_out;                        // [512, 32000]
    float* out_hs     = out_logits + (size_t)NQ * VOCAB;      // [512, 49, 1024]

    u16 *Xhi, *Xlo, *imgh, *imgl, *Wimgh, *Wimgl, *Wihh, *Wihl, *Whhh, *Whhl,
        *Wouth, *Woutl, *hh, *hl;
    float *Xg, *gates;
    cudaGetSymbolAddress((void**)&Xhi,   g_Xhi);
    cudaGetSymbolAddress((void**)&Xlo,   g_Xlo);
    cudaGetSymbolAddress((void**)&imgh,  g_imgh);
    cudaGetSymbolAddress((void**)&imgl,  g_imgl);
    cudaGetSymbolAddress((void**)&Wimgh, g_Wimgh);
    cudaGetSymbolAddress((void**)&Wimgl, g_Wimgl);
    cudaGetSymbolAddress((void**)&Wihh,  g_Wihh);
    cudaGetSymbolAddress((void**)&Wihl,  g_Wihl);
    cudaGetSymbolAddress((void**)&Whhh,  g_Whhh);
    cudaGetSymbolAddress((void**)&Whhl,  g_Whhl);
    cudaGetSymbolAddress((void**)&Wouth, g_Wouth);
    cudaGetSymbolAddress((void**)&Woutl, g_Woutl);
    cudaGetSymbolAddress((void**)&hh,    g_hh);
    cudaGetSymbolAddress((void**)&hl,    g_hl);
    cudaGetSymbolAddress((void**)&Xg,    g_Xg);
    cudaGetSymbolAddress((void**)&gates, g_gates);

    cudaFuncSetAttribute(tgemm, cudaFuncAttributeMaxDynamicSharedMemorySize,
                         TG_SMEM);   // idempotent; no static guards per rules

    // 0. fp32 -> split-bf16 conversions (one pass over each operand)
    conv_split<<<(NQ * IMG / 4) / 256, 256>>>(img, imgh, imgl, NQ * IMG / 4);
    conv_split<<<(HID * IMG / 4) / 256, 256>>>(W_img, Wimgh, Wimgl, HID * IMG / 4);
    conv_split<<<(G4 * EMBED / 4) / 256, 256>>>(W_ih, Wihh, Wihl, G4 * EMBED / 4);
    conv_split<<<(G4 * HID / 4) / 256, 256>>>(W_hh, Whhh, Whhl, G4 * HID / 4);
    conv_split<<<(VOCAB * HID / 4) / 256, 256>>>(W_out, Wouth, Woutl,
                                                 VOCAB * HID / 4);

    // 1. X[1..48] = emb[questions] (split on the fly)
    gather_emb<<<TQ * NQ, 256>>>(questions, emb);

    // 2. X[0] = img @ W_img^T + b_img          (M=512, N=1024, K=4096)
    //    result emitted directly as split-bf16 rows 0..511 of X
    tgemm<<<dim3(EMBED / 128, NQ / 128), 256, TG_SMEM>>>(
        imgh, imgl, Wimgh, Wimgl, nullptr, Xhi, Xlo,
        NQ, EMBED, IMG, nullptr, b_img, nullptr);

    // 3. Xg = X @ W_ih^T + b_ih + b_hh         (M=25088, N=4096, K=1024)
    tgemm<<<dim3(G4 / 128, (TS * NQ) / 128), 256, TG_SMEM>>>(
        Xhi, Xlo, Wihh, Wihl, Xg, nullptr, nullptr,
        TS * NQ, G4, EMBED, nullptr, b_ih, b_hh);

    // 4. h = c = 0
    zero_hc<<<(NQ * HID) / 256, 256>>>();

    // 5. recurrence: gates = h @ W_hh^T + Xg[t]; then cell
    for (int t = 0; t < TS; t++) {
        tgemm<<<dim3(G4 / 128, NQ / 128), 256, TG_SMEM>>>(
            hh, hl, Whhh, Whhl, gates, nullptr, nullptr,
            NQ, G4, HID, Xg + (size_t)t * NQ * G4, nullptr, nullptr);
        lstm_cell<<<(NQ * HID) / 256, 256>>>(out_hs, t);
    }

    // 6. logits = h_last @ W_out^T + b_out     (M=512, N=32000, K=1024)
    tgemm<<<dim3(VOCAB / 128, NQ / 128), 256, TG_SMEM>>>(
        hh, hl, Wouth, Woutl, out_logits, nullptr, nullptr,
        NQ, VOCAB, HID, nullptr, b_out, nullptr);
}

// round 7
// speedup vs baseline: 2.6353x; 1.0586x over previous
#include <cuda_runtime.h>
#include <cstdint>
#include <math.h>

typedef unsigned short u16;
typedef unsigned int   u32;
typedef unsigned long long u64;

// Problem constants
#define NQ    512
#define TQ    48
#define TS    49        // T+1 steps
#define VOCAB 32000
#define EMBED 1024
#define HID   1024
#define IMG   4096
#define G4    4096      // 4*HID

// ===================== scratch (device globals; no allocs allowed) ==========
__device__ u16  g_Xhi [TS * NQ * EMBED];     // split-bf16 input sequence
__device__ u16  g_Xlo [TS * NQ * EMBED];
__device__ u16  g_imgh[NQ * IMG],    g_imgl[NQ * IMG];
__device__ u16  g_Wimgh[HID * IMG],  g_Wimgl[HID * IMG];
__device__ u16  g_Wihh[G4 * EMBED],  g_Wihl[G4 * EMBED];   // PERMUTED rows
__device__ u16  g_Whhh[G4 * HID],    g_Whhl[G4 * HID];     // PERMUTED rows
__device__ u16  g_Wouth[VOCAB * HID], g_Woutl[VOCAB * HID];
__device__ u16  g_hh0[NQ * HID], g_hl0[NQ * HID];          // h ping-pong buf 0
__device__ u16  g_hh1[NQ * HID], g_hl1[NQ * HID];          // h ping-pong buf 1
__device__ float g_Xg[TS * NQ * G4];         // x@W_ih^T + pbias (permuted cols)
__device__ float g_pbias[G4];                // permuted b_ih + b_hh
__device__ unsigned g_bar;                   // device-wide barrier counter

// ===================== PTX helpers =====================
__device__ __forceinline__ u32 smem_to_u32(const void* p) {
    u32 a;
    asm("{ .reg .u64 t; cvta.to.shared.u64 t, %1; cvt.u32.u64 %0, t; }"
        : "=r"(a) : "l"(p));
    return a;
}

#define CP16(dst, src) \
    asm volatile("cp.async.cg.shared.global [%0], [%1], 16;" \
        :: "r"(dst), "l"(src) : "memory")
#define CP_COMMIT() asm volatile("cp.async.commit_group;" ::: "memory")
#define CP_WAIT2()  asm volatile("cp.async.wait_group 2;" ::: "memory")

#define LDSM4(r, addr) \
    asm volatile("ldmatrix.sync.aligned.m8n8.x4.shared.b16 {%0,%1,%2,%3}, [%4];" \
        : "=r"((r)[0]), "=r"((r)[1]), "=r"((r)[2]), "=r"((r)[3]) : "r"(addr))

#define MMA_BF16(d, a, b0, b1) \
    asm volatile("mma.sync.aligned.m16n8k16.row.col.f32.bf16.bf16.f32 " \
        "{%0,%1,%2,%3}, {%4,%5,%6,%7}, {%8,%9}, {%0,%1,%2,%3};" \
        : "+f"((d)[0]), "+f"((d)[1]), "+f"((d)[2]), "+f"((d)[3]) \
        : "r"((a)[0]), "r"((a)[1]), "r"((a)[2]), "r"((a)[3]), "r"(b0), "r"(b1))

// split helpers: hi = truncated top-16 bits (exact), lo = rn_bf16(x - hi)
__device__ __forceinline__ u32 hi_pack(float x, float y) {
    u32 bx = __float_as_uint(x), by = __float_as_uint(y), h;
    asm("prmt.b32 %0, %1, %2, 0x7632;" : "=r"(h) : "r"(bx), "r"(by));
    return h;  // (hi(y)<<16)|hi(x)
}
__device__ __forceinline__ u32 lo_pack(float x, float y) {
    float lx = x - __uint_as_float(__float_as_uint(x) & 0xFFFF0000u);
    float ly = y - __uint_as_float(__float_as_uint(y) & 0xFFFF0000u);
    u32 l;
    asm("cvt.rn.bf16x2.f32 %0, %1, %2;" : "=r"(l) : "f"(ly), "f"(lx));
    return l;
}

// Gate-interleave permutation: permuted row p <- original row
//   p = 128*s + 32*q + 8*g + d  <->  orig = g*1024 + (s*32 + q*8 + d)
__device__ __forceinline__ int perm_orig(int p) {
    int s = p >> 7, r = p & 127;
    return ((r >> 3) & 3) * 1024 + s * 32 + (r >> 5) * 8 + (r & 7);
}

// ============================================================================
// bf16 split GEMM: C[M,N] = A[M,K] @ B[N,K]^T (+Cin +bias1)
// 128x128 tile, BK=64, 256 threads (8 warps, each 64x32), 3-stage cp.async.
// SMEM per stage (64KB): Ahi,Alo,Bhi,Blo each 128 rows x 128B, SW128-swizzled.
// ============================================================================
#define TG_SMEM (3 * 4 * 16384)

__global__ __launch_bounds__(256) void tgemm(
    const u16* __restrict__ Ahi, const u16* __restrict__ Alo,
    const u16* __restrict__ Bhi, const u16* __restrict__ Blo,
    float* __restrict__ C, u16* __restrict__ Chi, u16* __restrict__ Clo,
    int M, int N, int K,
    const float* __restrict__ Cin, const float* __restrict__ bias1)
{
    extern __shared__ char smem[];
    const u32 sb = smem_to_u32(smem);
    const int tid = threadIdx.x;
    const int wid = tid >> 5;
    const int lid = tid & 31;
    const int warp_m = wid & 1;     // 2 warps over M
    const int warp_n = wid >> 1;    // 4 warps over N
    const int bm = blockIdx.y * 128;
    const int bn = blockIdx.x * 128;

    const int lrow8 = (lid & 7) + ((lid >> 3) & 1) * 8;
    const u32 kl = ((lid >> 4) & 1) * 16;
    u32 aoff[4], axor[4], boff[2], bxor[2];
#pragma unroll
    for (int mt = 0; mt < 4; mt++) {
        int r = warp_m * 64 + mt * 16 + lrow8;
        aoff[mt] = (u32)r * 128;
        axor[mt] = (u32)(r & 7) << 4;
    }
#pragma unroll
    for (int p = 0; p < 2; p++) {
        int r = warp_n * 32 + p * 16 + lrow8;
        boff[p] = (u32)r * 128;
        bxor[p] = (u32)(r & 7) << 4;
    }

    float acc[4][4][4];
#pragma unroll
    for (int i = 0; i < 4; i++)
#pragma unroll
        for (int j = 0; j < 4; j++)
#pragma unroll
            for (int k = 0; k < 4; k++) acc[i][j][k] = 0.f;

    auto issue = [&](int buf, int c) {
        const u32 s0 = sb + (u32)buf * 65536;
        const int k0 = c * 64;
#pragma unroll
        for (int p = 0; p < 4; p++) {
            int ch  = tid + p * 256;
            int row = ch >> 3;
            int seg = ch & 7;
            u32 doff = (u32)row * 128 + (((u32)seg * 16) ^ ((u32)(row & 7) << 4));
            size_t ai = (size_t)(bm + row) * K + k0 + seg * 8;
            size_t bi = (size_t)(bn + row) * K + k0 + seg * 8;
            CP16(s0 +         doff, Ahi + ai);
            CP16(s0 + 16384 + doff, Alo + ai);
            CP16(s0 + 32768 + doff, Bhi + bi);
            CP16(s0 + 49152 + doff, Blo + bi);
        }
    };

    const int nch = K >> 6;
    issue(0, 0); CP_COMMIT();
    issue(1, 1); CP_COMMIT();

    for (int c = 0; c < nch; c++) {
        if (c + 2 < nch) issue((c + 2) % 3, c + 2);
        CP_COMMIT();
        CP_WAIT2();
        __syncthreads();

        const u32 s0  = sb + (u32)(c % 3) * 65536;
        const u32 sAh = s0, sAl = s0 + 16384, sBh = s0 + 32768, sBl = s0 + 49152;
#pragma unroll
        for (int ks = 0; ks < 4; ks++) {
            const u32 kb = (u32)ks * 32 + kl;
            u32 Ah[4][4], Al[4][4];
#pragma unroll
            for (int mt = 0; mt < 4; mt++) {
                u32 o = aoff[mt] + (kb ^ axor[mt]);
                LDSM4(Ah[mt], sAh + o);
                LDSM4(Al[mt], sAl + o);
            }
            u32 Bh[2][4], Bl[2][4];
#pragma unroll
            for (int p = 0; p < 2; p++) {
                u32 o = boff[p] + (kb ^ bxor[p]);
                LDSM4(Bh[p], sBh + o);
                LDSM4(Bl[p], sBl + o);
            }
#pragma unroll
            for (int mt = 0; mt < 4; mt++)
#pragma unroll
                for (int nt = 0; nt < 4; nt++) {
                    const int p = nt >> 1, q = nt & 1;
                    MMA_BF16(acc[mt][nt], Ah[mt], Bh[p][q], Bh[p][q + 2]);
                    MMA_BF16(acc[mt][nt], Ah[mt], Bl[p][q], Bl[p][q + 2]);
                    MMA_BF16(acc[mt][nt], Al[mt], Bh[p][q], Bh[p][q + 2]);
                }
        }
        __syncthreads();
    }

    const int rl = lid >> 2;
    const int cl = (lid & 3) * 2;
#pragma unroll
    for (int mt = 0; mt < 4; mt++) {
#pragma unroll
        for (int nt = 0; nt < 4; nt++) {
            const int row0 = bm + warp_m * 64 + mt * 16 + rl;
            const int col  = bn + warp_n * 32 + nt * 8 + cl;
#pragma unroll
            for (int half = 0; half < 2; half++) {
                const int row = row0 + half * 8;
                float vx = acc[mt][nt][half * 2];
                float vy = acc[mt][nt][half * 2 + 1];
                const size_t gi = (size_t)row * N + col;
                if (Cin) { float2 c2 = *(const float2*)(Cin + gi); vx += c2.x; vy += c2.y; }
                if (bias1) { float2 b2 = *(const float2*)(bias1 + col); vx += b2.x; vy += b2.y; }
                if (C) *(float2*)(C + gi) = make_float2(vx, vy);
                if (Chi) {
                    *(u32*)(Chi + gi) = hi_pack(vx, vy);
                    *(u32*)(Clo + gi) = lo_pack(vx, vy);
                }
            }
        }
    }
}

// ============================================================================
// Persistent LSTM recurrence: all 49 steps in one kernel.
// grid = 128 CTAs (4 bm-blocks x 32 column strips), 256 threads, 192KB smem.
// B = permuted W_hh (rows 128*s .. 128*s+127 = gates interleaved for strip s).
// Warp q's four n8 tiles are gates i,f,g,o for the same 8 hidden columns ->
// LSTM cell is computed in registers; c lives in registers across all steps;
// h ping-pongs between two global split-bf16 buffers; one device barrier/step.
// ============================================================================
__global__ __launch_bounds__(256) void lstm_persist(const float* __restrict__ Xg,
                                                    float* __restrict__ hs_out)
{
    extern __shared__ char smem[];
    const u32 sb = smem_to_u32(smem);
    const int tid = threadIdx.x;
    const int wid = tid >> 5;
    const int lid = tid & 31;
    const int warp_m = wid & 1;
    const int warp_q = wid >> 1;
    const int bm   = (blockIdx.x & 3) * 128;
    const int sidx = blockIdx.x >> 2;
    const int bn   = sidx * 128;

    const int lrow8 = (lid & 7) + ((lid >> 3) & 1) * 8;
    const u32 kl = ((lid >> 4) & 1) * 16;
    u32 aoff[4], axor[4], boff[2], bxor[2];
#pragma unroll
    for (int mt = 0; mt < 4; mt++) {
        int r = warp_m * 64 + mt * 16 + lrow8;
        aoff[mt] = (u32)r * 128;
        axor[mt] = (u32)(r & 7) << 4;
    }
#pragma unroll
    for (int p = 0; p < 2; p++) {
        int r = warp_q * 32 + p * 16 + lrow8;
        boff[p] = (u32)r * 128;
        bxor[p] = (u32)(r & 7) << 4;
    }
    const int rl = lid >> 2;
    const int cl = (lid & 3) * 2;

    float c_[4][4];
#pragma unroll
    for (int i = 0; i < 4; i++)
#pragma unroll
        for (int j = 0; j < 4; j++) c_[i][j] = 0.f;

    for (int t = 0; t < TS; t++) {
        float acc[4][4][4];
#pragma unroll
        for (int i = 0; i < 4; i++)
#pragma unroll
            for (int j = 0; j < 4; j++)
#pragma unroll
                for (int k = 0; k < 4; k++) acc[i][j][k] = 0.f;

        if (t > 0) {
            // read h(t-1) from buffer (t-1)&1
            const u16* Ahi_ = ((t - 1) & 1) ? g_hh1 : g_hh0;
            const u16* Alo_ = ((t - 1) & 1) ? g_hl1 : g_hl0;

            auto issue = [&](int buf, int c) {
                const u32 s0 = sb + (u32)buf * 65536;
                const int k0 = c * 64;
#pragma unroll
                for (int p = 0; p < 4; p++) {
                    int ch  = tid + p * 256;
                    int row = ch >> 3;
                    int seg = ch & 7;
                    u32 doff = (u32)row * 128 +
                               (((u32)seg * 16) ^ ((u32)(row & 7) << 4));
                    size_t ai = (size_t)(bm + row) * HID + k0 + seg * 8;
                    size_t bi = (size_t)(bn + row) * HID + k0 + seg * 8;
                    CP16(s0 +         doff, Ahi_ + ai);
                    CP16(s0 + 16384 + doff, Alo_ + ai);
                    CP16(s0 + 32768 + doff, g_Whhh + bi);
                    CP16(s0 + 49152 + doff, g_Whhl + bi);
                }
            };

            issue(0, 0); CP_COMMIT();
            issue(1, 1); CP_COMMIT();
#pragma unroll 1
            for (int c = 0; c < 16; c++) {
                if (c + 2 < 16) issue((c + 2) % 3, c + 2);
                CP_COMMIT();
                CP_WAIT2();
                __syncthreads();
                const u32 s0  = sb + (u32)(c % 3) * 65536;
                const u32 sAh = s0, sAl = s0 + 16384,
                          sBh = s0 + 32768, sBl = s0 + 49152;
#pragma unroll
                for (int ks = 0; ks < 4; ks++) {
                    const u32 kb = (u32)ks * 32 + kl;
                    u32 Ah[4][4], Al[4][4];
#pragma unroll
                    for (int mt = 0; mt < 4; mt++) {
                        u32 o = aoff[mt] + (kb ^ axor[mt]);
                        LDSM4(Ah[mt], sAh + o);
                        LDSM4(Al[mt], sAl + o);
                    }
                    u32 Bh[2][4], Bl[2][4];
#pragma unroll
                    for (int p = 0; p < 2; p++) {
                        u32 o = boff[p] + (kb ^ bxor[p]);
                        LDSM4(Bh[p], sBh + o);
                        LDSM4(Bl[p], sBl + o);
                    }
#pragma unroll
                    for (int mt = 0; mt < 4; mt++)
#pragma unroll
                        for (int nt = 0; nt < 4; nt++) {
                            const int p = nt >> 1, q = nt & 1;
                            MMA_BF16(acc[mt][nt], Ah[mt], Bh[p][q], Bh[p][q + 2]);
                            MMA_BF16(acc[mt][nt], Ah[mt], Bl[p][q], Bl[p][q + 2]);
                            MMA_BF16(acc[mt][nt], Al[mt], Bh[p][q], Bh[p][q + 2]);
                        }
                }
                __syncthreads();
            }
        }

        // ---- in-register LSTM cell: acc[mt][gate][e] + Xg -> (c, h) ----
        u16* Hh = (t & 1) ? g_hh1 : g_hh0;
        u16* Hl = (t & 1) ? g_hl1 : g_hl0;
        const int colb = bn + warp_q * 32 + cl;   // permuted col of gate i
        const int kidx = sidx * 32 + warp_q * 8 + cl;  // hidden index (orig)
#pragma unroll
        for (int mt = 0; mt < 4; mt++) {
#pragma unroll
            for (int half = 0; half < 2; half++) {
                const int n = bm + warp_m * 64 + mt * 16 + rl + half * 8;
                const float* xr = Xg + ((size_t)t * NQ + n) * G4 + colb;
                float2 xi = *(const float2*)(xr + 0);
                float2 xf = *(const float2*)(xr + 8);
                float2 xg = *(const float2*)(xr + 16);
                float2 xo = *(const float2*)(xr + 24);
                float hv[2];
#pragma unroll
                for (int cp = 0; cp < 2; cp++) {
                    const int e = half * 2 + cp;
                    float gi = acc[mt][0][e] + (cp ? xi.y : xi.x);
                    float gf = acc[mt][1][e] + (cp ? xf.y : xf.x);
                    float gg = acc[mt][2][e] + (cp ? xg.y : xg.x);
                    float go = acc[mt][3][e] + (cp ? xo.y : xo.x);
                    float i_ = 1.f / (1.f + expf(-gi));
                    float f_ = 1.f / (1.f + expf(-gf));
                    float g_ = tanhf(gg);
                    float o_ = 1.f / (1.f + expf(-go));
                    float cc = f_ * c_[mt][e] + i_ * g_;
                    c_[mt][e] = cc;
                    hv[cp] = o_ * tanhf(cc);
                }
                const size_t hi_ = (size_t)n * HID + kidx;
                *(u32*)(Hh + hi_) = hi_pack(hv[0], hv[1]);
                *(u32*)(Hl + hi_) = lo_pack(hv[0], hv[1]);
                *(float2*)(hs_out + ((size_t)n * TS + t) * HID + kidx) =
                    make_float2(hv[0], hv[1]);
            }
        }

        // ---- device-wide barrier (skip after last step) ----
        if (t < TS - 1) {
            __threadfence();
            __syncthreads();
            if (tid == 0) {
                atomicAdd(&g_bar, 1u);
                const unsigned target = 128u * (unsigned)(t + 1);
                unsigned v;
                do {
                    asm volatile("ld.global.acquire.gpu.b32 %0, [%1];"
                                 : "=r"(v) : "l"(&g_bar));
                    if (v < target) __nanosleep(128);
                } while (v < target);
            }
            __syncthreads();
        }
    }
}

// ===================== small kernels =====================
__global__ void conv_split(const float* __restrict__ x, u16* __restrict__ hi,
                           u16* __restrict__ lo, int n4)
{
    int i = blockIdx.x * blockDim.x + threadIdx.x;
    if (i >= n4) return;
    float4 v = ((const float4*)x)[i];
    ((uint2*)hi)[i] = make_uint2(hi_pack(v.x, v.y), hi_pack(v.z, v.w));
    ((uint2*)lo)[i] = make_uint2(lo_pack(v.x, v.y), lo_pack(v.z, v.w));
}

// split + gate-interleave permute of a [4096][1024] weight (W_ih or W_hh)
__global__ void convp(const float* __restrict__ src, u16* __restrict__ hi,
                      u16* __restrict__ lo)
{
    int p = blockIdx.x;                       // dest (permuted) row
    int orig = perm_orig(p);
    float4 v = ((const float4*)(src + (size_t)orig * 1024))[threadIdx.x];
    size_t o4 = (size_t)p * 256 + threadIdx.x;
    ((uint2*)hi)[o4] = make_uint2(hi_pack(v.x, v.y), hi_pack(v.z, v.w));
    ((uint2*)lo)[o4] = make_uint2(lo_pack(v.x, v.y), lo_pack(v.z, v.w));
}

// gather embedding rows (blocks < TQ*NQ) + build permuted bias (last 16 blocks)
__global__ void gather_emb(const int* __restrict__ q, const float* __restrict__ emb,
                           const float* __restrict__ b_ih,
                           const float* __restrict__ b_hh)
{
    int row = blockIdx.x;
    if (row >= TQ * NQ) {
        int p = (row - TQ * NQ) * 256 + threadIdx.x;   // 0..4095
        int orig = perm_orig(p);
        g_pbias[p] = b_ih[orig] + b_hh[orig];
        return;
    }
    int t = row / NQ + 1;
    int n = row % NQ;
    int qi = q[n * TQ + (t - 1)];
    float4 v = ((const float4*)(emb + (size_t)qi * EMBED))[threadIdx.x];
    size_t base4 = ((size_t)t * NQ + n) * (EMBED / 4) + threadIdx.x;
    ((uint2*)g_Xhi)[base4] = make_uint2(hi_pack(v.x, v.y), hi_pack(v.z, v.w));
    ((uint2*)g_Xlo)[base4] = make_uint2(lo_pack(v.x, v.y), lo_pack(v.z, v.w));
}

__global__ void zero_bar() { g_bar = 0u; }

// ===================== host =====================
extern "C" void kernel_launch(void* const* d_in, const int* in_sizes, int n_in,
                              void* d_out, int out_size)
{
    (void)in_sizes; (void)n_in; (void)out_size;
    const int*   questions = (const int*)  d_in[0];
    const float* img       = (const float*)d_in[1];
    const float* emb       = (const float*)d_in[2];
    const float* W_img     = (const float*)d_in[3];
    const float* b_img     = (const float*)d_in[4];
    const float* W_ih      = (const float*)d_in[5];
    const float* W_hh      = (const float*)d_in[6];
    const float* b_ih      = (const float*)d_in[7];
    const float* b_hh      = (const float*)d_in[8];
    const float* W_out     = (const float*)d_in[9];
    const float* b_out     = (const float*)d_in[10];

    float* out_logits = (float*)d_out;                        // [512, 32000]
    float* out_hs     = out_logits + (size_t)NQ * VOCAB;      // [512, 49, 1024]

    u16 *Xhi, *Xlo, *imgh, *imgl, *Wimgh, *Wimgl, *Wihh, *Wihl, *Whhh, *Whhl,
        *Wouth, *Woutl, *hh0, *hl0;
    float *Xg, *pbias;
    cudaGetSymbolAddress((void**)&Xhi,   g_Xhi);
    cudaGetSymbolAddress((void**)&Xlo,   g_Xlo);
    cudaGetSymbolAddress((void**)&imgh,  g_imgh);
    cudaGetSymbolAddress((void**)&imgl,  g_imgl);
    cudaGetSymbolAddress((void**)&Wimgh, g_Wimgh);
    cudaGetSymbolAddress((void**)&Wimgl, g_Wimgl);
    cudaGetSymbolAddress((void**)&Wihh,  g_Wihh);
    cudaGetSymbolAddress((void**)&Wihl,  g_Wihl);
    cudaGetSymbolAddress((void**)&Whhh,  g_Whhh);
    cudaGetSymbolAddress((void**)&Whhl,  g_Whhl);
    cudaGetSymbolAddress((void**)&Wouth, g_Wouth);
    cudaGetSymbolAddress((void**)&Woutl, g_Woutl);
    cudaGetSymbolAddress((void**)&hh0,   g_hh0);
    cudaGetSymbolAddress((void**)&hl0,   g_hl0);
    cudaGetSymbolAddress((void**)&Xg,    g_Xg);
    cudaGetSymbolAddress((void**)&pbias, g_pbias);

    cudaFuncSetAttribute(tgemm, cudaFuncAttributeMaxDynamicSharedMemorySize,
                         TG_SMEM);
    cudaFuncSetAttribute(lstm_persist,
                         cudaFuncAttributeMaxDynamicSharedMemorySize, TG_SMEM);

    // #0: gather embeddings + permuted bias
    gather_emb<<<TQ * NQ + 16, 256>>>(questions, emb, b_ih, b_hh);

    // #1-3: conversions needed before the two big GEMMs
    conv_split<<<(NQ * IMG / 4 + 255) / 256, 256>>>(img, imgh, imgl, NQ * IMG / 4);
    conv_split<<<(HID * IMG / 4 + 255) / 256, 256>>>(W_img, Wimgh, Wimgl,
                                                     HID * IMG / 4);
    convp<<<G4, 256>>>(W_ih, Wihh, Wihl);   // permuted split W_ih

    // #4: X[0] = img @ W_img^T + b_img (emitted as split-bf16 rows 0..511 of X)
    tgemm<<<dim3(EMBED / 128, NQ / 128), 256, TG_SMEM>>>(
        imgh, imgl, Wimgh, Wimgl, nullptr, Xhi, Xlo,
        NQ, EMBED, IMG, nullptr, b_img);

    // #5 (ncu target): Xg = X @ W_ihP^T + pbias   (permuted gate columns)
    tgemm<<<dim3(G4 / 128, (TS * NQ) / 128), 256, TG_SMEM>>>(
        Xhi, Xlo, Wihh, Wihl, Xg, nullptr, nullptr,
        TS * NQ, G4, EMBED, nullptr, pbias);

    // #6-7: permuted split W_hh; reset device barrier
    convp<<<G4, 256>>>(W_hh, Whhh, Whhl);
    zero_bar<<<1, 1>>>();

    // #8: the whole recurrence in one persistent kernel
    lstm_persist<<<128, 256, TG_SMEM>>>(Xg, out_hs);

    // #9-10: logits = h_last @ W_out^T + b_out  (h_48 lives in buffer 0)
    conv_split<<<(VOCAB * HID / 4 + 255) / 256, 256>>>(W_out, Wouth, Woutl,
                                                       VOCAB * HID / 4);
    tgemm<<<dim3(VOCAB / 128, NQ / 128), 256, TG_SMEM>>>(
        hh0, hl0, Wouth, Woutl, out_logits, nullptr, nullptr,
        NQ, VOCAB, HID, nullptr, b_out);
}

// round 9
// speedup vs baseline: 2.7185x; 1.0316x over previous
#include <cuda_runtime.h>
#include <cstdint>
#include <math.h>

typedef unsigned short u16;
typedef unsigned int   u32;
typedef unsigned long long u64;

// Problem constants
#define NQ    512
#define TQ    48
#define TS    49        // T+1 steps
#define VOCAB 32000
#define EMBED 1024
#define HID   1024
#define IMG   4096
#define G4    4096      // 4*HID

// ===================== scratch (device globals; no allocs allowed) ==========
__device__ u16  g_Xhi [TS * NQ * EMBED];     // split-bf16 input sequence
__device__ u16  g_Xlo [TS * NQ * EMBED];
__device__ u16  g_imgh[NQ * IMG],    g_imgl[NQ * IMG];
__device__ u16  g_Wimgh[HID * IMG],  g_Wimgl[HID * IMG];
__device__ u16  g_Wihh[G4 * EMBED],  g_Wihl[G4 * EMBED];   // PERMUTED rows
__device__ u16  g_Whhh[G4 * HID],    g_Whhl[G4 * HID];     // PERMUTED rows
__device__ u16  g_Wouth[VOCAB * HID], g_Woutl[VOCAB * HID];
__device__ u16  g_hh0[NQ * HID], g_hl0[NQ * HID];          // h ping-pong buf 0
__device__ u16  g_hh1[NQ * HID], g_hl1[NQ * HID];          // h ping-pong buf 1
__device__ float g_Xg[TS * NQ * G4];         // x@W_ih^T + pbias (permuted cols)
__device__ float g_pbias[G4];                // permuted b_ih + b_hh
__device__ unsigned g_bar;                   // device-wide barrier counter

// ===================== PTX helpers =====================
__device__ __forceinline__ u32 smem_to_u32(const void* p) {
    u32 a;
    asm("{ .reg .u64 t; cvta.to.shared.u64 t, %1; cvt.u32.u64 %0, t; }"
        : "=r"(a) : "l"(p));
    return a;
}

#define CP16(dst, src) \
    asm volatile("cp.async.cg.shared.global [%0], [%1], 16;" \
        :: "r"(dst), "l"(src) : "memory")
#define CP_COMMIT() asm volatile("cp.async.commit_group;" ::: "memory")
#define CP_WAIT2()  asm volatile("cp.async.wait_group 2;" ::: "memory")

#define LDSM4(r, addr) \
    asm volatile("ldmatrix.sync.aligned.m8n8.x4.shared.b16 {%0,%1,%2,%3}, [%4];" \
        : "=r"((r)[0]), "=r"((r)[1]), "=r"((r)[2]), "=r"((r)[3]) : "r"(addr))

#define MMA_BF16(d, a, b0, b1) \
    asm volatile("mma.sync.aligned.m16n8k16.row.col.f32.bf16.bf16.f32 " \
        "{%0,%1,%2,%3}, {%4,%5,%6,%7}, {%8,%9}, {%0,%1,%2,%3};" \
        : "+f"((d)[0]), "+f"((d)[1]), "+f"((d)[2]), "+f"((d)[3]) \
        : "r"((a)[0]), "r"((a)[1]), "r"((a)[2]), "r"((a)[3]), "r"(b0), "r"(b1))

// split helpers: hi = truncated top-16 bits (exact), lo = rn_bf16(x - hi)
__device__ __forceinline__ u32 hi_pack(float x, float y) {
    u32 bx = __float_as_uint(x), by = __float_as_uint(y), h;
    asm("prmt.b32 %0, %1, %2, 0x7632;" : "=r"(h) : "r"(bx), "r"(by));
    return h;  // (hi(y)<<16)|hi(x)
}
__device__ __forceinline__ u32 lo_pack(float x, float y) {
    float lx = x - __uint_as_float(__float_as_uint(x) & 0xFFFF0000u);
    float ly = y - __uint_as_float(__float_as_uint(y) & 0xFFFF0000u);
    u32 l;
    asm("cvt.rn.bf16x2.f32 %0, %1, %2;" : "=r"(l) : "f"(ly), "f"(lx));
    return l;
}

// Gate-interleave permutation: permuted row p <- original row
//   p = 128*s + 32*q + 8*g + d  <->  orig = g*1024 + (s*32 + q*8 + d)
__device__ __forceinline__ int perm_orig(int p) {
    int s = p >> 7, r = p & 127;
    return ((r >> 3) & 3) * 1024 + s * 32 + (r >> 5) * 8 + (r & 7);
}

// ============================================================================
// bf16 split GEMM: C[M,N] = A[M,K] @ B[N,K]^T (+Cin +bias1)
// 128x128 tile, BK=32, 256 threads (8 warps, each 64x32), 3-stage cp.async.
// SMEM per stage (32KB): Ahi,Alo,Bhi,Blo each 128 rows x 64B, SW64-swizzled
//   (xor = ((row>>1)&3)<<4 : bijective, conflict-free for ldmatrix).
// 96KB total -> 2 CTAs/SM (16 warps) to hide cp.async/L2 latency.
// ============================================================================
#define TG_SMEM (3 * 4 * 8192)

__global__ __launch_bounds__(256, 2) void tgemm(
    const u16* __restrict__ Ahi, const u16* __restrict__ Alo,
    const u16* __restrict__ Bhi, const u16* __restrict__ Blo,
    float* __restrict__ C, u16* __restrict__ Chi, u16* __restrict__ Clo,
    int M, int N, int K,
    const float* __restrict__ Cin, const float* __restrict__ bias1)
{
    extern __shared__ char smem[];
    const u32 sb = smem_to_u32(smem);
    const int tid = threadIdx.x;
    const int wid = tid >> 5;
    const int lid = tid & 31;
    const int warp_m = wid & 1;     // 2 warps over M
    const int warp_n = wid >> 1;    // 4 warps over N
    const int bm = blockIdx.y * 128;
    const int bn = blockIdx.x * 128;

    const int lrow8 = (lid & 7) + ((lid >> 3) & 1) * 8;
    const u32 kl = ((lid >> 4) & 1) * 16;
    u32 aoff[4], axor[4], boff[2], bxor[2];
#pragma unroll
    for (int mt = 0; mt < 4; mt++) {
        int r = warp_m * 64 + mt * 16 + lrow8;
        aoff[mt] = (u32)r * 64;
        axor[mt] = (u32)((r >> 1) & 3) << 4;
    }
#pragma unroll
    for (int p = 0; p < 2; p++) {
        int r = warp_n * 32 + p * 16 + lrow8;
        boff[p] = (u32)r * 64;
        bxor[p] = (u32)((r >> 1) & 3) << 4;
    }

    float acc[4][4][4];
#pragma unroll
    for (int i = 0; i < 4; i++)
#pragma unroll
        for (int j = 0; j < 4; j++)
#pragma unroll
            for (int k = 0; k < 4; k++) acc[i][j][k] = 0.f;

    // async loader for one 128x32 stage (4 planes of 8KB)
    auto issue = [&](int buf, int c) {
        const u32 s0 = sb + (u32)buf * 32768;
        const int k0 = c * 32;
#pragma unroll
        for (int p = 0; p < 2; p++) {
            int ch  = tid + p * 256;         // 0..511
            int row = ch >> 2;
            int seg = ch & 3;
            u32 doff = (u32)row * 64 +
                       (((u32)seg * 16) ^ ((u32)((row >> 1) & 3) << 4));
            size_t ai = (size_t)(bm + row) * K + k0 + seg * 8;
            size_t bi = (size_t)(bn + row) * K + k0 + seg * 8;
            CP16(s0 +         doff, Ahi + ai);
            CP16(s0 +  8192 + doff, Alo + ai);
            CP16(s0 + 16384 + doff, Bhi + bi);
            CP16(s0 + 24576 + doff, Blo + bi);
        }
    };

    const int nch = K >> 5;
    issue(0, 0); CP_COMMIT();
    issue(1, 1); CP_COMMIT();

    for (int c = 0; c < nch; c++) {
        if (c + 2 < nch) issue((c + 2) % 3, c + 2);
        CP_COMMIT();
        CP_WAIT2();
        __syncthreads();

        const u32 s0  = sb + (u32)(c % 3) * 32768;
        const u32 sAh = s0, sAl = s0 + 8192, sBh = s0 + 16384, sBl = s0 + 24576;
#pragma unroll
        for (int ks = 0; ks < 2; ks++) {
            const u32 kb = (u32)ks * 32 + kl;
            u32 Ah[4][4], Al[4][4];
#pragma unroll
            for (int mt = 0; mt < 4; mt++) {
                u32 o = aoff[mt] + (kb ^ axor[mt]);
                LDSM4(Ah[mt], sAh + o);
                LDSM4(Al[mt], sAl + o);
            }
            u32 Bh[2][4], Bl[2][4];
#pragma unroll
            for (int p = 0; p < 2; p++) {
                u32 o = boff[p] + (kb ^ bxor[p]);
                LDSM4(Bh[p], sBh + o);
                LDSM4(Bl[p], sBl + o);
            }
#pragma unroll
            for (int mt = 0; mt < 4; mt++)
#pragma unroll
                for (int nt = 0; nt < 4; nt++) {
                    const int p = nt >> 1, q = nt & 1;
                    MMA_BF16(acc[mt][nt], Ah[mt], Bh[p][q], Bh[p][q + 2]);
                    MMA_BF16(acc[mt][nt], Ah[mt], Bl[p][q], Bl[p][q + 2]);
                    MMA_BF16(acc[mt][nt], Al[mt], Bh[p][q], Bh[p][q + 2]);
                }
        }
        __syncthreads();
    }

    const int rl = lid >> 2;
    const int cl = (lid & 3) * 2;
#pragma unroll
    for (int mt = 0; mt < 4; mt++) {
#pragma unroll
        for (int nt = 0; nt < 4; nt++) {
            const int row0 = bm + warp_m * 64 + mt * 16 + rl;
            const int col  = bn + warp_n * 32 + nt * 8 + cl;
#pragma unroll
            for (int half = 0; half < 2; half++) {
                const int row = row0 + half * 8;
                float vx = acc[mt][nt][half * 2];
                float vy = acc[mt][nt][half * 2 + 1];
                const size_t gi = (size_t)row * N + col;
                if (Cin) { float2 c2 = *(const float2*)(Cin + gi); vx += c2.x; vy += c2.y; }
                if (bias1) { float2 b2 = *(const float2*)(bias1 + col); vx += b2.x; vy += b2.y; }
                if (C) *(float2*)(C + gi) = make_float2(vx, vy);
                if (Chi) {
                    *(u32*)(Chi + gi) = hi_pack(vx, vy);
                    *(u32*)(Clo + gi) = lo_pack(vx, vy);
                }
            }
        }
    }
}

// ============================================================================
// Persistent LSTM recurrence: all 49 steps in one kernel. (unchanged from R7)
// grid = 128 CTAs (4 bm-blocks x 32 column strips), 256 threads, 192KB smem.
// ============================================================================
#define LP_SMEM (3 * 4 * 16384)

__global__ __launch_bounds__(256) void lstm_persist(const float* __restrict__ Xg,
                                                    float* __restrict__ hs_out)
{
    extern __shared__ char smem[];
    const u32 sb = smem_to_u32(smem);
    const int tid = threadIdx.x;
    const int wid = tid >> 5;
    const int lid = tid & 31;
    const int warp_m = wid & 1;
    const int warp_q = wid >> 1;
    const int bm   = (blockIdx.x & 3) * 128;
    const int sidx = blockIdx.x >> 2;
    const int bn   = sidx * 128;

    const int lrow8 = (lid & 7) + ((lid >> 3) & 1) * 8;
    const u32 kl = ((lid >> 4) & 1) * 16;
    u32 aoff[4], axor[4], boff[2], bxor[2];
#pragma unroll
    for (int mt = 0; mt < 4; mt++) {
        int r = warp_m * 64 + mt * 16 + lrow8;
        aoff[mt] = (u32)r * 128;
        axor[mt] = (u32)(r & 7) << 4;
    }
#pragma unroll
    for (int p = 0; p < 2; p++) {
        int r = warp_q * 32 + p * 16 + lrow8;
        boff[p] = (u32)r * 128;
        bxor[p] = (u32)(r & 7) << 4;
    }
    const int rl = lid >> 2;
    const int cl = (lid & 3) * 2;

    float c_[4][4];
#pragma unroll
    for (int i = 0; i < 4; i++)
#pragma unroll
        for (int j = 0; j < 4; j++) c_[i][j] = 0.f;

    for (int t = 0; t < TS; t++) {
        float acc[4][4][4];
#pragma unroll
        for (int i = 0; i < 4; i++)
#pragma unroll
            for (int j = 0; j < 4; j++)
#pragma unroll
                for (int k = 0; k < 4; k++) acc[i][j][k] = 0.f;

        if (t > 0) {
            const u16* Ahi_ = ((t - 1) & 1) ? g_hh1 : g_hh0;
            const u16* Alo_ = ((t - 1) & 1) ? g_hl1 : g_hl0;

            auto issue = [&](int buf, int c) {
                const u32 s0 = sb + (u32)buf * 65536;
                const int k0 = c * 64;
#pragma unroll
                for (int p = 0; p < 4; p++) {
                    int ch  = tid + p * 256;
                    int row = ch >> 3;
                    int seg = ch & 7;
                    u32 doff = (u32)row * 128 +
                               (((u32)seg * 16) ^ ((u32)(row & 7) << 4));
                    size_t ai = (size_t)(bm + row) * HID + k0 + seg * 8;
                    size_t bi = (size_t)(bn + row) * HID + k0 + seg * 8;
                    CP16(s0 +         doff, Ahi_ + ai);
                    CP16(s0 + 16384 + doff, Alo_ + ai);
                    CP16(s0 + 32768 + doff, g_Whhh + bi);
                    CP16(s0 + 49152 + doff, g_Whhl + bi);
                }
            };

            issue(0, 0); CP_COMMIT();
            issue(1, 1); CP_COMMIT();
#pragma unroll 1
            for (int c = 0; c < 16; c++) {
                if (c + 2 < 16) issue((c + 2) % 3, c + 2);
                CP_COMMIT();
                CP_WAIT2();
                __syncthreads();
                const u32 s0  = sb + (u32)(c % 3) * 65536;
                const u32 sAh = s0, sAl = s0 + 16384,
                          sBh = s0 + 32768, sBl = s0 + 49152;
#pragma unroll
                for (int ks = 0; ks < 4; ks++) {
                    const u32 kb = (u32)ks * 32 + kl;
                    u32 Ah[4][4], Al[4][4];
#pragma unroll
                    for (int mt = 0; mt < 4; mt++) {
                        u32 o = aoff[mt] + (kb ^ axor[mt]);
                        LDSM4(Ah[mt], sAh + o);
                        LDSM4(Al[mt], sAl + o);
                    }
                    u32 Bh[2][4], Bl[2][4];
#pragma unroll
                    for (int p = 0; p < 2; p++) {
                        u32 o = boff[p] + (kb ^ bxor[p]);
                        LDSM4(Bh[p], sBh + o);
                        LDSM4(Bl[p], sBl + o);
                    }
#pragma unroll
                    for (int mt = 0; mt < 4; mt++)
#pragma unroll
                        for (int nt = 0; nt < 4; nt++) {
                            const int p = nt >> 1, q = nt & 1;
                            MMA_BF16(acc[mt][nt], Ah[mt], Bh[p][q], Bh[p][q + 2]);
                            MMA_BF16(acc[mt][nt], Ah[mt], Bl[p][q], Bl[p][q + 2]);
                            MMA_BF16(acc[mt][nt], Al[mt], Bh[p][q], Bh[p][q + 2]);
                        }
                }
                __syncthreads();
            }
        }

        // ---- in-register LSTM cell ----
        u16* Hh = (t & 1) ? g_hh1 : g_hh0;
        u16* Hl = (t & 1) ? g_hl1 : g_hl0;
        const int colb = bn + warp_q * 32 + cl;
        const int kidx = sidx * 32 + warp_q * 8 + cl;
#pragma unroll
        for (int mt = 0; mt < 4; mt++) {
#pragma unroll
            for (int half = 0; half < 2; half++) {
                const int n = bm + warp_m * 64 + mt * 16 + rl + half * 8;
                const float* xr = Xg + ((size_t)t * NQ + n) * G4 + colb;
                float2 xi = *(const float2*)(xr + 0);
                float2 xf = *(const float2*)(xr + 8);
                float2 xg = *(const float2*)(xr + 16);
                float2 xo = *(const float2*)(xr + 24);
                float hv[2];
#pragma unroll
                for (int cp = 0; cp < 2; cp++) {
                    const int e = half * 2 + cp;
                    float gi = acc[mt][0][e] + (cp ? xi.y : xi.x);
                    float gf = acc[mt][1][e] + (cp ? xf.y : xf.x);
                    float gg = acc[mt][2][e] + (cp ? xg.y : xg.x);
                    float go = acc[mt][3][e] + (cp ? xo.y : xo.x);
                    float i_ = 1.f / (1.f + expf(-gi));
                    float f_ = 1.f / (1.f + expf(-gf));
                    float g_ = tanhf(gg);
                    float o_ = 1.f / (1.f + expf(-go));
                    float cc = f_ * c_[mt][e] + i_ * g_;
                    c_[mt][e] = cc;
                    hv[cp] = o_ * tanhf(cc);
                }
                const size_t hi_ = (size_t)n * HID + kidx;
                *(u32*)(Hh + hi_) = hi_pack(hv[0], hv[1]);
                *(u32*)(Hl + hi_) = lo_pack(hv[0], hv[1]);
                *(float2*)(hs_out + ((size_t)n * TS + t) * HID + kidx) =
                    make_float2(hv[0], hv[1]);
            }
        }

        // ---- device-wide barrier (skip after last step) ----
        if (t < TS - 1) {
            __threadfence();
            __syncthreads();
            if (tid == 0) {
                atomicAdd(&g_bar, 1u);
                const unsigned target = 128u * (unsigned)(t + 1);
                unsigned v;
                do {
                    asm volatile("ld.global.acquire.gpu.b32 %0, [%1];"
                                 : "=r"(v) : "l"(&g_bar));
                    if (v < target) __nanosleep(128);
                } while (v < target);
            }
            __syncthreads();
        }
    }
}

// ===================== small kernels =====================
__global__ void conv_split(const float* __restrict__ x, u16* __restrict__ hi,
                           u16* __restrict__ lo, int n4)
{
    int i = blockIdx.x * blockDim.x + threadIdx.x;
    if (i >= n4) return;
    float4 v = ((const float4*)x)[i];
    ((uint2*)hi)[i] = make_uint2(hi_pack(v.x, v.y), hi_pack(v.z, v.w));
    ((uint2*)lo)[i] = make_uint2(lo_pack(v.x, v.y), lo_pack(v.z, v.w));
}

// split + gate-interleave permute of a [4096][1024] weight (W_ih or W_hh)
__global__ void convp(const float* __restrict__ src, u16* __restrict__ hi,
                      u16* __restrict__ lo)
{
    int p = blockIdx.x;                       // dest (permuted) row
    int orig = perm_orig(p);
    float4 v = ((const float4*)(src + (size_t)orig * 1024))[threadIdx.x];
    size_t o4 = (size_t)p * 256 + threadIdx.x;
    ((uint2*)hi)[o4] = make_uint2(hi_pack(v.x, v.y), hi_pack(v.z, v.w));
    ((uint2*)lo)[o4] = make_uint2(lo_pack(v.x, v.y), lo_pack(v.z, v.w));
}

// gather embedding rows (blocks < TQ*NQ) + build permuted bias (last 16 blocks)
__global__ void gather_emb(const int* __restrict__ q, const float* __restrict__ emb,
                           const float* __restrict__ b_ih,
                           const float* __restrict__ b_hh)
{
    int row = blockIdx.x;
    if (row >= TQ * NQ) {
        int p = (row - TQ * NQ) * 256 + threadIdx.x;   // 0..4095
        int orig = perm_orig(p);
        g_pbias[p] = b_ih[orig] + b_hh[orig];
        return;
    }
    int t = row / NQ + 1;
    int n = row % NQ;
    int qi = q[n * TQ + (t - 1)];
    float4 v = ((const float4*)(emb + (size_t)qi * EMBED))[threadIdx.x];
    size_t base4 = ((size_t)t * NQ + n) * (EMBED / 4) + threadIdx.x;
    ((uint2*)g_Xhi)[base4] = make_uint2(hi_pack(v.x, v.y), hi_pack(v.z, v.w));
    ((uint2*)g_Xlo)[base4] = make_uint2(lo_pack(v.x, v.y), lo_pack(v.z, v.w));
}

__global__ void zero_bar() { g_bar = 0u; }

// ===================== host =====================
extern "C" void kernel_launch(void* const* d_in, const int* in_sizes, int n_in,
                              void* d_out, int out_size)
{
    (void)in_sizes; (void)n_in; (void)out_size;
    const int*   questions = (const int*)  d_in[0];
    const float* img       = (const float*)d_in[1];
    const float* emb       = (const float*)d_in[2];
    const float* W_img     = (const float*)d_in[3];
    const float* b_img     = (const float*)d_in[4];
    const float* W_ih      = (const float*)d_in[5];
    const float* W_hh      = (const float*)d_in[6];
    const float* b_ih      = (const float*)d_in[7];
    const float* b_hh      = (const float*)d_in[8];
    const float* W_out     = (const float*)d_in[9];
    const float* b_out     = (const float*)d_in[10];

    float* out_logits = (float*)d_out;                        // [512, 32000]
    float* out_hs     = out_logits + (size_t)NQ * VOCAB;      // [512, 49, 1024]

    u16 *Xhi, *Xlo, *imgh, *imgl, *Wimgh, *Wimgl, *Wihh, *Wihl, *Whhh, *Whhl,
        *Wouth, *Woutl, *hh0, *hl0;
    float *Xg, *pbias;
    cudaGetSymbolAddress((void**)&Xhi,   g_Xhi);
    cudaGetSymbolAddress((void**)&Xlo,   g_Xlo);
    cudaGetSymbolAddress((void**)&imgh,  g_imgh);
    cudaGetSymbolAddress((void**)&imgl,  g_imgl);
    cudaGetSymbolAddress((void**)&Wimgh, g_Wimgh);
    cudaGetSymbolAddress((void**)&Wimgl, g_Wimgl);
    cudaGetSymbolAddress((void**)&Wihh,  g_Wihh);
    cudaGetSymbolAddress((void**)&Wihl,  g_Wihl);
    cudaGetSymbolAddress((void**)&Whhh,  g_Whhh);
    cudaGetSymbolAddress((void**)&Whhl,  g_Whhl);
    cudaGetSymbolAddress((void**)&Wouth, g_Wouth);
    cudaGetSymbolAddress((void**)&Woutl, g_Woutl);
    cudaGetSymbolAddress((void**)&hh0,   g_hh0);
    cudaGetSymbolAddress((void**)&hl0,   g_hl0);
    cudaGetSymbolAddress((void**)&Xg,    g_Xg);
    cudaGetSymbolAddress((void**)&pbias, g_pbias);

    cudaFuncSetAttribute(tgemm, cudaFuncAttributeMaxDynamicSharedMemorySize,
                         TG_SMEM);
    cudaFuncSetAttribute(lstm_persist,
                         cudaFuncAttributeMaxDynamicSharedMemorySize, LP_SMEM);

    // #0: gather embeddings + permuted bias
    gather_emb<<<TQ * NQ + 16, 256>>>(questions, emb, b_ih, b_hh);

    // #1-2: conversions needed by the img GEMM
    conv_split<<<(NQ * IMG / 4 + 255) / 256, 256>>>(img, imgh, imgl, NQ * IMG / 4);
    conv_split<<<(HID * IMG / 4 + 255) / 256, 256>>>(W_img, Wimgh, Wimgl,
                                                     HID * IMG / 4);

    // #3 (ncu capture slot): X[0] = img @ W_img^T + b_img (split output)
    tgemm<<<dim3(EMBED / 128, NQ / 128), 256, TG_SMEM>>>(
        imgh, imgl, Wimgh, Wimgl, nullptr, Xhi, Xlo,
        NQ, EMBED, IMG, nullptr, b_img);

    // #4: permuted split W_ih
    convp<<<G4, 256>>>(W_ih, Wihh, Wihl);

    // #5: Xg = X @ W_ihP^T + pbias   (permuted gate columns)
    tgemm<<<dim3(G4 / 128, (TS * NQ) / 128), 256, TG_SMEM>>>(
        Xhi, Xlo, Wihh, Wihl, Xg, nullptr, nullptr,
        TS * NQ, G4, EMBED, nullptr, pbias);

    // #6-7: permuted split W_hh; reset device barrier
    convp<<<G4, 256>>>(W_hh, Whhh, Whhl);
    zero_bar<<<1, 1>>>();

    // #8: the whole recurrence in one persistent kernel
    lstm_persist<<<128, 256, LP_SMEM>>>(Xg, out_hs);

    // #9-10: logits = h_last @ W_out^T + b_out  (h_48 lives in buffer 0)
    conv_split<<<(VOCAB * HID / 4 + 255) / 256, 256>>>(W_out, Wouth, Woutl,
                                                       VOCAB * HID / 4);
    tgemm<<<dim3(VOCAB / 128, NQ / 128), 256, TG_SMEM>>>(
        hh0, hl0, Wouth, Woutl, out_logits, nullptr, nullptr,
        NQ, VOCAB, HID, nullptr, b_out);
}

// round 10
// speedup vs baseline: 2.9982x; 1.1029x over previous
#include <cuda_runtime.h>
#include <cstdint>
#include <math.h>

typedef unsigned short u16;
typedef unsigned int   u32;
typedef unsigned long long u64;

// Problem constants
#define NQ    512
#define TQ    48
#define TS    49        // T+1 steps
#define VOCAB 32000
#define EMBED 1024
#define HID   1024
#define IMG   4096
#define G4    4096      // 4*HID

// ===================== scratch (device globals; no allocs allowed) ==========
__device__ u16  g_Xhi [TS * NQ * EMBED];     // split-bf16 input sequence
__device__ u16  g_Xlo [TS * NQ * EMBED];
__device__ u16  g_imgh[NQ * IMG],    g_imgl[NQ * IMG];
__device__ u16  g_Wimgh[HID * IMG],  g_Wimgl[HID * IMG];
__device__ u16  g_Wihh[G4 * EMBED],  g_Wihl[G4 * EMBED];   // PERMUTED rows
__device__ u16  g_Whhh[G4 * HID],    g_Whhl[G4 * HID];     // PERMUTED rows
__device__ u16  g_Wouth[VOCAB * HID], g_Woutl[VOCAB * HID];
__device__ u16  g_hh0[NQ * HID], g_hl0[NQ * HID];          // h ping-pong buf 0
__device__ u16  g_hh1[NQ * HID], g_hl1[NQ * HID];          // h ping-pong buf 1
__device__ float g_Xg[TS * NQ * G4];         // x@W_ih^T + pbias (permuted cols)
__device__ float g_pbias[G4];                // permuted b_ih + b_hh
__device__ float g_part[4 * NQ * EMBED];     // split-K partials for img GEMM
__device__ unsigned g_bar;                   // device-wide barrier counter

// ===================== PTX helpers =====================
__device__ __forceinline__ u32 smem_to_u32(const void* p) {
    u32 a;
    asm("{ .reg .u64 t; cvta.to.shared.u64 t, %1; cvt.u32.u64 %0, t; }"
        : "=r"(a) : "l"(p));
    return a;
}

#define CP16(dst, src) \
    asm volatile("cp.async.cg.shared.global [%0], [%1], 16;" \
        :: "r"(dst), "l"(src) : "memory")
#define CP_COMMIT() asm volatile("cp.async.commit_group;" ::: "memory")
#define CP_WAIT2()  asm volatile("cp.async.wait_group 2;" ::: "memory")

#define LDSM4(r, addr) \
    asm volatile("ldmatrix.sync.aligned.m8n8.x4.shared.b16 {%0,%1,%2,%3}, [%4];" \
        : "=r"((r)[0]), "=r"((r)[1]), "=r"((r)[2]), "=r"((r)[3]) : "r"(addr))

#define MMA_BF16(d, a, b0, b1) \
    asm volatile("mma.sync.aligned.m16n8k16.row.col.f32.bf16.bf16.f32 " \
        "{%0,%1,%2,%3}, {%4,%5,%6,%7}, {%8,%9}, {%0,%1,%2,%3};" \
        : "+f"((d)[0]), "+f"((d)[1]), "+f"((d)[2]), "+f"((d)[3]) \
        : "r"((a)[0]), "r"((a)[1]), "r"((a)[2]), "r"((a)[3]), "r"(b0), "r"(b1))

// split helpers: hi = truncated top-16 bits (exact), lo = rn_bf16(x - hi)
__device__ __forceinline__ u32 hi_pack(float x, float y) {
    u32 bx = __float_as_uint(x), by = __float_as_uint(y), h;
    asm("prmt.b32 %0, %1, %2, 0x7632;" : "=r"(h) : "r"(bx), "r"(by));
    return h;  // (hi(y)<<16)|hi(x)
}
__device__ __forceinline__ u32 lo_pack(float x, float y) {
    float lx = x - __uint_as_float(__float_as_uint(x) & 0xFFFF0000u);
    float ly = y - __uint_as_float(__float_as_uint(y) & 0xFFFF0000u);
    u32 l;
    asm("cvt.rn.bf16x2.f32 %0, %1, %2;" : "=r"(l) : "f"(ly), "f"(lx));
    return l;
}

// Gate-interleave permutation: permuted row p <- original row
//   p = 128*s + 32*q + 8*g + d  <->  orig = g*1024 + (s*32 + q*8 + d)
__device__ __forceinline__ int perm_orig(int p) {
    int s = p >> 7, r = p & 127;
    return ((r >> 3) & 3) * 1024 + s * 32 + (r >> 5) * 8 + (r & 7);
}

// ============================================================================
// bf16 split GEMM: C[M,N] = A[M,K(chunk)] @ B[N,K]^T (+Cin +bias1)
// ldk = leading dim of A/B rows; K = this launch's K-chunk length;
// blockIdx.z selects K-chunk (kbase = z*K) and partial-output plane z*M*N.
// 128x128 tile, BK=32, 256 threads (8 warps, each 64x32), 3-stage cp.async.
// SW64 swizzle (xor = ((row>>1)&3)<<4). 96KB smem -> 2 CTAs/SM.
// ============================================================================
#define TG_SMEM (3 * 4 * 8192)

__global__ __launch_bounds__(256, 2) void tgemm(
    const u16* __restrict__ Ahi, const u16* __restrict__ Alo,
    const u16* __restrict__ Bhi, const u16* __restrict__ Blo,
    float* __restrict__ C, u16* __restrict__ Chi, u16* __restrict__ Clo,
    int M, int N, int K, int ldk,
    const float* __restrict__ Cin, const float* __restrict__ bias1)
{
    extern __shared__ char smem[];
    const u32 sb = smem_to_u32(smem);
    const int tid = threadIdx.x;
    const int wid = tid >> 5;
    const int lid = tid & 31;
    const int warp_m = wid & 1;     // 2 warps over M
    const int warp_n = wid >> 1;    // 4 warps over N
    const int bm = blockIdx.y * 128;
    const int bn = blockIdx.x * 128;
    const int kbase = blockIdx.z * K;
    if (C) C += (size_t)blockIdx.z * M * N;

    const int lrow8 = (lid & 7) + ((lid >> 3) & 1) * 8;
    const u32 kl = ((lid >> 4) & 1) * 16;
    u32 aoff[4], axor[4], boff[2], bxor[2];
#pragma unroll
    for (int mt = 0; mt < 4; mt++) {
        int r = warp_m * 64 + mt * 16 + lrow8;
        aoff[mt] = (u32)r * 64;
        axor[mt] = (u32)((r >> 1) & 3) << 4;
    }
#pragma unroll
    for (int p = 0; p < 2; p++) {
        int r = warp_n * 32 + p * 16 + lrow8;
        boff[p] = (u32)r * 64;
        bxor[p] = (u32)((r >> 1) & 3) << 4;
    }

    float acc[4][4][4];
#pragma unroll
    for (int i = 0; i < 4; i++)
#pragma unroll
        for (int j = 0; j < 4; j++)
#pragma unroll
            for (int k = 0; k < 4; k++) acc[i][j][k] = 0.f;

    auto issue = [&](int buf, int c) {
        const u32 s0 = sb + (u32)buf * 32768;
        const int k0 = kbase + c * 32;
#pragma unroll
        for (int p = 0; p < 2; p++) {
            int ch  = tid + p * 256;         // 0..511
            int row = ch >> 2;
            int seg = ch & 3;
            u32 doff = (u32)row * 64 +
                       (((u32)seg * 16) ^ ((u32)((row >> 1) & 3) << 4));
            size_t ai = (size_t)(bm + row) * ldk + k0 + seg * 8;
            size_t bi = (size_t)(bn + row) * ldk + k0 + seg * 8;
            CP16(s0 +         doff, Ahi + ai);
            CP16(s0 +  8192 + doff, Alo + ai);
            CP16(s0 + 16384 + doff, Bhi + bi);
            CP16(s0 + 24576 + doff, Blo + bi);
        }
    };

    const int nch = K >> 5;
    issue(0, 0); CP_COMMIT();
    issue(1, 1); CP_COMMIT();

    for (int c = 0; c < nch; c++) {
        if (c + 2 < nch) issue((c + 2) % 3, c + 2);
        CP_COMMIT();
        CP_WAIT2();
        __syncthreads();

        const u32 s0  = sb + (u32)(c % 3) * 32768;
        const u32 sAh = s0, sAl = s0 + 8192, sBh = s0 + 16384, sBl = s0 + 24576;
#pragma unroll
        for (int ks = 0; ks < 2; ks++) {
            const u32 kb = (u32)ks * 32 + kl;
            u32 Ah[4][4], Al[4][4];
#pragma unroll
            for (int mt = 0; mt < 4; mt++) {
                u32 o = aoff[mt] + (kb ^ axor[mt]);
                LDSM4(Ah[mt], sAh + o);
                LDSM4(Al[mt], sAl + o);
            }
            u32 Bh[2][4], Bl[2][4];
#pragma unroll
            for (int p = 0; p < 2; p++) {
                u32 o = boff[p] + (kb ^ bxor[p]);
                LDSM4(Bh[p], sBh + o);
                LDSM4(Bl[p], sBl + o);
            }
#pragma unroll
            for (int mt = 0; mt < 4; mt++)
#pragma unroll
                for (int nt = 0; nt < 4; nt++) {
                    const int p = nt >> 1, q = nt & 1;
                    MMA_BF16(acc[mt][nt], Ah[mt], Bh[p][q], Bh[p][q + 2]);
                    MMA_BF16(acc[mt][nt], Ah[mt], Bl[p][q], Bl[p][q + 2]);
                    MMA_BF16(acc[mt][nt], Al[mt], Bh[p][q], Bh[p][q + 2]);
                }
        }
        __syncthreads();
    }

    const int rl = lid >> 2;
    const int cl = (lid & 3) * 2;
#pragma unroll
    for (int mt = 0; mt < 4; mt++) {
#pragma unroll
        for (int nt = 0; nt < 4; nt++) {
            const int row0 = bm + warp_m * 64 + mt * 16 + rl;
            const int col  = bn + warp_n * 32 + nt * 8 + cl;
#pragma unroll
            for (int half = 0; half < 2; half++) {
                const int row = row0 + half * 8;
                float vx = acc[mt][nt][half * 2];
                float vy = acc[mt][nt][half * 2 + 1];
                const size_t gi = (size_t)row * N + col;
                if (Cin) { float2 c2 = *(const float2*)(Cin + gi); vx += c2.x; vy += c2.y; }
                if (bias1) { float2 b2 = *(const float2*)(bias1 + col); vx += b2.x; vy += b2.y; }
                if (C) *(float2*)(C + gi) = make_float2(vx, vy);
                if (Chi) {
                    *(u32*)(Chi + gi) = hi_pack(vx, vy);
                    *(u32*)(Clo + gi) = lo_pack(vx, vy);
                }
            }
        }
    }
}

// ============================================================================
// Persistent LSTM recurrence: all 49 steps in one kernel.
// grid = 128 CTAs (4 bm-blocks x 32 column strips), 512 threads (16 warps,
// each 32x32: warp_m over 4 M-blocks, warp_q over 4 gate-column groups).
// BK=64, 3-stage cp.async, 192KB smem. Xg[t] prefetched into registers before
// the GEMM so the cell's global reads are never exposed. c in registers all
// steps; h ping-pongs split-bf16 in global; one device barrier per step.
// ============================================================================
#define LP_SMEM (3 * 4 * 16384)

__global__ __launch_bounds__(512) void lstm_persist(const float* __restrict__ Xg,
                                                    float* __restrict__ hs_out)
{
    extern __shared__ char smem[];
    const u32 sb = smem_to_u32(smem);
    const int tid = threadIdx.x;
    const int wid = tid >> 5;
    const int lid = tid & 31;
    const int warp_m = wid & 3;     // 4 warps over M (32 rows each)
    const int warp_q = wid >> 2;    // 4 warps over the 128-col strip (32 each)
    const int bm   = (blockIdx.x & 3) * 128;
    const int sidx = blockIdx.x >> 2;
    const int bn   = sidx * 128;

    const int lrow8 = (lid & 7) + ((lid >> 3) & 1) * 8;
    const u32 kl = ((lid >> 4) & 1) * 16;
    u32 aoff[2], axor[2], boff[2], bxor[2];
#pragma unroll
    for (int mt = 0; mt < 2; mt++) {
        int r = warp_m * 32 + mt * 16 + lrow8;
        aoff[mt] = (u32)r * 128;
        axor[mt] = (u32)(r & 7) << 4;
    }
#pragma unroll
    for (int p = 0; p < 2; p++) {
        int r = warp_q * 32 + p * 16 + lrow8;
        boff[p] = (u32)r * 128;
        bxor[p] = (u32)(r & 7) << 4;
    }
    const int rl = lid >> 2;
    const int cl = (lid & 3) * 2;
    const int colb = bn + warp_q * 32 + cl;        // permuted col of gate i
    const int kidx = sidx * 32 + warp_q * 8 + cl;  // hidden index (orig)

    float c_[2][4];
#pragma unroll
    for (int i = 0; i < 2; i++)
#pragma unroll
        for (int j = 0; j < 4; j++) c_[i][j] = 0.f;

    for (int t = 0; t < TS; t++) {
        // ---- prefetch Xg[t] into registers (independent of the GEMM) ----
        float2 xi[2][2], xf[2][2], xg[2][2], xo[2][2];
#pragma unroll
        for (int mt = 0; mt < 2; mt++)
#pragma unroll
            for (int half = 0; half < 2; half++) {
                const int n = bm + warp_m * 32 + mt * 16 + rl + half * 8;
                const float* xr = Xg + ((size_t)t * NQ + n) * G4 + colb;
                xi[mt][half] = *(const float2*)(xr + 0);
                xf[mt][half] = *(const float2*)(xr + 8);
                xg[mt][half] = *(const float2*)(xr + 16);
                xo[mt][half] = *(const float2*)(xr + 24);
            }

        float acc[2][4][4];
#pragma unroll
        for (int i = 0; i < 2; i++)
#pragma unroll
            for (int j = 0; j < 4; j++)
#pragma unroll
                for (int k = 0; k < 4; k++) acc[i][j][k] = 0.f;

        if (t > 0) {
            const u16* Ahi_ = ((t - 1) & 1) ? g_hh1 : g_hh0;
            const u16* Alo_ = ((t - 1) & 1) ? g_hl1 : g_hl0;

            auto issue = [&](int buf, int c) {
                const u32 s0 = sb + (u32)buf * 65536;
                const int k0 = c * 64;
#pragma unroll
                for (int p = 0; p < 2; p++) {
                    int ch  = tid + p * 512;    // 0..1023
                    int row = ch >> 3;
                    int seg = ch & 7;
                    u32 doff = (u32)row * 128 +
                               (((u32)seg * 16) ^ ((u32)(row & 7) << 4));
                    size_t ai = (size_t)(bm + row) * HID + k0 + seg * 8;
                    size_t bi = (size_t)(bn + row) * HID + k0 + seg * 8;
                    CP16(s0 +         doff, Ahi_ + ai);
                    CP16(s0 + 16384 + doff, Alo_ + ai);
                    CP16(s0 + 32768 + doff, g_Whhh + bi);
                    CP16(s0 + 49152 + doff, g_Whhl + bi);
                }
            };

            issue(0, 0); CP_COMMIT();
            issue(1, 1); CP_COMMIT();
#pragma unroll 1
            for (int c = 0; c < 16; c++) {
                if (c + 2 < 16) issue((c + 2) % 3, c + 2);
                CP_COMMIT();
                CP_WAIT2();
                __syncthreads();
                const u32 s0  = sb + (u32)(c % 3) * 65536;
                const u32 sAh = s0, sAl = s0 + 16384,
                          sBh = s0 + 32768, sBl = s0 + 49152;
#pragma unroll
                for (int ks = 0; ks < 4; ks++) {
                    const u32 kb = (u32)ks * 32 + kl;
                    u32 Ah[2][4], Al[2][4];
#pragma unroll
                    for (int mt = 0; mt < 2; mt++) {
                        u32 o = aoff[mt] + (kb ^ axor[mt]);
                        LDSM4(Ah[mt], sAh + o);
                        LDSM4(Al[mt], sAl + o);
                    }
                    u32 Bh[2][4], Bl[2][4];
#pragma unroll
                    for (int p = 0; p < 2; p++) {
                        u32 o = boff[p] + (kb ^ bxor[p]);
                        LDSM4(Bh[p], sBh + o);
                        LDSM4(Bl[p], sBl + o);
                    }
#pragma unroll
                    for (int mt = 0; mt < 2; mt++)
#pragma unroll
                        for (int nt = 0; nt < 4; nt++) {
                            const int p = nt >> 1, q = nt & 1;
                            MMA_BF16(acc[mt][nt], Ah[mt], Bh[p][q], Bh[p][q + 2]);
                            MMA_BF16(acc[mt][nt], Ah[mt], Bl[p][q], Bl[p][q + 2]);
                            MMA_BF16(acc[mt][nt], Al[mt], Bh[p][q], Bh[p][q + 2]);
                        }
                }
                __syncthreads();
            }
        }

        // ---- in-register LSTM cell ----
        u16* Hh = (t & 1) ? g_hh1 : g_hh0;
        u16* Hl = (t & 1) ? g_hl1 : g_hl0;
#pragma unroll
        for (int mt = 0; mt < 2; mt++) {
#pragma unroll
            for (int half = 0; half < 2; half++) {
                const int n = bm + warp_m * 32 + mt * 16 + rl + half * 8;
                float hv[2];
#pragma unroll
                for (int cp = 0; cp < 2; cp++) {
                    const int e = half * 2 + cp;
                    float gi = acc[mt][0][e] + (cp ? xi[mt][half].y : xi[mt][half].x);
                    float gf = acc[mt][1][e] + (cp ? xf[mt][half].y : xf[mt][half].x);
                    float gg = acc[mt][2][e] + (cp ? xg[mt][half].y : xg[mt][half].x);
                    float go = acc[mt][3][e] + (cp ? xo[mt][half].y : xo[mt][half].x);
                    float i_ = 1.f / (1.f + expf(-gi));
                    float f_ = 1.f / (1.f + expf(-gf));
                    float g_ = tanhf(gg);
                    float o_ = 1.f / (1.f + expf(-go));
                    float cc = f_ * c_[mt][e] + i_ * g_;
                    c_[mt][e] = cc;
                    hv[cp] = o_ * tanhf(cc);
                }
                const size_t hi_ = (size_t)n * HID + kidx;
                *(u32*)(Hh + hi_) = hi_pack(hv[0], hv[1]);
                *(u32*)(Hl + hi_) = lo_pack(hv[0], hv[1]);
                *(float2*)(hs_out + ((size_t)n * TS + t) * HID + kidx) =
                    make_float2(hv[0], hv[1]);
            }
        }

        // ---- device-wide barrier (skip after last step) ----
        if (t < TS - 1) {
            __threadfence();
            __syncthreads();
            if (tid == 0) {
                atomicAdd(&g_bar, 1u);
                const unsigned target = 128u * (unsigned)(t + 1);
                unsigned v;
                do {
                    asm volatile("ld.global.acquire.gpu.b32 %0, [%1];"
                                 : "=r"(v) : "l"(&g_bar));
                    if (v < target) __nanosleep(128);
                } while (v < target);
            }
            __syncthreads();
        }
    }
}

// ===================== small kernels =====================
__global__ void conv_split(const float* __restrict__ x, u16* __restrict__ hi,
                           u16* __restrict__ lo, int n4)
{
    int i = blockIdx.x * blockDim.x + threadIdx.x;
    if (i >= n4) return;
    float4 v = ((const float4*)x)[i];
    ((uint2*)hi)[i] = make_uint2(hi_pack(v.x, v.y), hi_pack(v.z, v.w));
    ((uint2*)lo)[i] = make_uint2(lo_pack(v.x, v.y), lo_pack(v.z, v.w));
}

// split + gate-interleave permute of a [4096][1024] weight (W_ih or W_hh)
__global__ void convp(const float* __restrict__ src, u16* __restrict__ hi,
                      u16* __restrict__ lo)
{
    int p = blockIdx.x;                       // dest (permuted) row
    int orig = perm_orig(p);
    float4 v = ((const float4*)(src + (size_t)orig * 1024))[threadIdx.x];
    size_t o4 = (size_t)p * 256 + threadIdx.x;
    ((uint2*)hi)[o4] = make_uint2(hi_pack(v.x, v.y), hi_pack(v.z, v.w));
    ((uint2*)lo)[o4] = make_uint2(lo_pack(v.x, v.y), lo_pack(v.z, v.w));
}

// gather embedding rows (blocks < TQ*NQ) + build permuted bias (last 16 blocks)
__global__ void gather_emb(const int* __restrict__ q, const float* __restrict__ emb,
                           const float* __restrict__ b_ih,
                           const float* __restrict__ b_hh)
{
    int row = blockIdx.x;
    if (row >= TQ * NQ) {
        int p = (row - TQ * NQ) * 256 + threadIdx.x;   // 0..4095
        int orig = perm_orig(p);
        g_pbias[p] = b_ih[orig] + b_hh[orig];
        return;
    }
    int t = row / NQ + 1;
    int n = row % NQ;
    int qi = q[n * TQ + (t - 1)];
    float4 v = ((const float4*)(emb + (size_t)qi * EMBED))[threadIdx.x];
    size_t base4 = ((size_t)t * NQ + n) * (EMBED / 4) + threadIdx.x;
    ((uint2*)g_Xhi)[base4] = make_uint2(hi_pack(v.x, v.y), hi_pack(v.z, v.w));
    ((uint2*)g_Xlo)[base4] = make_uint2(lo_pack(v.x, v.y), lo_pack(v.z, v.w));
}

// reduce the 4 img split-K partials + bias -> split-bf16 X[0] rows 0..511
__global__ void reduce_img(const float* __restrict__ b_img)
{
    int i = blockIdx.x * blockDim.x + threadIdx.x;   // 0 .. 512*512-1 (pairs)
    int row = i >> 9;
    int c2 = (i & 511) * 2;
    size_t o = (size_t)row * EMBED + c2;
    const size_t P = (size_t)NQ * EMBED;
    float x = g_part[o] + g_part[o + P] + g_part[o + 2 * P] + g_part[o + 3 * P]
              + b_img[c2];
    float y = g_part[o + 1] + g_part[o + 1 + P] + g_part[o + 1 + 2 * P]
              + g_part[o + 1 + 3 * P] + b_img[c2 + 1];
    ((u32*)g_Xhi)[o >> 1] = hi_pack(x, y);
    ((u32*)g_Xlo)[o >> 1] = lo_pack(x, y);
}

__global__ void zero_bar() { g_bar = 0u; }

// ===================== host =====================
extern "C" void kernel_launch(void* const* d_in, const int* in_sizes, int n_in,
                              void* d_out, int out_size)
{
    (void)in_sizes; (void)n_in; (void)out_size;
    const int*   questions = (const int*)  d_in[0];
    const float* img       = (const float*)d_in[1];
    const float* emb       = (const float*)d_in[2];
    const float* W_img     = (const float*)d_in[3];
    const float* b_img     = (const float*)d_in[4];
    const float* W_ih      = (const float*)d_in[5];
    const float* W_hh      = (const float*)d_in[6];
    const float* b_ih      = (const float*)d_in[7];
    const float* b_hh      = (const float*)d_in[8];
    const float* W_out     = (const float*)d_in[9];
    const float* b_out     = (const float*)d_in[10];

    float* out_logits = (float*)d_out;                        // [512, 32000]
    float* out_hs     = out_logits + (size_t)NQ * VOCAB;      // [512, 49, 1024]

    u16 *Xhi, *Xlo, *imgh, *imgl, *Wimgh, *Wimgl, *Wihh, *Wihl, *Whhh, *Whhl,
        *Wouth, *Woutl, *hh0, *hl0;
    float *Xg, *pbias, *part;
    cudaGetSymbolAddress((void**)&Xhi,   g_Xhi);
    cudaGetSymbolAddress((void**)&Xlo,   g_Xlo);
    cudaGetSymbolAddress((void**)&imgh,  g_imgh);
    cudaGetSymbolAddress((void**)&imgl,  g_imgl);
    cudaGetSymbolAddress((void**)&Wimgh, g_Wimgh);
    cudaGetSymbolAddress((void**)&Wimgl, g_Wimgl);
    cudaGetSymbolAddress((void**)&Wihh,  g_Wihh);
    cudaGetSymbolAddress((void**)&Wihl,  g_Wihl);
    cudaGetSymbolAddress((void**)&Whhh,  g_Whhh);
    cudaGetSymbolAddress((void**)&Whhl,  g_Whhl);
    cudaGetSymbolAddress((void**)&Wouth, g_Wouth);
    cudaGetSymbolAddress((void**)&Woutl, g_Woutl);
    cudaGetSymbolAddress((void**)&hh0,   g_hh0);
    cudaGetSymbolAddress((void**)&hl0,   g_hl0);
    cudaGetSymbolAddress((void**)&Xg,    g_Xg);
    cudaGetSymbolAddress((void**)&pbias, g_pbias);
    cudaGetSymbolAddress((void**)&part,  g_part);

    cudaFuncSetAttribute(tgemm, cudaFuncAttributeMaxDynamicSharedMemorySize,
                         TG_SMEM);
    cudaFuncSetAttribute(lstm_persist,
                         cudaFuncAttributeMaxDynamicSharedMemorySize, LP_SMEM);

    // #0: gather embeddings + permuted bias
    gather_emb<<<TQ * NQ + 16, 256>>>(questions, emb, b_ih, b_hh);

    // #1-2: conversions needed by the img GEMM
    conv_split<<<(NQ * IMG / 4 + 255) / 256, 256>>>(img, imgh, imgl, NQ * IMG / 4);
    conv_split<<<(HID * IMG / 4 + 255) / 256, 256>>>(W_img, Wimgh, Wimgl,
                                                     HID * IMG / 4);

    // #3 (ncu capture slot): img GEMM, split-K=4 -> fp32 partials
    tgemm<<<dim3(EMBED / 128, NQ / 128, 4), 256, TG_SMEM>>>(
        imgh, imgl, Wimgh, Wimgl, part, nullptr, nullptr,
        NQ, EMBED, IMG / 4, IMG, nullptr, nullptr);

    // #4: reduce partials + b_img -> split X[0]
    reduce_img<<<(NQ * EMBED / 2) / 256, 256>>>(b_img);

    // #5: permuted split W_ih
    convp<<<G4, 256>>>(W_ih, Wihh, Wihl);

    // #6: Xg = X @ W_ihP^T + pbias   (permuted gate columns)
    tgemm<<<dim3(G4 / 128, (TS * NQ) / 128, 1), 256, TG_SMEM>>>(
        Xhi, Xlo, Wihh, Wihl, Xg, nullptr, nullptr,
        TS * NQ, G4, EMBED, EMBED, nullptr, pbias);

    // #7-8: permuted split W_hh; reset device barrier
    convp<<<G4, 256>>>(W_hh, Whhh, Whhl);
    zero_bar<<<1, 1>>>();

    // #9: the whole recurrence in one persistent kernel (512 threads)
    lstm_persist<<<128, 512, LP_SMEM>>>(Xg, out_hs);

    // #10-11: logits = h_last @ W_out^T + b_out  (h_48 lives in buffer 0)
    conv_split<<<(VOCAB * HID / 4 + 255) / 256, 256>>>(W_out, Wouth, Woutl,
                                                       VOCAB * HID / 4);
    tgemm<<<dim3(VOCAB / 128, NQ / 128, 1), 256, TG_SMEM>>>(
        hh0, hl0, Wouth, Woutl, out_logits, nullptr, nullptr,
        NQ, VOCAB, HID, HID, nullptr, b_out);
}

// round 11
// speedup vs baseline: 4.0815x; 1.3613x over previous
#include <cuda_runtime.h>
#include <cuda_fp16.h>
#include <cstdint>
#include <math.h>

typedef unsigned short u16;
typedef unsigned int   u32;

// Problem constants
#define NQ    512
#define TQ    48
#define TS    49        // T+1 steps
#define VOCAB 32000
#define EMBED 1024
#define HID   1024
#define IMG   4096
#define G4    4096      // 4*HID

// ===================== scratch (device globals; no allocs allowed) ==========
__device__ u16  g_Xhi [TS * NQ * EMBED];     // fp16(X) input sequence (hi only)
__device__ u16  g_imgh[NQ * IMG];            // fp16(img)
__device__ u16  g_Wimgh[HID * IMG],  g_Wimgl[HID * IMG];
__device__ u16  g_Wihh[G4 * EMBED],  g_Wihl[G4 * EMBED];   // PERMUTED rows
__device__ u16  g_Whhh[G4 * HID],    g_Whhl[G4 * HID];     // PERMUTED rows
__device__ u16  g_Wouth[VOCAB * HID], g_Woutl[VOCAB * HID];
__device__ u16  g_hh0[NQ * HID], g_hl0[NQ * HID];          // h ping-pong buf 0
__device__ u16  g_hh1[NQ * HID], g_hl1[NQ * HID];          // h ping-pong buf 1
__device__ float g_Xg[TS * NQ * G4];         // x@W_ih^T + pbias (permuted cols)
__device__ float g_pbias[G4];                // permuted b_ih + b_hh
__device__ float g_part[4 * NQ * EMBED];     // split-K partials for img GEMM
__device__ unsigned g_bar;                   // device-wide barrier counter

// ===================== PTX helpers =====================
__device__ __forceinline__ u32 smem_to_u32(const void* p) {
    u32 a;
    asm("{ .reg .u64 t; cvta.to.shared.u64 t, %1; cvt.u32.u64 %0, t; }"
        : "=r"(a) : "l"(p));
    return a;
}

#define CP16(dst, src) \
    asm volatile("cp.async.cg.shared.global [%0], [%1], 16;" \
        :: "r"(dst), "l"(src) : "memory")
#define CP_COMMIT() asm volatile("cp.async.commit_group;" ::: "memory")
#define CP_WAIT2()  asm volatile("cp.async.wait_group 2;" ::: "memory")

#define LDSM4(r, addr) \
    asm volatile("ldmatrix.sync.aligned.m8n8.x4.shared.b16 {%0,%1,%2,%3}, [%4];" \
        : "=r"((r)[0]), "=r"((r)[1]), "=r"((r)[2]), "=r"((r)[3]) : "r"(addr))

#define MMA_F16(d, a, b0, b1) \
    asm volatile("mma.sync.aligned.m16n8k16.row.col.f32.f16.f16.f32 " \
        "{%0,%1,%2,%3}, {%4,%5,%6,%7}, {%8,%9}, {%0,%1,%2,%3};" \
        : "+f"((d)[0]), "+f"((d)[1]), "+f"((d)[2]), "+f"((d)[3]) \
        : "r"((a)[0]), "r"((a)[1]), "r"((a)[2]), "r"((a)[3]), "r"(b0), "r"(b1))

// fp16 split: hi = rn_fp16(x) (rel err 2^-12), lo = rn_fp16(x - hi)
__device__ __forceinline__ u32 f16hi(float x, float y) {
    __half2 h = __floats2half2_rn(x, y);            // x in low half
    return *reinterpret_cast<u32*>(&h);
}
__device__ __forceinline__ u32 f16lo(float x, float y) {
    __half2 h = __floats2half2_rn(x, y);
    float rx = x - __low2float(h);
    float ry = y - __high2float(h);
    __half2 l = __floats2half2_rn(rx, ry);
    return *reinterpret_cast<u32*>(&l);
}

// Gate-interleave permutation: permuted row p <- original row
//   p = 128*s + 32*q + 8*g + d  <->  orig = g*1024 + (s*32 + q*8 + d)
__device__ __forceinline__ int perm_orig(int p) {
    int s = p >> 7, r = p & 127;
    return ((r >> 3) & 3) * 1024 + s * 32 + (r >> 5) * 8 + (r & 7);
}

// ============================================================================
// fp16 split GEMM: C[M,N] = A @ B^T (+Cin +bias1), K-major A/B, fp32 accum.
// TERMS=2: A fp16 (Ahi only)   ; MMAs per tile: Ah*Bh + Ah*Bl    (err ~2^-12)
// TERMS=3: A split (Ahi,Alo)   ; MMAs: Ah*Bh + Ah*Bl + Al*Bh     (err ~2^-22)
// 128x128 tile, BK=32, 256 threads (8 warps, 64x32 each), 3-stage cp.async,
// SW64 swizzle. Stage = TERMS+1 planes of 8KB. 2 CTAs/SM.
// blockIdx.z = split-K chunk (kbase=z*K, partial plane z*M*N when C!=null).
// ============================================================================
#define TG2_SMEM (3 * 3 * 8192)
#define TG3_SMEM (3 * 4 * 8192)

template <int TERMS>
__global__ __launch_bounds__(256, 2) void tgemm(
    const u16* __restrict__ Ahi, const u16* __restrict__ Alo,
    const u16* __restrict__ Bhi, const u16* __restrict__ Blo,
    float* __restrict__ C, u16* __restrict__ Chi,
    int M, int N, int K, int ldk,
    const float* __restrict__ Cin, const float* __restrict__ bias1)
{
    extern __shared__ char smem[];
    const u32 sb = smem_to_u32(smem);
    const u32 STAGE = (TERMS + 1) * 8192;
    const int tid = threadIdx.x;
    const int wid = tid >> 5;
    const int lid = tid & 31;
    const int warp_m = wid & 1;
    const int warp_n = wid >> 1;
    const int bm = blockIdx.y * 128;
    const int bn = blockIdx.x * 128;
    const int kbase = blockIdx.z * K;
    if (C) C += (size_t)blockIdx.z * M * N;

    const int lrow8 = (lid & 7) + ((lid >> 3) & 1) * 8;
    const u32 kl = ((lid >> 4) & 1) * 16;
    u32 aoff[4], axor[4], boff[2], bxor[2];
#pragma unroll
    for (int mt = 0; mt < 4; mt++) {
        int r = warp_m * 64 + mt * 16 + lrow8;
        aoff[mt] = (u32)r * 64;
        axor[mt] = (u32)((r >> 1) & 3) << 4;
    }
#pragma unroll
    for (int p = 0; p < 2; p++) {
        int r = warp_n * 32 + p * 16 + lrow8;
        boff[p] = (u32)r * 64;
        bxor[p] = (u32)((r >> 1) & 3) << 4;
    }

    float acc[4][4][4];
#pragma unroll
    for (int i = 0; i < 4; i++)
#pragma unroll
        for (int j = 0; j < 4; j++)
#pragma unroll
            for (int k = 0; k < 4; k++) acc[i][j][k] = 0.f;

    auto issue = [&](int buf, int c) {
        const u32 s0 = sb + (u32)buf * STAGE;
        const int k0 = kbase + c * 32;
#pragma unroll
        for (int p = 0; p < 2; p++) {
            int ch  = tid + p * 256;         // 0..511
            int row = ch >> 2;
            int seg = ch & 3;
            u32 doff = (u32)row * 64 +
                       (((u32)seg * 16) ^ ((u32)((row >> 1) & 3) << 4));
            size_t ai = (size_t)(bm + row) * ldk + k0 + seg * 8;
            size_t bi = (size_t)(bn + row) * ldk + k0 + seg * 8;
            CP16(s0 + doff, Ahi + ai);
            if (TERMS == 3) {
                CP16(s0 +  8192 + doff, Alo + ai);
                CP16(s0 + 16384 + doff, Bhi + bi);
                CP16(s0 + 24576 + doff, Blo + bi);
            } else {
                CP16(s0 +  8192 + doff, Bhi + bi);
                CP16(s0 + 16384 + doff, Blo + bi);
            }
        }
    };

    const int nch = K >> 5;
    issue(0, 0); CP_COMMIT();
    issue(1, 1); CP_COMMIT();

    for (int c = 0; c < nch; c++) {
        if (c + 2 < nch) issue((c + 2) % 3, c + 2);
        CP_COMMIT();
        CP_WAIT2();
        __syncthreads();

        const u32 s0  = sb + (u32)(c % 3) * STAGE;
        const u32 sAh = s0;
        const u32 sAl = s0 + 8192;                      // TERMS==3 only
        const u32 sBh = s0 + (TERMS == 3 ? 16384 : 8192);
        const u32 sBl = s0 + (TERMS == 3 ? 24576 : 16384);
#pragma unroll
        for (int ks = 0; ks < 2; ks++) {
            const u32 kb = (u32)ks * 32 + kl;
            u32 Ah[4][4], Al[4][4];
#pragma unroll
            for (int mt = 0; mt < 4; mt++) {
                u32 o = aoff[mt] + (kb ^ axor[mt]);
                LDSM4(Ah[mt], sAh + o);
                if (TERMS == 3) LDSM4(Al[mt], sAl + o);
            }
            u32 Bh[2][4], Bl[2][4];
#pragma unroll
            for (int p = 0; p < 2; p++) {
                u32 o = boff[p] + (kb ^ bxor[p]);
                LDSM4(Bh[p], sBh + o);
                LDSM4(Bl[p], sBl + o);
            }
#pragma unroll
            for (int mt = 0; mt < 4; mt++)
#pragma unroll
                for (int nt = 0; nt < 4; nt++) {
                    const int p = nt >> 1, q = nt & 1;
                    MMA_F16(acc[mt][nt], Ah[mt], Bh[p][q], Bh[p][q + 2]);
                    MMA_F16(acc[mt][nt], Ah[mt], Bl[p][q], Bl[p][q + 2]);
                    if (TERMS == 3)
                        MMA_F16(acc[mt][nt], Al[mt], Bh[p][q], Bh[p][q + 2]);
                }
        }
        __syncthreads();
    }

    const int rl = lid >> 2;
    const int cl = (lid & 3) * 2;
#pragma unroll
    for (int mt = 0; mt < 4; mt++) {
#pragma unroll
        for (int nt = 0; nt < 4; nt++) {
            const int row0 = bm + warp_m * 64 + mt * 16 + rl;
            const int col  = bn + warp_n * 32 + nt * 8 + cl;
#pragma unroll
            for (int half = 0; half < 2; half++) {
                const int row = row0 + half * 8;
                float vx = acc[mt][nt][half * 2];
                float vy = acc[mt][nt][half * 2 + 1];
                const size_t gi = (size_t)row * N + col;
                if (Cin) { float2 c2 = *(const float2*)(Cin + gi); vx += c2.x; vy += c2.y; }
                if (bias1) { float2 b2 = *(const float2*)(bias1 + col); vx += b2.x; vy += b2.y; }
                if (C) *(float2*)(C + gi) = make_float2(vx, vy);
                if (Chi) *(u32*)(Chi + gi) = f16hi(vx, vy);
            }
        }
    }
}

// ============================================================================
// Persistent LSTM recurrence, 2-term fp16: gates = fp16(h) @ (W_hh hi+lo).
// grid = 128 CTAs (4 bm x 32 strips), 512 threads (16 warps, 32x32 each).
// BK=64, 3-stage cp.async, 3 planes/stage (Ah,Bh,Bl) = 144KB smem.
// Xg[t] prefetched to registers; c in registers; h ping-pong split-fp16 in
// global (hi read by recurrence, hi+lo read by the 3-term logits GEMM).
// ============================================================================
#define LP_SMEM (3 * 3 * 16384)

__global__ __launch_bounds__(512) void lstm_persist(const float* __restrict__ Xg,
                                                    float* __restrict__ hs_out)
{
    extern __shared__ char smem[];
    const u32 sb = smem_to_u32(smem);
    const int tid = threadIdx.x;
    const int wid = tid >> 5;
    const int lid = tid & 31;
    const int warp_m = wid & 3;
    const int warp_q = wid >> 2;
    const int bm   = (blockIdx.x & 3) * 128;
    const int sidx = blockIdx.x >> 2;
    const int bn   = sidx * 128;

    const int lrow8 = (lid & 7) + ((lid >> 3) & 1) * 8;
    const u32 kl = ((lid >> 4) & 1) * 16;
    u32 aoff[2], axor[2], boff[2], bxor[2];
#pragma unroll
    for (int mt = 0; mt < 2; mt++) {
        int r = warp_m * 32 + mt * 16 + lrow8;
        aoff[mt] = (u32)r * 128;
        axor[mt] = (u32)(r & 7) << 4;
    }
#pragma unroll
    for (int p = 0; p < 2; p++) {
        int r = warp_q * 32 + p * 16 + lrow8;
        boff[p] = (u32)r * 128;
        bxor[p] = (u32)(r & 7) << 4;
    }
    const int rl = lid >> 2;
    const int cl = (lid & 3) * 2;
    const int colb = bn + warp_q * 32 + cl;
    const int kidx = sidx * 32 + warp_q * 8 + cl;

    float c_[2][4];
#pragma unroll
    for (int i = 0; i < 2; i++)
#pragma unroll
        for (int j = 0; j < 4; j++) c_[i][j] = 0.f;

    for (int t = 0; t < TS; t++) {
        // ---- prefetch Xg[t] into registers ----
        float2 xi[2][2], xf[2][2], xg[2][2], xo[2][2];
#pragma unroll
        for (int mt = 0; mt < 2; mt++)
#pragma unroll
            for (int half = 0; half < 2; half++) {
                const int n = bm + warp_m * 32 + mt * 16 + rl + half * 8;
                const float* xr = Xg + ((size_t)t * NQ + n) * G4 + colb;
                xi[mt][half] = *(const float2*)(xr + 0);
                xf[mt][half] = *(const float2*)(xr + 8);
                xg[mt][half] = *(const float2*)(xr + 16);
                xo[mt][half] = *(const float2*)(xr + 24);
            }

        float acc[2][4][4];
#pragma unroll
        for (int i = 0; i < 2; i++)
#pragma unroll
            for (int j = 0; j < 4; j++)
#pragma unroll
                for (int k = 0; k < 4; k++) acc[i][j][k] = 0.f;

        if (t > 0) {
            const u16* Ahi_ = ((t - 1) & 1) ? g_hh1 : g_hh0;

            auto issue = [&](int buf, int c) {
                const u32 s0 = sb + (u32)buf * 49152;
                const int k0 = c * 64;
#pragma unroll
                for (int p = 0; p < 2; p++) {
                    int ch  = tid + p * 512;    // 0..1023
                    int row = ch >> 3;
                    int seg = ch & 7;
                    u32 doff = (u32)row * 128 +
                               (((u32)seg * 16) ^ ((u32)(row & 7) << 4));
                    size_t ai = (size_t)(bm + row) * HID + k0 + seg * 8;
                    size_t bi = (size_t)(bn + row) * HID + k0 + seg * 8;
                    CP16(s0 +         doff, Ahi_ + ai);
                    CP16(s0 + 16384 + doff, g_Whhh + bi);
                    CP16(s0 + 32768 + doff, g_Whhl + bi);
                }
            };

            issue(0, 0); CP_COMMIT();
            issue(1, 1); CP_COMMIT();
#pragma unroll 1
            for (int c = 0; c < 16; c++) {
                if (c + 2 < 16) issue((c + 2) % 3, c + 2);
                CP_COMMIT();
                CP_WAIT2();
                __syncthreads();
                const u32 s0  = sb + (u32)(c % 3) * 49152;
                const u32 sAh = s0, sBh = s0 + 16384, sBl = s0 + 32768;
#pragma unroll
                for (int ks = 0; ks < 4; ks++) {
                    const u32 kb = (u32)ks * 32 + kl;
                    u32 Ah[2][4];
#pragma unroll
                    for (int mt = 0; mt < 2; mt++)
                        LDSM4(Ah[mt], sAh + aoff[mt] + (kb ^ axor[mt]));
                    u32 Bh[2][4], Bl[2][4];
#pragma unroll
                    for (int p = 0; p < 2; p++) {
                        u32 o = boff[p] + (kb ^ bxor[p]);
                        LDSM4(Bh[p], sBh + o);
                        LDSM4(Bl[p], sBl + o);
                    }
#pragma unroll
                    for (int mt = 0; mt < 2; mt++)
#pragma unroll
                        for (int nt = 0; nt < 4; nt++) {
                            const int p = nt >> 1, q = nt & 1;
                            MMA_F16(acc[mt][nt], Ah[mt], Bh[p][q], Bh[p][q + 2]);
                            MMA_F16(acc[mt][nt], Ah[mt], Bl[p][q], Bl[p][q + 2]);
                        }
                }
                __syncthreads();
            }
        }

        // ---- in-register LSTM cell ----
        u16* Hh = (t & 1) ? g_hh1 : g_hh0;
        u16* Hl = (t & 1) ? g_hl1 : g_hl0;
#pragma unroll
        for (int mt = 0; mt < 2; mt++) {
#pragma unroll
            for (int half = 0; half < 2; half++) {
                const int n = bm + warp_m * 32 + mt * 16 + rl + half * 8;
                float hv[2];
#pragma unroll
                for (int cp = 0; cp < 2; cp++) {
                    const int e = half * 2 + cp;
                    float gi = acc[mt][0][e] + (cp ? xi[mt][half].y : xi[mt][half].x);
                    float gf = acc[mt][1][e] + (cp ? xf[mt][half].y : xf[mt][half].x);
                    float gg = acc[mt][2][e] + (cp ? xg[mt][half].y : xg[mt][half].x);
                    float go = acc[mt][3][e] + (cp ? xo[mt][half].y : xo[mt][half].x);
                    float i_ = 1.f / (1.f + expf(-gi));
                    float f_ = 1.f / (1.f + expf(-gf));
                    float g_ = tanhf(gg);
                    float o_ = 1.f / (1.f + expf(-go));
                    float cc = f_ * c_[mt][e] + i_ * g_;
                    c_[mt][e] = cc;
                    hv[cp] = o_ * tanhf(cc);
                }
                const size_t hi_ = (size_t)n * HID + kidx;
                *(u32*)(Hh + hi_) = f16hi(hv[0], hv[1]);
                *(u32*)(Hl + hi_) = f16lo(hv[0], hv[1]);
                *(float2*)(hs_out + ((size_t)n * TS + t) * HID + kidx) =
                    make_float2(hv[0], hv[1]);
            }
        }

        // ---- device-wide barrier (skip after last step) ----
        if (t < TS - 1) {
            __threadfence();
            __syncthreads();
            if (tid == 0) {
                atomicAdd(&g_bar, 1u);
                const unsigned target = 128u * (unsigned)(t + 1);
                unsigned v;
                do {
                    asm volatile("ld.global.acquire.gpu.b32 %0, [%1];"
                                 : "=r"(v) : "l"(&g_bar));
                    if (v < target) __nanosleep(128);
                } while (v < target);
            }
            __syncthreads();
        }
    }
}

// ===================== small kernels =====================
// fp32 -> fp16 split (lo optional); n4 = n/4
__global__ void conv_split(const float* __restrict__ x, u16* __restrict__ hi,
                           u16* __restrict__ lo, int n4)
{
    int i = blockIdx.x * blockDim.x + threadIdx.x;
    if (i >= n4) return;
    float4 v = ((const float4*)x)[i];
    ((uint2*)hi)[i] = make_uint2(f16hi(v.x, v.y), f16hi(v.z, v.w));
    if (lo) ((uint2*)lo)[i] = make_uint2(f16lo(v.x, v.y), f16lo(v.z, v.w));
}

// fp16 split + gate-interleave permute of a [4096][1024] weight
__global__ void convp(const float* __restrict__ src, u16* __restrict__ hi,
                      u16* __restrict__ lo)
{
    int p = blockIdx.x;
    int orig = perm_orig(p);
    float4 v = ((const float4*)(src + (size_t)orig * 1024))[threadIdx.x];
    size_t o4 = (size_t)p * 256 + threadIdx.x;
    ((uint2*)hi)[o4] = make_uint2(f16hi(v.x, v.y), f16hi(v.z, v.w));
    ((uint2*)lo)[o4] = make_uint2(f16lo(v.x, v.y), f16lo(v.z, v.w));
}

// gather embedding rows as fp16 (blocks < TQ*NQ) + permuted bias (last 16)
__global__ void gather_emb(const int* __restrict__ q, const float* __restrict__ emb,
                           const float* __restrict__ b_ih,
                           const float* __restrict__ b_hh)
{
    int row = blockIdx.x;
    if (row >= TQ * NQ) {
        int p = (row - TQ * NQ) * 256 + threadIdx.x;
        int orig = perm_orig(p);
        g_pbias[p] = b_ih[orig] + b_hh[orig];
        return;
    }
    int t = row / NQ + 1;
    int n = row % NQ;
    int qi = q[n * TQ + (t - 1)];
    float4 v = ((const float4*)(emb + (size_t)qi * EMBED))[threadIdx.x];
    size_t base4 = ((size_t)t * NQ + n) * (EMBED / 4) + threadIdx.x;
    ((uint2*)g_Xhi)[base4] = make_uint2(f16hi(v.x, v.y), f16hi(v.z, v.w));
}

// reduce the 4 img split-K partials + bias -> fp16 X[0] rows 0..511
__global__ void reduce_img(const float* __restrict__ b_img)
{
    int i = blockIdx.x * blockDim.x + threadIdx.x;   // pairs
    int row = i >> 9;
    int c2 = (i & 511) * 2;
    size_t o = (size_t)row * EMBED + c2;
    const size_t P = (size_t)NQ * EMBED;
    float x = g_part[o] + g_part[o + P] + g_part[o + 2 * P] + g_part[o + 3 * P]
              + b_img[c2];
    float y = g_part[o + 1] + g_part[o + 1 + P] + g_part[o + 1 + 2 * P]
              + g_part[o + 1 + 3 * P] + b_img[c2 + 1];
    ((u32*)g_Xhi)[o >> 1] = f16hi(x, y);
}

__global__ void zero_bar() { g_bar = 0u; }

// ===================== host =====================
extern "C" void kernel_launch(void* const* d_in, const int* in_sizes, int n_in,
                              void* d_out, int out_size)
{
    (void)in_sizes; (void)n_in; (void)out_size;
    const int*   questions = (const int*)  d_in[0];
    const float* img       = (const float*)d_in[1];
    const float* emb       = (const float*)d_in[2];
    const float* W_img     = (const float*)d_in[3];
    const float* b_img     = (const float*)d_in[4];
    const float* W_ih      = (const float*)d_in[5];
    const float* W_hh      = (const float*)d_in[6];
    const float* b_ih      = (const float*)d_in[7];
    const float* b_hh      = (const float*)d_in[8];
    const float* W_out     = (const float*)d_in[9];
    const float* b_out     = (const float*)d_in[10];

    float* out_logits = (float*)d_out;                        // [512, 32000]
    float* out_hs     = out_logits + (size_t)NQ * VOCAB;      // [512, 49, 1024]

    u16 *Xhi, *imgh, *Wimgh, *Wimgl, *Wihh, *Wihl, *Whhh, *Whhl,
        *Wouth, *Woutl, *hh0, *hl0;
    float *Xg, *pbias, *part;
    cudaGetSymbolAddress((void**)&Xhi,   g_Xhi);
    cudaGetSymbolAddress((void**)&imgh,  g_imgh);
    cudaGetSymbolAddress((void**)&Wimgh, g_Wimgh);
    cudaGetSymbolAddress((void**)&Wimgl, g_Wimgl);
    cudaGetSymbolAddress((void**)&Wihh,  g_Wihh);
    cudaGetSymbolAddress((void**)&Wihl,  g_Wihl);
    cudaGetSymbolAddress((void**)&Whhh,  g_Whhh);
    cudaGetSymbolAddress((void**)&Whhl,  g_Whhl);
    cudaGetSymbolAddress((void**)&Wouth, g_Wouth);
    cudaGetSymbolAddress((void**)&Woutl, g_Woutl);
    cudaGetSymbolAddress((void**)&hh0,   g_hh0);
    cudaGetSymbolAddress((void**)&hl0,   g_hl0);
    cudaGetSymbolAddress((void**)&Xg,    g_Xg);
    cudaGetSymbolAddress((void**)&pbias, g_pbias);
    cudaGetSymbolAddress((void**)&part,  g_part);

    cudaFuncSetAttribute(tgemm<2>, cudaFuncAttributeMaxDynamicSharedMemorySize,
                         TG2_SMEM);
    cudaFuncSetAttribute(tgemm<3>, cudaFuncAttributeMaxDynamicSharedMemorySize,
                         TG3_SMEM);
    cudaFuncSetAttribute(lstm_persist,
                         cudaFuncAttributeMaxDynamicSharedMemorySize, LP_SMEM);

    // #0: gather embeddings (fp16) + permuted bias
    gather_emb<<<TQ * NQ + 16, 256>>>(questions, emb, b_ih, b_hh);

    // #1-2: conversions for the img GEMM (img: hi only; W_img: hi+lo)
    conv_split<<<(NQ * IMG / 4 + 255) / 256, 256>>>(img, imgh, nullptr,
                                                    NQ * IMG / 4);
    conv_split<<<(HID * IMG / 4 + 255) / 256, 256>>>(W_img, Wimgh, Wimgl,
                                                     HID * IMG / 4);

    // #3 (ncu capture slot): img GEMM, 2-term, split-K=4 -> fp32 partials
    tgemm<2><<<dim3(EMBED / 128, NQ / 128, 4), 256, TG2_SMEM>>>(
        imgh, nullptr, Wimgh, Wimgl, part, nullptr,
        NQ, EMBED, IMG / 4, IMG, nullptr, nullptr);

    // #4: reduce partials + b_img -> fp16 X[0]
    reduce_img<<<(NQ * EMBED / 2) / 256, 256>>>(b_img);

    // #5: permuted split W_ih
    convp<<<G4, 256>>>(W_ih, Wihh, Wihl);

    // #6: Xg = X @ W_ihP^T + pbias   (2-term: X fp16, W split)
    tgemm<2><<<dim3(G4 / 128, (TS * NQ) / 128, 1), 256, TG2_SMEM>>>(
        Xhi, nullptr, Wihh, Wihl, Xg, nullptr,
        TS * NQ, G4, EMBED, EMBED, nullptr, pbias);

    // #7-8: permuted split W_hh; reset device barrier
    convp<<<G4, 256>>>(W_hh, Whhh, Whhl);
    zero_bar<<<1, 1>>>();

    // #9: the whole recurrence in one persistent kernel (2-term fp16)
    lstm_persist<<<128, 512, LP_SMEM>>>(Xg, out_hs);

    // #10-11: logits = h_last @ W_out^T + b_out  (3-term for precision)
    conv_split<<<(VOCAB * HID / 4 + 255) / 256, 256>>>(W_out, Wouth, Woutl,
                                                       VOCAB * HID / 4);
    tgemm<3><<<dim3(VOCAB / 128, NQ / 128, 1), 256, TG3_SMEM>>>(
        hh0, hl0, Wouth, Woutl, out_logits, nullptr,
        NQ, VOCAB, HID, HID, nullptr, b_out);
}

// round 13
// speedup vs baseline: 4.2172x; 1.0333x over previous
#include <cuda_runtime.h>
#include <cuda_fp16.h>
#include <cstdint>
#include <math.h>

typedef unsigned short u16;
typedef unsigned int   u32;

// Problem constants
#define NQ    512
#define TQ    48
#define TS    49        // T+1 steps
#define VOCAB 32000
#define EMBED 1024
#define HID   1024
#define IMG   4096
#define G4    4096      // 4*HID

// ===================== scratch (device globals; no allocs allowed) ==========
__device__ u16  g_Xhi [TS * NQ * EMBED];     // fp16(X) input sequence
__device__ u16  g_imgh[NQ * IMG];            // fp16(img)
__device__ u16  g_Wimgh[HID * IMG],  g_Wimgl[HID * IMG];
__device__ u16  g_Wihh[G4 * EMBED],  g_Wihl[G4 * EMBED];   // PERMUTED rows
__device__ u16  g_Whhh[G4 * HID],    g_Whhl[G4 * HID];     // PERMUTED rows
__device__ u16  g_Wouth[VOCAB * HID], g_Woutl[VOCAB * HID];
__device__ u16  g_hh0[NQ * HID];             // h ping-pong buf 0 (fp16)
__device__ u16  g_hh1[NQ * HID];             // h ping-pong buf 1 (fp16)
__device__ float g_Xg[TS * NQ * G4];         // x@W_ih^T + pbias (permuted cols)
__device__ float g_pbias[G4];                // permuted b_ih + b_hh
__device__ float g_part[4 * NQ * EMBED];     // split-K partials for img GEMM
__device__ unsigned g_bar;                   // device-wide barrier counter

// ===================== PTX helpers =====================
__device__ __forceinline__ u32 smem_to_u32(const void* p) {
    u32 a;
    asm("{ .reg .u64 t; cvta.to.shared.u64 t, %1; cvt.u32.u64 %0, t; }"
        : "=r"(a) : "l"(p));
    return a;
}

#define CP16(dst, src) \
    asm volatile("cp.async.cg.shared.global [%0], [%1], 16;" \
        :: "r"(dst), "l"(src) : "memory")
#define CP_COMMIT() asm volatile("cp.async.commit_group;" ::: "memory")
#define CP_WAIT2()  asm volatile("cp.async.wait_group 2;" ::: "memory")
#define CP_WAIT3()  asm volatile("cp.async.wait_group 3;" ::: "memory")

#define LDSM4(r, addr) \
    asm volatile("ldmatrix.sync.aligned.m8n8.x4.shared.b16 {%0,%1,%2,%3}, [%4];" \
        : "=r"((r)[0]), "=r"((r)[1]), "=r"((r)[2]), "=r"((r)[3]) : "r"(addr))

#define MMA_F16(d, a, b0, b1) \
    asm volatile("mma.sync.aligned.m16n8k16.row.col.f32.f16.f16.f32 " \
        "{%0,%1,%2,%3}, {%4,%5,%6,%7}, {%8,%9}, {%0,%1,%2,%3};" \
        : "+f"((d)[0]), "+f"((d)[1]), "+f"((d)[2]), "+f"((d)[3]) \
        : "r"((a)[0]), "r"((a)[1]), "r"((a)[2]), "r"((a)[3]), "r"(b0), "r"(b1))

// fp16 split: hi = rn_fp16(x) (rel err 2^-12), lo = rn_fp16(x - hi)
__device__ __forceinline__ u32 f16hi(float x, float y) {
    __half2 h = __floats2half2_rn(x, y);
    return *reinterpret_cast<u32*>(&h);
}
__device__ __forceinline__ u32 f16lo(float x, float y) {
    __half2 h = __floats2half2_rn(x, y);
    float rx = x - __low2float(h);
    float ry = y - __high2float(h);
    __half2 l = __floats2half2_rn(rx, ry);
    return *reinterpret_cast<u32*>(&l);
}

// Gate-interleave permutation: permuted row p <- original row
__device__ __forceinline__ int perm_orig(int p) {
    int s = p >> 7, r = p & 127;
    return ((r >> 3) & 3) * 1024 + s * 32 + (r >> 5) * 8 + (r & 7);
}

// ============================================================================
// 2-term fp16 GEMM: C[M,N] = A @ B^T (+Cin +bias1), fp32 accum.
// A fp16 (err 2^-12), B split (hi+lo, full precision).
// 128x128 tile, BK=32, 256 threads (8 warps, 64x32), FOUR-stage cp.async.
// Stage = 3 planes (Ah,Bh,Bl) x 8KB = 24KB; 96KB total -> 2 CTAs/SM.
// blockIdx.z = split-K chunk (kbase=z*K, partial plane z*M*N).
// Requires nch = K/32 >= 3.
// ============================================================================
#define TG_SMEM (4 * 3 * 8192)

__global__ __launch_bounds__(256, 2) void tgemm(
    const u16* __restrict__ Ahi,
    const u16* __restrict__ Bhi, const u16* __restrict__ Blo,
    float* __restrict__ C, int M, int N, int K, int ldk,
    const float* __restrict__ Cin, const float* __restrict__ bias1)
{
    extern __shared__ char smem[];
    const u32 sb = smem_to_u32(smem);
    const int tid = threadIdx.x;
    const int wid = tid >> 5;
    const int lid = tid & 31;
    const int warp_m = wid & 1;
    const int warp_n = wid >> 1;
    const int bm = blockIdx.y * 128;
    const int bn = blockIdx.x * 128;
    const int kbase = blockIdx.z * K;
    if (C) C += (size_t)blockIdx.z * M * N;

    const int lrow8 = (lid & 7) + ((lid >> 3) & 1) * 8;
    const u32 kl = ((lid >> 4) & 1) * 16;
    u32 aoff[4], axor[4], boff[2], bxor[2];
#pragma unroll
    for (int mt = 0; mt < 4; mt++) {
        int r = warp_m * 64 + mt * 16 + lrow8;
        aoff[mt] = (u32)r * 64;
        axor[mt] = (u32)((r >> 1) & 3) << 4;
    }
#pragma unroll
    for (int p = 0; p < 2; p++) {
        int r = warp_n * 32 + p * 16 + lrow8;
        boff[p] = (u32)r * 64;
        bxor[p] = (u32)((r >> 1) & 3) << 4;
    }

    float acc[4][4][4];
#pragma unroll
    for (int i = 0; i < 4; i++)
#pragma unroll
        for (int j = 0; j < 4; j++)
#pragma unroll
            for (int k = 0; k < 4; k++) acc[i][j][k] = 0.f;

    auto issue = [&](int buf, int c) {
        const u32 s0 = sb + (u32)buf * 24576;
        const int k0 = kbase + c * 32;
#pragma unroll
        for (int p = 0; p < 2; p++) {
            int ch  = tid + p * 256;         // 0..511
            int row = ch >> 2;
            int seg = ch & 3;
            u32 doff = (u32)row * 64 +
                       (((u32)seg * 16) ^ ((u32)((row >> 1) & 3) << 4));
            size_t ai = (size_t)(bm + row) * ldk + k0 + seg * 8;
            size_t bi = (size_t)(bn + row) * ldk + k0 + seg * 8;
            CP16(s0 +         doff, Ahi + ai);
            CP16(s0 +  8192 + doff, Bhi + bi);
            CP16(s0 + 16384 + doff, Blo + bi);
        }
    };

    const int nch = K >> 5;
    issue(0, 0); CP_COMMIT();
    issue(1, 1); CP_COMMIT();
    issue(2, 2); CP_COMMIT();

    for (int c = 0; c < nch; c++) {
        if (c + 3 < nch) issue((c + 3) & 3, c + 3);
        CP_COMMIT();
        CP_WAIT3();
        __syncthreads();

        const u32 s0  = sb + (u32)(c & 3) * 24576;
        const u32 sAh = s0, sBh = s0 + 8192, sBl = s0 + 16384;
#pragma unroll
        for (int ks = 0; ks < 2; ks++) {
            const u32 kb = (u32)ks * 32 + kl;
            u32 Ah[4][4];
#pragma unroll
            for (int mt = 0; mt < 4; mt++)
                LDSM4(Ah[mt], sAh + aoff[mt] + (kb ^ axor[mt]));
            u32 Bh[2][4], Bl[2][4];
#pragma unroll
            for (int p = 0; p < 2; p++) {
                u32 o = boff[p] + (kb ^ bxor[p]);
                LDSM4(Bh[p], sBh + o);
                LDSM4(Bl[p], sBl + o);
            }
#pragma unroll
            for (int mt = 0; mt < 4; mt++)
#pragma unroll
                for (int nt = 0; nt < 4; nt++) {
                    const int p = nt >> 1, q = nt & 1;
                    MMA_F16(acc[mt][nt], Ah[mt], Bh[p][q], Bh[p][q + 2]);
                    MMA_F16(acc[mt][nt], Ah[mt], Bl[p][q], Bl[p][q + 2]);
                }
        }
        __syncthreads();
    }

    const int rl = lid >> 2;
    const int cl = (lid & 3) * 2;
#pragma unroll
    for (int mt = 0; mt < 4; mt++) {
#pragma unroll
        for (int nt = 0; nt < 4; nt++) {
            const int row0 = bm + warp_m * 64 + mt * 16 + rl;
            const int col  = bn + warp_n * 32 + nt * 8 + cl;
#pragma unroll
            for (int half = 0; half < 2; half++) {
                const int row = row0 + half * 8;
                float vx = acc[mt][nt][half * 2];
                float vy = acc[mt][nt][half * 2 + 1];
                const size_t gi = (size_t)row * N + col;
                if (Cin) { float2 c2 = *(const float2*)(Cin + gi); vx += c2.x; vy += c2.y; }
                if (bias1) { float2 b2 = *(const float2*)(bias1 + col); vx += b2.x; vy += b2.y; }
                *(float2*)(C + gi) = make_float2(vx, vy);
            }
        }
    }
}

// ============================================================================
// Persistent LSTM recurrence, 2-term fp16. 128 CTAs x 512 threads.
// SMEM: persistent W chunks 0,1 (Wh+Wl, 32KB each, loaded ONCE) +
//       3 rotating stages of (Ah 16KB, Wh 16KB, Wl 16KB) = 208KB total.
// Chunk c: A from rot(c%3); W from P0 (c==0), P1 (c==1), rot(c%3) (c>=2).
// Group order per step: A0,A1,F2 pre-loop; in-loop always-commit; wait2.
// Xg[t] prefetched to registers; c in registers; one device barrier/step.
// ============================================================================
#define LP_SMEM (65536 + 3 * 49152)   // 212992

__global__ __launch_bounds__(512) void lstm_persist(const float* __restrict__ Xg,
                                                    float* __restrict__ hs_out)
{
    extern __shared__ char smem[];
    const u32 sb = smem_to_u32(smem);
    const int tid = threadIdx.x;
    const int wid = tid >> 5;
    const int lid = tid & 31;
    const int warp_m = wid & 3;
    const int warp_q = wid >> 2;
    const int bm   = (blockIdx.x & 3) * 128;
    const int sidx = blockIdx.x >> 2;
    const int bn   = sidx * 128;

    const int lrow8 = (lid & 7) + ((lid >> 3) & 1) * 8;
    const u32 kl = ((lid >> 4) & 1) * 16;
    u32 aoff[2], axor[2], boff[2], bxor[2];
#pragma unroll
    for (int mt = 0; mt < 2; mt++) {
        int r = warp_m * 32 + mt * 16 + lrow8;
        aoff[mt] = (u32)r * 128;
        axor[mt] = (u32)(r & 7) << 4;
    }
#pragma unroll
    for (int p = 0; p < 2; p++) {
        int r = warp_q * 32 + p * 16 + lrow8;
        boff[p] = (u32)r * 128;
        bxor[p] = (u32)(r & 7) << 4;
    }
    const int rl = lid >> 2;
    const int cl = (lid & 3) * 2;
    const int colb = bn + warp_q * 32 + cl;
    const int kidx = sidx * 32 + warp_q * 8 + cl;

    // rotating stage base
    auto RB = [&](int s) -> u32 { return sb + 65536 + (u32)s * 49152; };

    // ---- load persistent W chunks 0,1 ONCE (completes during t=0) ----
#pragma unroll
    for (int p = 0; p < 2; p++) {
#pragma unroll
        for (int pp = 0; pp < 2; pp++) {
            int ch  = tid + pp * 512;       // 0..1023
            int row = ch >> 3;
            int seg = ch & 7;
            u32 doff = (u32)row * 128 + (((u32)seg * 16) ^ ((u32)(row & 7) << 4));
            size_t bi = (size_t)(bn + row) * HID + p * 64 + seg * 8;
            CP16(sb + (u32)p * 32768 +         doff, g_Whhh + bi);
            CP16(sb + (u32)p * 32768 + 16384 + doff, g_Whhl + bi);
        }
    }
    CP_COMMIT();

    float c_[2][4];
#pragma unroll
    for (int i = 0; i < 2; i++)
#pragma unroll
        for (int j = 0; j < 4; j++) c_[i][j] = 0.f;

    for (int t = 0; t < TS; t++) {
        // ---- prefetch Xg[t] into registers ----
        float2 xi[2][2], xf[2][2], xg[2][2], xo[2][2];
#pragma unroll
        for (int mt = 0; mt < 2; mt++)
#pragma unroll
            for (int half = 0; half < 2; half++) {
                const int n = bm + warp_m * 32 + mt * 16 + rl + half * 8;
                const float* xr = Xg + ((size_t)t * NQ + n) * G4 + colb;
                xi[mt][half] = *(const float2*)(xr + 0);
                xf[mt][half] = *(const float2*)(xr + 8);
                xg[mt][half] = *(const float2*)(xr + 16);
                xo[mt][half] = *(const float2*)(xr + 24);
            }

        float acc[2][4][4];
#pragma unroll
        for (int i = 0; i < 2; i++)
#pragma unroll
            for (int j = 0; j < 4; j++)
#pragma unroll
                for (int k = 0; k < 4; k++) acc[i][j][k] = 0.f;

        if (t > 0) {
            const u16* Ahi_ = ((t - 1) & 1) ? g_hh1 : g_hh0;

            auto issue_A = [&](int s, int c) {
                const u32 s0 = RB(s);
                const int k0 = c * 64;
#pragma unroll
                for (int pp = 0; pp < 2; pp++) {
                    int ch  = tid + pp * 512;
                    int row = ch >> 3;
                    int seg = ch & 7;
                    u32 doff = (u32)row * 128 +
                               (((u32)seg * 16) ^ ((u32)(row & 7) << 4));
                    CP16(s0 + doff, Ahi_ + (size_t)(bm + row) * HID + k0 + seg * 8);
                }
            };
            auto issue_full = [&](int s, int c) {
                const u32 s0 = RB(s);
                const int k0 = c * 64;
#pragma unroll
                for (int pp = 0; pp < 2; pp++) {
                    int ch  = tid + pp * 512;
                    int row = ch >> 3;
                    int seg = ch & 7;
                    u32 doff = (u32)row * 128 +
                               (((u32)seg * 16) ^ ((u32)(row & 7) << 4));
                    size_t ai = (size_t)(bm + row) * HID + k0 + seg * 8;
                    size_t bi = (size_t)(bn + row) * HID + k0 + seg * 8;
                    CP16(s0 +         doff, Ahi_ + ai);
                    CP16(s0 + 16384 + doff, g_Whhh + bi);
                    CP16(s0 + 32768 + doff, g_Whhl + bi);
                }
            };

            issue_A(0, 0);    CP_COMMIT();
            issue_A(1, 1);    CP_COMMIT();
            issue_full(2, 2); CP_COMMIT();

#pragma unroll 1
            for (int c = 0; c < 16; c++) {
                CP_WAIT2();
                __syncthreads();
                const u32 sAh = RB(c % 3);
                u32 sBh, sBl;
                if (c == 0)      { sBh = sb;         sBl = sb + 16384; }
                else if (c == 1) { sBh = sb + 32768; sBl = sb + 49152; }
                else             { sBh = sAh + 16384; sBl = sAh + 32768; }
#pragma unroll
                for (int ks = 0; ks < 4; ks++) {
                    const u32 kb = (u32)ks * 32 + kl;
                    u32 Ah[2][4];
#pragma unroll
                    for (int mt = 0; mt < 2; mt++)
                        LDSM4(Ah[mt], sAh + aoff[mt] + (kb ^ axor[mt]));
                    u32 Bh[2][4], Bl[2][4];
#pragma unroll
                    for (int p = 0; p < 2; p++) {
                        u32 o = boff[p] + (kb ^ bxor[p]);
                        LDSM4(Bh[p], sBh + o);
                        LDSM4(Bl[p], sBl + o);
                    }
#pragma unroll
                    for (int mt = 0; mt < 2; mt++)
#pragma unroll
                        for (int nt = 0; nt < 4; nt++) {
                            const int p = nt >> 1, q = nt & 1;
                            MMA_F16(acc[mt][nt], Ah[mt], Bh[p][q], Bh[p][q + 2]);
                            MMA_F16(acc[mt][nt], Ah[mt], Bl[p][q], Bl[p][q + 2]);
                        }
                }
                __syncthreads();
                if (c + 3 < 16) issue_full((c + 3) % 3, c + 3);
                CP_COMMIT();
            }
        }

        // ---- in-register LSTM cell ----
        u16* Hh = (t & 1) ? g_hh1 : g_hh0;
#pragma unroll
        for (int mt = 0; mt < 2; mt++) {
#pragma unroll
            for (int half = 0; half < 2; half++) {
                const int n = bm + warp_m * 32 + mt * 16 + rl + half * 8;
                float hv[2];
#pragma unroll
                for (int cp = 0; cp < 2; cp++) {
                    const int e = half * 2 + cp;
                    float gi = acc[mt][0][e] + (cp ? xi[mt][half].y : xi[mt][half].x);
                    float gf = acc[mt][1][e] + (cp ? xf[mt][half].y : xf[mt][half].x);
                    float gg = acc[mt][2][e] + (cp ? xg[mt][half].y : xg[mt][half].x);
                    float go = acc[mt][3][e] + (cp ? xo[mt][half].y : xo[mt][half].x);
                    float i_ = 1.f / (1.f + expf(-gi));
                    float f_ = 1.f / (1.f + expf(-gf));
                    float g_ = tanhf(gg);
                    float o_ = 1.f / (1.f + expf(-go));
                    float cc = f_ * c_[mt][e] + i_ * g_;
                    c_[mt][e] = cc;
                    hv[cp] = o_ * tanhf(cc);
                }
                *(u32*)(Hh + (size_t)n * HID + kidx) = f16hi(hv[0], hv[1]);
                *(float2*)(hs_out + ((size_t)n * TS + t) * HID + kidx) =
                    make_float2(hv[0], hv[1]);
            }
        }

        // ---- device-wide barrier (skip after last step) ----
        if (t < TS - 1) {
            __threadfence();
            __syncthreads();
            if (tid == 0) {
                atomicAdd(&g_bar, 1u);
                const unsigned target = 128u * (unsigned)(t + 1);
                unsigned v;
                do {
                    asm volatile("ld.global.acquire.gpu.b32 %0, [%1];"
                                 : "=r"(v) : "l"(&g_bar));
                    if (v < target) __nanosleep(64);
                } while (v < target);
            }
            __syncthreads();
        }
    }
}

// ===================== small kernels =====================
__global__ void conv_split(const float* __restrict__ x, u16* __restrict__ hi,
                           u16* __restrict__ lo, int n4)
{
    int i = blockIdx.x * blockDim.x + threadIdx.x;
    if (i >= n4) return;
    float4 v = ((const float4*)x)[i];
    ((uint2*)hi)[i] = make_uint2(f16hi(v.x, v.y), f16hi(v.z, v.w));
    if (lo) ((uint2*)lo)[i] = make_uint2(f16lo(v.x, v.y), f16lo(v.z, v.w));
}

__global__ void convp(const float* __restrict__ src, u16* __restrict__ hi,
                      u16* __restrict__ lo)
{
    int p = blockIdx.x;
    int orig = perm_orig(p);
    float4 v = ((const float4*)(src + (size_t)orig * 1024))[threadIdx.x];
    size_t o4 = (size_t)p * 256 + threadIdx.x;
    ((uint2*)hi)[o4] = make_uint2(f16hi(v.x, v.y), f16hi(v.z, v.w));
    ((uint2*)lo)[o4] = make_uint2(f16lo(v.x, v.y), f16lo(v.z, v.w));
}

__global__ void gather_emb(const int* __restrict__ q, const float* __restrict__ emb,
                           const float* __restrict__ b_ih,
                           const float* __restrict__ b_hh)
{
    int row = blockIdx.x;
    if (row >= TQ * NQ) {
        int p = (row - TQ * NQ) * 256 + threadIdx.x;
        int orig = perm_orig(p);
        g_pbias[p] = b_ih[orig] + b_hh[orig];
        return;
    }
    int t = row / NQ + 1;
    int n = row % NQ;
    int qi = q[n * TQ + (t - 1)];
    float4 v = ((const float4*)(emb + (size_t)qi * EMBED))[threadIdx.x];
    size_t base4 = ((size_t)t * NQ + n) * (EMBED / 4) + threadIdx.x;
    ((uint2*)g_Xhi)[base4] = make_uint2(f16hi(v.x, v.y), f16hi(v.z, v.w));
}

__global__ void reduce_img(const float* __restrict__ b_img)
{
    int i = blockIdx.x * blockDim.x + threadIdx.x;   // pairs
    int row = i >> 9;
    int c2 = (i & 511) * 2;
    size_t o = (size_t)row * EMBED + c2;
    const size_t P = (size_t)NQ * EMBED;
    float x = g_part[o] + g_part[o + P] + g_part[o + 2 * P] + g_part[o + 3 * P]
              + b_img[c2];
    float y = g_part[o + 1] + g_part[o + 1 + P] + g_part[o + 1 + 2 * P]
              + g_part[o + 1 + 3 * P] + b_img[c2 + 1];
    ((u32*)g_Xhi)[o >> 1] = f16hi(x, y);
}

__global__ void zero_bar() { g_bar = 0u; }

// ===================== host =====================
extern "C" void kernel_launch(void* const* d_in, const int* in_sizes, int n_in,
                              void* d_out, int out_size)
{
    (void)in_sizes; (void)n_in; (void)out_size;
    const int*   questions = (const int*)  d_in[0];
    const float* img       = (const float*)d_in[1];
    const float* emb       = (const float*)d_in[2];
    const float* W_img     = (const float*)d_in[3];
    const float* b_img     = (const float*)d_in[4];
    const float* W_ih      = (const float*)d_in[5];
    const float* W_hh      = (const float*)d_in[6];
    const float* b_ih      = (const float*)d_in[7];
    const float* b_hh      = (const float*)d_in[8];
    const float* W_out     = (const float*)d_in[9];
    const float* b_out     = (const float*)d_in[10];

    float* out_logits = (float*)d_out;                        // [512, 32000]
    float* out_hs     = out_logits + (size_t)NQ * VOCAB;      // [512, 49, 1024]

    u16 *Xhi, *imgh, *Wimgh, *Wimgl, *Wihh, *Wihl, *Whhh, *Whhl,
        *Wouth, *Woutl, *hh0;
    float *Xg, *pbias, *part;
    cudaGetSymbolAddress((void**)&Xhi,   g_Xhi);
    cudaGetSymbolAddress((void**)&imgh,  g_imgh);
    cudaGetSymbolAddress((void**)&Wimgh, g_Wimgh);
    cudaGetSymbolAddress((void**)&Wimgl, g_Wimgl);
    cudaGetSymbolAddress((void**)&Wihh,  g_Wihh);
    cudaGetSymbolAddress((void**)&Wihl,  g_Wihl);
    cudaGetSymbolAddress((void**)&Whhh,  g_Whhh);
    cudaGetSymbolAddress((void**)&Whhl,  g_Whhl);
    cudaGetSymbolAddress((void**)&Wouth, g_Wouth);
    cudaGetSymbolAddress((void**)&Woutl, g_Woutl);
    cudaGetSymbolAddress((void**)&hh0,   g_hh0);
    cudaGetSymbolAddress((void**)&Xg,    g_Xg);
    cudaGetSymbolAddress((void**)&pbias, g_pbias);
    cudaGetSymbolAddress((void**)&part,  g_part);

    cudaFuncSetAttribute(tgemm, cudaFuncAttributeMaxDynamicSharedMemorySize,
                         TG_SMEM);
    cudaFuncSetAttribute(lstm_persist,
                         cudaFuncAttributeMaxDynamicSharedMemorySize, LP_SMEM);

    // #0: gather embeddings (fp16) + permuted bias
    gather_emb<<<TQ * NQ + 16, 256>>>(questions, emb, b_ih, b_hh);

    // #1-2: conversions for the img GEMM
    conv_split<<<(NQ * IMG / 4 + 255) / 256, 256>>>(img, imgh, nullptr,
                                                    NQ * IMG / 4);
    conv_split<<<(HID * IMG / 4 + 255) / 256, 256>>>(W_img, Wimgh, Wimgl,
                                                     HID * IMG / 4);

    // #3 (ncu capture slot): img GEMM, split-K=4 -> fp32 partials
    tgemm<<<dim3(EMBED / 128, NQ / 128, 4), 256, TG_SMEM>>>(
        imgh, Wimgh, Wimgl, part, NQ, EMBED, IMG / 4, IMG, nullptr, nullptr);

    // #4: reduce partials + b_img -> fp16 X[0]
    reduce_img<<<(NQ * EMBED / 2) / 256, 256>>>(b_img);

    // #5: permuted split W_ih
    convp<<<G4, 256>>>(W_ih, Wihh, Wihl);

    // #6: Xg = X @ W_ihP^T + pbias
    tgemm<<<dim3(G4 / 128, (TS * NQ) / 128, 1), 256, TG_SMEM>>>(
        Xhi, Wihh, Wihl, Xg, TS * NQ, G4, EMBED, EMBED, nullptr, pbias);

    // #7-8: permuted split W_hh; reset device barrier
    convp<<<G4, 256>>>(W_hh, Whhh, Whhl);
    zero_bar<<<1, 1>>>();

    // #9: the whole recurrence in one persistent kernel
    lstm_persist<<<128, 512, LP_SMEM>>>(Xg, out_hs);

    // #10-11: logits = h_last @ W_out^T + b_out  (2-term; h_48 in buffer 0)
    conv_split<<<(VOCAB * HID / 4 + 255) / 256, 256>>>(W_out, Wouth, Woutl,
                                                       VOCAB * HID / 4);
    tgemm<<<dim3(VOCAB / 128, NQ / 128, 1), 256, TG_SMEM>>>(
        hh0, Wouth, Woutl, out_logits, NQ, VOCAB, HID, HID, nullptr, b_out);
}

// round 15
// speedup vs baseline: 4.9897x; 1.1832x over previous
#include <cuda_runtime.h>
#include <cuda_fp16.h>
#include <cstdint>
#include <math.h>

typedef unsigned short u16;
typedef unsigned int   u32;

// Problem constants
#define NQ    512
#define TQ    48
#define TS    49        // T+1 steps
#define VOCAB 32000
#define EMBED 1024
#define HID   1024
#define IMG   4096
#define G4    4096      // 4*HID

// ===================== scratch (device globals; no allocs allowed) ==========
__device__ u16  g_Xhi [TS * NQ * EMBED];     // fp16(X) input sequence
__device__ u16  g_imgh[NQ * IMG];            // fp16(img)
__device__ u16  g_Wimgh[HID * IMG],  g_Wimgl[HID * IMG];
__device__ u16  g_Wihh[G4 * EMBED];          // PERMUTED rows, fp16 (1-term)
__device__ u16  g_Whhh[G4 * HID],    g_Whhl[G4 * HID];     // PERMUTED rows
__device__ u16  g_Wouth[VOCAB * HID], g_Woutl[VOCAB * HID];
__device__ u16  g_hh0[NQ * HID];             // h ping-pong buf 0 (fp16)
__device__ u16  g_hh1[NQ * HID];             // h ping-pong buf 1 (fp16)
__device__ float g_Xg[TS * NQ * G4];         // x@W_ih^T + pbias (permuted cols)
__device__ float g_pbias[G4];                // permuted b_ih + b_hh
__device__ float g_part[4 * NQ * EMBED];     // split-K partials for img GEMM
__device__ unsigned g_bar;                   // device-wide barrier counter

// ===================== PTX helpers =====================
__device__ __forceinline__ u32 smem_to_u32(const void* p) {
    u32 a;
    asm("{ .reg .u64 t; cvta.to.shared.u64 t, %1; cvt.u32.u64 %0, t; }"
        : "=r"(a) : "l"(p));
    return a;
}

#define CP16(dst, src) \
    asm volatile("cp.async.cg.shared.global [%0], [%1], 16;" \
        :: "r"(dst), "l"(src) : "memory")
#define CP_COMMIT() asm volatile("cp.async.commit_group;" ::: "memory")
#define CP_WAIT2()  asm volatile("cp.async.wait_group 2;" ::: "memory")
#define CP_WAIT3()  asm volatile("cp.async.wait_group 3;" ::: "memory")

#define LDSM4(r, addr) \
    asm volatile("ldmatrix.sync.aligned.m8n8.x4.shared.b16 {%0,%1,%2,%3}, [%4];" \
        : "=r"((r)[0]), "=r"((r)[1]), "=r"((r)[2]), "=r"((r)[3]) : "r"(addr))

#define MMA_F16(d, a, b0, b1) \
    asm volatile("mma.sync.aligned.m16n8k16.row.col.f32.f16.f16.f32 " \
        "{%0,%1,%2,%3}, {%4,%5,%6,%7}, {%8,%9}, {%0,%1,%2,%3};" \
        : "+f"((d)[0]), "+f"((d)[1]), "+f"((d)[2]), "+f"((d)[3]) \
        : "r"((a)[0]), "r"((a)[1]), "r"((a)[2]), "r"((a)[3]), "r"(b0), "r"(b1))

// fp16 split: hi = rn_fp16(x) (rel err 2^-12), lo = rn_fp16(x - hi)
__device__ __forceinline__ u32 f16hi(float x, float y) {
    __half2 h = __floats2half2_rn(x, y);
    return *reinterpret_cast<u32*>(&h);
}
__device__ __forceinline__ u32 f16lo(float x, float y) {
    __half2 h = __floats2half2_rn(x, y);
    float rx = x - __low2float(h);
    float ry = y - __high2float(h);
    __half2 l = __floats2half2_rn(rx, ry);
    return *reinterpret_cast<u32*>(&l);
}

// Gate-interleave permutation: permuted row p <- original row
__device__ __forceinline__ int perm_orig(int p) {
    int s = p >> 7, r = p & 127;
    return ((r >> 3) & 3) * 1024 + s * 32 + (r >> 5) * 8 + (r & 7);
}

// ============================================================================
// fp16 GEMM: C[M,N] = A @ B^T (+Cin +bias1), fp32 accum.
// TERMS=1: A fp16, B fp16 (one MMA/tile; err ~sqrt2 * 2^-12)
// TERMS=2: A fp16, B split hi+lo (two MMAs/tile; err ~2^-12)
// 128x128 tile, BK=32, 256 threads (8 warps, 64x32), FOUR-stage cp.async.
// Stage = (TERMS+1) planes x 8KB. TERMS=1: 64KB total; TERMS=2: 96KB.
// blockIdx.z = split-K chunk (kbase=z*K, partial plane z*M*N).
// Requires nch = K/32 >= 4 for full pipeline (all call sites satisfy).
// ============================================================================
#define TG1_SMEM (4 * 2 * 8192)
#define TG2_SMEM (4 * 3 * 8192)

template <int TERMS>
__global__ __launch_bounds__(256, 2) void tgemm(
    const u16* __restrict__ Ahi,
    const u16* __restrict__ Bhi, const u16* __restrict__ Blo,
    float* __restrict__ C, int M, int N, int K, int ldk,
    const float* __restrict__ Cin, const float* __restrict__ bias1)
{
    extern __shared__ char smem[];
    const u32 sb = smem_to_u32(smem);
    const u32 STAGE = (TERMS + 1) * 8192;
    const int tid = threadIdx.x;
    const int wid = tid >> 5;
    const int lid = tid & 31;
    const int warp_m = wid & 1;
    const int warp_n = wid >> 1;
    const int bm = blockIdx.y * 128;
    const int bn = blockIdx.x * 128;
    const int kbase = blockIdx.z * K;
    if (C) C += (size_t)blockIdx.z * M * N;

    const int lrow8 = (lid & 7) + ((lid >> 3) & 1) * 8;
    const u32 kl = ((lid >> 4) & 1) * 16;
    u32 aoff[4], axor[4], boff[2], bxor[2];
#pragma unroll
    for (int mt = 0; mt < 4; mt++) {
        int r = warp_m * 64 + mt * 16 + lrow8;
        aoff[mt] = (u32)r * 64;
        axor[mt] = (u32)((r >> 1) & 3) << 4;
    }
#pragma unroll
    for (int p = 0; p < 2; p++) {
        int r = warp_n * 32 + p * 16 + lrow8;
        boff[p] = (u32)r * 64;
        bxor[p] = (u32)((r >> 1) & 3) << 4;
    }

    float acc[4][4][4];
#pragma unroll
    for (int i = 0; i < 4; i++)
#pragma unroll
        for (int j = 0; j < 4; j++)
#pragma unroll
            for (int k = 0; k < 4; k++) acc[i][j][k] = 0.f;

    auto issue = [&](int buf, int c) {
        const u32 s0 = sb + (u32)buf * STAGE;
        const int k0 = kbase + c * 32;
#pragma unroll
        for (int p = 0; p < 2; p++) {
            int ch  = tid + p * 256;         // 0..511
            int row = ch >> 2;
            int seg = ch & 3;
            u32 doff = (u32)row * 64 +
                       (((u32)seg * 16) ^ ((u32)((row >> 1) & 3) << 4));
            size_t ai = (size_t)(bm + row) * ldk + k0 + seg * 8;
            size_t bi = (size_t)(bn + row) * ldk + k0 + seg * 8;
            CP16(s0 +         doff, Ahi + ai);
            CP16(s0 +  8192 + doff, Bhi + bi);
            if (TERMS == 2) CP16(s0 + 16384 + doff, Blo + bi);
        }
    };

    const int nch = K >> 5;
    issue(0, 0); CP_COMMIT();
    issue(1, 1); CP_COMMIT();
    issue(2, 2); CP_COMMIT();

    for (int c = 0; c < nch; c++) {
        if (c + 3 < nch) issue((c + 3) & 3, c + 3);
        CP_COMMIT();
        CP_WAIT3();
        __syncthreads();

        const u32 s0  = sb + (u32)(c & 3) * STAGE;
        const u32 sAh = s0, sBh = s0 + 8192, sBl = s0 + 16384;
#pragma unroll
        for (int ks = 0; ks < 2; ks++) {
            const u32 kb = (u32)ks * 32 + kl;
            u32 Ah[4][4];
#pragma unroll
            for (int mt = 0; mt < 4; mt++)
                LDSM4(Ah[mt], sAh + aoff[mt] + (kb ^ axor[mt]));
            u32 Bh[2][4], Bl[2][4];
#pragma unroll
            for (int p = 0; p < 2; p++) {
                u32 o = boff[p] + (kb ^ bxor[p]);
                LDSM4(Bh[p], sBh + o);
                if (TERMS == 2) LDSM4(Bl[p], sBl + o);
            }
#pragma unroll
            for (int mt = 0; mt < 4; mt++)
#pragma unroll
                for (int nt = 0; nt < 4; nt++) {
                    const int p = nt >> 1, q = nt & 1;
                    MMA_F16(acc[mt][nt], Ah[mt], Bh[p][q], Bh[p][q + 2]);
                    if (TERMS == 2)
                        MMA_F16(acc[mt][nt], Ah[mt], Bl[p][q], Bl[p][q + 2]);
                }
        }
        __syncthreads();
    }

    const int rl = lid >> 2;
    const int cl = (lid & 3) * 2;
#pragma unroll
    for (int mt = 0; mt < 4; mt++) {
#pragma unroll
        for (int nt = 0; nt < 4; nt++) {
            const int row0 = bm + warp_m * 64 + mt * 16 + rl;
            const int col  = bn + warp_n * 32 + nt * 8 + cl;
#pragma unroll
            for (int half = 0; half < 2; half++) {
                const int row = row0 + half * 8;
                float vx = acc[mt][nt][half * 2];
                float vy = acc[mt][nt][half * 2 + 1];
                const size_t gi = (size_t)row * N + col;
                if (Cin) { float2 c2 = *(const float2*)(Cin + gi); vx += c2.x; vy += c2.y; }
                if (bias1) { float2 b2 = *(const float2*)(bias1 + col); vx += b2.x; vy += b2.y; }
                *(float2*)(C + gi) = make_float2(vx, vy);
            }
        }
    }
}

// ============================================================================
// Persistent LSTM recurrence, 2-term fp16. 128 CTAs x 512 threads.
// SMEM: persistent W chunks 0,1 (Wh+Wl, 32KB each, loaded ONCE) +
//       3 rotating stages of (Ah 16KB, Wh 16KB, Wl 16KB) = 208KB total.
// Chunk c: A from rot(c%3); W from P0 (c==0), P1 (c==1), rot(c%3) (c>=2).
// Xg[t] prefetched to registers; c in registers; one device barrier/step.
// ============================================================================
#define LP_SMEM (65536 + 3 * 49152)   // 212992

__global__ __launch_bounds__(512) void lstm_persist(const float* __restrict__ Xg,
                                                    float* __restrict__ hs_out)
{
    extern __shared__ char smem[];
    const u32 sb = smem_to_u32(smem);
    const int tid = threadIdx.x;
    const int wid = tid >> 5;
    const int lid = tid & 31;
    const int warp_m = wid & 3;
    const int warp_q = wid >> 2;
    const int bm   = (blockIdx.x & 3) * 128;
    const int sidx = blockIdx.x >> 2;
    const int bn   = sidx * 128;

    const int lrow8 = (lid & 7) + ((lid >> 3) & 1) * 8;
    const u32 kl = ((lid >> 4) & 1) * 16;
    u32 aoff[2], axor[2], boff[2], bxor[2];
#pragma unroll
    for (int mt = 0; mt < 2; mt++) {
        int r = warp_m * 32 + mt * 16 + lrow8;
        aoff[mt] = (u32)r * 128;
        axor[mt] = (u32)(r & 7) << 4;
    }
#pragma unroll
    for (int p = 0; p < 2; p++) {
        int r = warp_q * 32 + p * 16 + lrow8;
        boff[p] = (u32)r * 128;
        bxor[p] = (u32)(r & 7) << 4;
    }
    const int rl = lid >> 2;
    const int cl = (lid & 3) * 2;
    const int colb = bn + warp_q * 32 + cl;
    const int kidx = sidx * 32 + warp_q * 8 + cl;

    auto RB = [&](int s) -> u32 { return sb + 65536 + (u32)s * 49152; };

    // ---- load persistent W chunks 0,1 ONCE (completes during t=0) ----
#pragma unroll
    for (int p = 0; p < 2; p++) {
#pragma unroll
        for (int pp = 0; pp < 2; pp++) {
            int ch  = tid + pp * 512;       // 0..1023
            int row = ch >> 3;
            int seg = ch & 7;
            u32 doff = (u32)row * 128 + (((u32)seg * 16) ^ ((u32)(row & 7) << 4));
            size_t bi = (size_t)(bn + row) * HID + p * 64 + seg * 8;
            CP16(sb + (u32)p * 32768 +         doff, g_Whhh + bi);
            CP16(sb + (u32)p * 32768 + 16384 + doff, g_Whhl + bi);
        }
    }
    CP_COMMIT();

    float c_[2][4];
#pragma unroll
    for (int i = 0; i < 2; i++)
#pragma unroll
        for (int j = 0; j < 4; j++) c_[i][j] = 0.f;

    for (int t = 0; t < TS; t++) {
        // ---- prefetch Xg[t] into registers ----
        float2 xi[2][2], xf[2][2], xg[2][2], xo[2][2];
#pragma unroll
        for (int mt = 0; mt < 2; mt++)
#pragma unroll
            for (int half = 0; half < 2; half++) {
                const int n = bm + warp_m * 32 + mt * 16 + rl + half * 8;
                const float* xr = Xg + ((size_t)t * NQ + n) * G4 + colb;
                xi[mt][half] = *(const float2*)(xr + 0);
                xf[mt][half] = *(const float2*)(xr + 8);
                xg[mt][half] = *(const float2*)(xr + 16);
                xo[mt][half] = *(const float2*)(xr + 24);
            }

        float acc[2][4][4];
#pragma unroll
        for (int i = 0; i < 2; i++)
#pragma unroll
            for (int j = 0; j < 4; j++)
#pragma unroll
                for (int k = 0; k < 4; k++) acc[i][j][k] = 0.f;

        if (t > 0) {
            const u16* Ahi_ = ((t - 1) & 1) ? g_hh1 : g_hh0;

            auto issue_A = [&](int s, int c) {
                const u32 s0 = RB(s);
                const int k0 = c * 64;
#pragma unroll
                for (int pp = 0; pp < 2; pp++) {
                    int ch  = tid + pp * 512;
                    int row = ch >> 3;
                    int seg = ch & 7;
                    u32 doff = (u32)row * 128 +
                               (((u32)seg * 16) ^ ((u32)(row & 7) << 4));
                    CP16(s0 + doff, Ahi_ + (size_t)(bm + row) * HID + k0 + seg * 8);
                }
            };
            auto issue_full = [&](int s, int c) {
                const u32 s0 = RB(s);
                const int k0 = c * 64;
#pragma unroll
                for (int pp = 0; pp < 2; pp++) {
                    int ch  = tid + pp * 512;
                    int row = ch >> 3;
                    int seg = ch & 7;
                    u32 doff = (u32)row * 128 +
                               (((u32)seg * 16) ^ ((u32)(row & 7) << 4));
                    size_t ai = (size_t)(bm + row) * HID + k0 + seg * 8;
                    size_t bi = (size_t)(bn + row) * HID + k0 + seg * 8;
                    CP16(s0 +         doff, Ahi_ + ai);
                    CP16(s0 + 16384 + doff, g_Whhh + bi);
                    CP16(s0 + 32768 + doff, g_Whhl + bi);
                }
            };

            issue_A(0, 0);    CP_COMMIT();
            issue_A(1, 1);    CP_COMMIT();
            issue_full(2, 2); CP_COMMIT();

#pragma unroll 1
            for (int c = 0; c < 16; c++) {
                CP_WAIT2();
                __syncthreads();
                const u32 sAh = RB(c % 3);
                u32 sBh, sBl;
                if (c == 0)      { sBh = sb;         sBl = sb + 16384; }
                else if (c == 1) { sBh = sb + 32768; sBl = sb + 49152; }
                else             { sBh = sAh + 16384; sBl = sAh + 32768; }
#pragma unroll
                for (int ks = 0; ks < 4; ks++) {
                    const u32 kb = (u32)ks * 32 + kl;
                    u32 Ah[2][4];
#pragma unroll
                    for (int mt = 0; mt < 2; mt++)
                        LDSM4(Ah[mt], sAh + aoff[mt] + (kb ^ axor[mt]));
                    u32 Bh[2][4], Bl[2][4];
#pragma unroll
                    for (int p = 0; p < 2; p++) {
                        u32 o = boff[p] + (kb ^ bxor[p]);
                        LDSM4(Bh[p], sBh + o);
                        LDSM4(Bl[p], sBl + o);
                    }
#pragma unroll
                    for (int mt = 0; mt < 2; mt++)
#pragma unroll
                        for (int nt = 0; nt < 4; nt++) {
                            const int p = nt >> 1, q = nt & 1;
                            MMA_F16(acc[mt][nt], Ah[mt], Bh[p][q], Bh[p][q + 2]);
                            MMA_F16(acc[mt][nt], Ah[mt], Bl[p][q], Bl[p][q + 2]);
                        }
                }
                __syncthreads();
                if (c + 3 < 16) issue_full((c + 3) % 3, c + 3);
                CP_COMMIT();
            }
        }

        // ---- in-register LSTM cell ----
        u16* Hh = (t & 1) ? g_hh1 : g_hh0;
#pragma unroll
        for (int mt = 0; mt < 2; mt++) {
#pragma unroll
            for (int half = 0; half < 2; half++) {
                const int n = bm + warp_m * 32 + mt * 16 + rl + half * 8;
                float hv[2];
#pragma unroll
                for (int cp = 0; cp < 2; cp++) {
                    const int e = half * 2 + cp;
                    float gi = acc[mt][0][e] + (cp ? xi[mt][half].y : xi[mt][half].x);
                    float gf = acc[mt][1][e] + (cp ? xf[mt][half].y : xf[mt][half].x);
                    float gg = acc[mt][2][e] + (cp ? xg[mt][half].y : xg[mt][half].x);
                    float go = acc[mt][3][e] + (cp ? xo[mt][half].y : xo[mt][half].x);
                    float i_ = 1.f / (1.f + expf(-gi));
                    float f_ = 1.f / (1.f + expf(-gf));
                    float g_ = tanhf(gg);
                    float o_ = 1.f / (1.f + expf(-go));
                    float cc = f_ * c_[mt][e] + i_ * g_;
                    c_[mt][e] = cc;
                    hv[cp] = o_ * tanhf(cc);
                }
                *(u32*)(Hh + (size_t)n * HID + kidx) = f16hi(hv[0], hv[1]);
                *(float2*)(hs_out + ((size_t)n * TS + t) * HID + kidx) =
                    make_float2(hv[0], hv[1]);
            }
        }

        // ---- device-wide barrier (skip after last step) ----
        if (t < TS - 1) {
            __threadfence();
            __syncthreads();
            if (tid == 0) {
                atomicAdd(&g_bar, 1u);
                const unsigned target = 128u * (unsigned)(t + 1);
                unsigned v;
                do {
                    asm volatile("ld.global.acquire.gpu.b32 %0, [%1];"
                                 : "=r"(v) : "l"(&g_bar));
                    if (v < target) __nanosleep(64);
                } while (v < target);
            }
            __syncthreads();
        }
    }
}

// ===================== small kernels =====================
__global__ void conv_split(const float* __restrict__ x, u16* __restrict__ hi,
                           u16* __restrict__ lo, int n4)
{
    int i = blockIdx.x * blockDim.x + threadIdx.x;
    if (i >= n4) return;
    float4 v = ((const float4*)x)[i];
    ((uint2*)hi)[i] = make_uint2(f16hi(v.x, v.y), f16hi(v.z, v.w));
    if (lo) ((uint2*)lo)[i] = make_uint2(f16lo(v.x, v.y), f16lo(v.z, v.w));
}

// fp16 (+ optional lo) + gate-interleave permute of a [4096][1024] weight
__global__ void convp(const float* __restrict__ src, u16* __restrict__ hi,
                      u16* __restrict__ lo)
{
    int p = blockIdx.x;
    int orig = perm_orig(p);
    float4 v = ((const float4*)(src + (size_t)orig * 1024))[threadIdx.x];
    size_t o4 = (size_t)p * 256 + threadIdx.x;
    ((uint2*)hi)[o4] = make_uint2(f16hi(v.x, v.y), f16hi(v.z, v.w));
    if (lo) ((uint2*)lo)[o4] = make_uint2(f16lo(v.x, v.y), f16lo(v.z, v.w));
}

__global__ void gather_emb(const int* __restrict__ q, const float* __restrict__ emb,
                           const float* __restrict__ b_ih,
                           const float* __restrict__ b_hh)
{
    int row = blockIdx.x;
    if (row >= TQ * NQ) {
        int p = (row - TQ * NQ) * 256 + threadIdx.x;
        int orig = perm_orig(p);
        g_pbias[p] = b_ih[orig] + b_hh[orig];
        return;
    }
    int t = row / NQ + 1;
    int n = row % NQ;
    int qi = q[n * TQ + (t - 1)];
    float4 v = ((const float4*)(emb + (size_t)qi * EMBED))[threadIdx.x];
    size_t base4 = ((size_t)t * NQ + n) * (EMBED / 4) + threadIdx.x;
    ((uint2*)g_Xhi)[base4] = make_uint2(f16hi(v.x, v.y), f16hi(v.z, v.w));
}

__global__ void reduce_img(const float* __restrict__ b_img)
{
    int i = blockIdx.x * blockDim.x + threadIdx.x;   // pairs
    int row = i >> 9;
    int c2 = (i & 511) * 2;
    size_t o = (size_t)row * EMBED + c2;
    const size_t P = (size_t)NQ * EMBED;
    float x = g_part[o] + g_part[o + P] + g_part[o + 2 * P] + g_part[o + 3 * P]
              + b_img[c2];
    float y = g_part[o + 1] + g_part[o + 1 + P] + g_part[o + 1 + 2 * P]
              + g_part[o + 1 + 3 * P] + b_img[c2 + 1];
    ((u32*)g_Xhi)[o >> 1] = f16hi(x, y);
}

__global__ void zero_bar() { g_bar = 0u; }

// ===================== host =====================
extern "C" void kernel_launch(void* const* d_in, const int* in_sizes, int n_in,
                              void* d_out, int out_size)
{
    (void)in_sizes; (void)n_in; (void)out_size;
    const int*   questions = (const int*)  d_in[0];
    const float* img       = (const float*)d_in[1];
    const float* emb       = (const float*)d_in[2];
    const float* W_img     = (const float*)d_in[3];
    const float* b_img     = (const float*)d_in[4];
    const float* W_ih      = (const float*)d_in[5];
    const float* W_hh      = (const float*)d_in[6];
    const float* b_ih      = (const float*)d_in[7];
    const float* b_hh      = (const float*)d_in[8];
    const float* W_out     = (const float*)d_in[9];
    const float* b_out     = (const float*)d_in[10];

    float* out_logits = (float*)d_out;                        // [512, 32000]
    float* out_hs     = out_logits + (size_t)NQ * VOCAB;      // [512, 49, 1024]

    u16 *Xhi, *imgh, *Wimgh, *Wimgl, *Wihh, *Whhh, *Whhl, *Wouth, *Woutl, *hh0;
    float *Xg, *pbias, *part;
    cudaGetSymbolAddress((void**)&Xhi,   g_Xhi);
    cudaGetSymbolAddress((void**)&imgh,  g_imgh);
    cudaGetSymbolAddress((void**)&Wimgh, g_Wimgh);
    cudaGetSymbolAddress((void**)&Wimgl, g_Wimgl);
    cudaGetSymbolAddress((void**)&Wihh,  g_Wihh);
    cudaGetSymbolAddress((void**)&Whhh,  g_Whhh);
    cudaGetSymbolAddress((void**)&Whhl,  g_Whhl);
    cudaGetSymbolAddress((void**)&Wouth, g_Wouth);
    cudaGetSymbolAddress((void**)&Woutl, g_Woutl);
    cudaGetSymbolAddress((void**)&hh0,   g_hh0);
    cudaGetSymbolAddress((void**)&Xg,    g_Xg);
    cudaGetSymbolAddress((void**)&pbias, g_pbias);
    cudaGetSymbolAddress((void**)&part,  g_part);

    cudaFuncSetAttribute(tgemm<1>, cudaFuncAttributeMaxDynamicSharedMemorySize,
                         TG1_SMEM);
    cudaFuncSetAttribute(tgemm<2>, cudaFuncAttributeMaxDynamicSharedMemorySize,
                         TG2_SMEM);
    cudaFuncSetAttribute(lstm_persist,
                         cudaFuncAttributeMaxDynamicSharedMemorySize, LP_SMEM);

    // #0: gather embeddings (fp16) + permuted bias
    gather_emb<<<TQ * NQ + 16, 256>>>(questions, emb, b_ih, b_hh);

    // #1-2: conversions for the img GEMM
    conv_split<<<(NQ * IMG / 4 + 255) / 256, 256>>>(img, imgh, nullptr,
                                                    NQ * IMG / 4);
    conv_split<<<(HID * IMG / 4 + 255) / 256, 256>>>(W_img, Wimgh, Wimgl,
                                                     HID * IMG / 4);

    // #3 (ncu capture slot): img GEMM, 2-term, split-K=4 -> fp32 partials
    tgemm<2><<<dim3(EMBED / 128, NQ / 128, 4), 256, TG2_SMEM>>>(
        imgh, Wimgh, Wimgl, part, NQ, EMBED, IMG / 4, IMG, nullptr, nullptr);

    // #4: reduce partials + b_img -> fp16 X[0]
    reduce_img<<<(NQ * EMBED / 2) / 256, 256>>>(b_img);

    // #5: permuted fp16 W_ih (hi only — 1-term Xg)
    convp<<<G4, 256>>>(W_ih, Wihh, nullptr);

    // #6: Xg = X @ W_ihP^T + pbias   (1-TERM: halved MMA work)
    tgemm<1><<<dim3(G4 / 128, (TS * NQ) / 128, 1), 256, TG1_SMEM>>>(
        Xhi, Wihh, nullptr, Xg, TS * NQ, G4, EMBED, EMBED, nullptr, pbias);

    // #7-8: permuted split W_hh; reset device barrier
    convp<<<G4, 256>>>(W_hh, Whhh, Whhl);
    zero_bar<<<1, 1>>>();

    // #9: the whole recurrence in one persistent kernel (2-term)
    lstm_persist<<<128, 512, LP_SMEM>>>(Xg, out_hs);

    // #10-11: logits = h_last @ W_out^T + b_out  (2-term; h_48 in buffer 0)
    conv_split<<<(VOCAB * HID / 4 + 255) / 256, 256>>>(W_out, Wouth, Woutl,
                                                       VOCAB * HID / 4);
    tgemm<2><<<dim3(VOCAB / 128, NQ / 128, 1), 256, TG2_SMEM>>>(
        hh0, Wouth, Woutl, out_logits, NQ, VOCAB, HID, HID, nullptr, b_out);
}

// round 17
// speedup vs baseline: 6.7351x; 1.3498x over previous
#include <cuda_runtime.h>
#include <cuda_fp16.h>
#include <cstdint>
#include <math.h>

typedef unsigned short u16;
typedef unsigned int   u32;

// Problem constants
#define NQ    512
#define TQ    48
#define TS    49        // T+1 steps
#define VOCAB 32000
#define EMBED 1024
#define HID   1024
#define IMG   4096
#define G4    4096      // 4*HID

// ===================== scratch (device globals; no allocs allowed) ==========
__device__ u16  g_Xhi [TS * NQ * EMBED];     // fp16(X) input sequence
__device__ u16  g_imgh[NQ * IMG];            // fp16(img)
__device__ u16  g_Wimgh[HID * IMG],  g_Wimgl[HID * IMG];
__device__ u16  g_Wihh[G4 * EMBED];          // PERMUTED rows, fp16
__device__ u16  g_Whhh[G4 * HID];            // PERMUTED rows, fp16 (1-term)
__device__ u16  g_Wouth[VOCAB * HID];        // fp16 (1-term)
__device__ u16  g_hh0[NQ * HID];             // h ping-pong buf 0 (fp16)
__device__ u16  g_hh1[NQ * HID];             // h ping-pong buf 1 (fp16)
__device__ u16  g_Xg16[TS * NQ * G4];        // fp16(x@W_ih^T + pbias), permuted
__device__ float g_pbias[G4];                // permuted b_ih + b_hh
__device__ float g_part[4 * NQ * EMBED];     // split-K partials for img GEMM
__device__ unsigned g_bar;                   // device-wide barrier counter

// ===================== PTX helpers =====================
__device__ __forceinline__ u32 smem_to_u32(const void* p) {
    u32 a;
    asm("{ .reg .u64 t; cvta.to.shared.u64 t, %1; cvt.u32.u64 %0, t; }"
        : "=r"(a) : "l"(p));
    return a;
}

#define CP16(dst, src) \
    asm volatile("cp.async.cg.shared.global [%0], [%1], 16;" \
        :: "r"(dst), "l"(src) : "memory")
#define CP_COMMIT() asm volatile("cp.async.commit_group;" ::: "memory")
#define CP_WAIT2()  asm volatile("cp.async.wait_group 2;" ::: "memory")
#define CP_WAIT3()  asm volatile("cp.async.wait_group 3;" ::: "memory")

#define LDSM4(r, addr) \
    asm volatile("ldmatrix.sync.aligned.m8n8.x4.shared.b16 {%0,%1,%2,%3}, [%4];" \
        : "=r"((r)[0]), "=r"((r)[1]), "=r"((r)[2]), "=r"((r)[3]) : "r"(addr))

#define MMA_F16(d, a, b0, b1) \
    asm volatile("mma.sync.aligned.m16n8k16.row.col.f32.f16.f16.f32 " \
        "{%0,%1,%2,%3}, {%4,%5,%6,%7}, {%8,%9}, {%0,%1,%2,%3};" \
        : "+f"((d)[0]), "+f"((d)[1]), "+f"((d)[2]), "+f"((d)[3]) \
        : "r"((a)[0]), "r"((a)[1]), "r"((a)[2]), "r"((a)[3]), "r"(b0), "r"(b1))

// fp16 split: hi = rn_fp16(x) (rel err 2^-12), lo = rn_fp16(x - hi)
__device__ __forceinline__ u32 f16hi(float x, float y) {
    __half2 h = __floats2half2_rn(x, y);
    return *reinterpret_cast<u32*>(&h);
}
__device__ __forceinline__ u32 f16lo(float x, float y) {
    __half2 h = __floats2half2_rn(x, y);
    float rx = x - __low2float(h);
    float ry = y - __high2float(h);
    __half2 l = __floats2half2_rn(rx, ry);
    return *reinterpret_cast<u32*>(&l);
}

// Gate-interleave permutation: permuted row p <- original row
__device__ __forceinline__ int perm_orig(int p) {
    int s = p >> 7, r = p & 127;
    return ((r >> 3) & 3) * 1024 + s * 32 + (r >> 5) * 8 + (r & 7);
}

// ============================================================================
// fp16 GEMM: C = A @ B^T (+Cin +bias1), fp32 accum.
// TERMS=1: B fp16 (one MMA/tile). TERMS=2: B split hi+lo (two MMAs/tile).
// Output: fp32 C, or fp16 C16 (when non-null; used for the Xg tensor).
// 128x128 tile, BK=32, 256 threads (8 warps, 64x32), FOUR-stage cp.async.
// blockIdx.z = split-K chunk (kbase=z*K, partial plane z*M*N when C).
// ============================================================================
#define TG1_SMEM (4 * 2 * 8192)
#define TG2_SMEM (4 * 3 * 8192)

template <int TERMS>
__global__ __launch_bounds__(256, 2) void tgemm(
    const u16* __restrict__ Ahi,
    const u16* __restrict__ Bhi, const u16* __restrict__ Blo,
    float* __restrict__ C, u16* __restrict__ C16,
    int M, int N, int K, int ldk,
    const float* __restrict__ Cin, const float* __restrict__ bias1)
{
    extern __shared__ char smem[];
    const u32 sb = smem_to_u32(smem);
    const u32 STAGE = (TERMS + 1) * 8192;
    const int tid = threadIdx.x;
    const int wid = tid >> 5;
    const int lid = tid & 31;
    const int warp_m = wid & 1;
    const int warp_n = wid >> 1;
    const int bm = blockIdx.y * 128;
    const int bn = blockIdx.x * 128;
    const int kbase = blockIdx.z * K;
    if (C) C += (size_t)blockIdx.z * M * N;

    const int lrow8 = (lid & 7) + ((lid >> 3) & 1) * 8;
    const u32 kl = ((lid >> 4) & 1) * 16;
    u32 aoff[4], axor[4], boff[2], bxor[2];
#pragma unroll
    for (int mt = 0; mt < 4; mt++) {
        int r = warp_m * 64 + mt * 16 + lrow8;
        aoff[mt] = (u32)r * 64;
        axor[mt] = (u32)((r >> 1) & 3) << 4;
    }
#pragma unroll
    for (int p = 0; p < 2; p++) {
        int r = warp_n * 32 + p * 16 + lrow8;
        boff[p] = (u32)r * 64;
        bxor[p] = (u32)((r >> 1) & 3) << 4;
    }

    float acc[4][4][4];
#pragma unroll
    for (int i = 0; i < 4; i++)
#pragma unroll
        for (int j = 0; j < 4; j++)
#pragma unroll
            for (int k = 0; k < 4; k++) acc[i][j][k] = 0.f;

    auto issue = [&](int buf, int c) {
        const u32 s0 = sb + (u32)buf * STAGE;
        const int k0 = kbase + c * 32;
#pragma unroll
        for (int p = 0; p < 2; p++) {
            int ch  = tid + p * 256;         // 0..511
            int row = ch >> 2;
            int seg = ch & 3;
            u32 doff = (u32)row * 64 +
                       (((u32)seg * 16) ^ ((u32)((row >> 1) & 3) << 4));
            size_t ai = (size_t)(bm + row) * ldk + k0 + seg * 8;
            size_t bi = (size_t)(bn + row) * ldk + k0 + seg * 8;
            CP16(s0 +         doff, Ahi + ai);
            CP16(s0 +  8192 + doff, Bhi + bi);
            if (TERMS == 2) CP16(s0 + 16384 + doff, Blo + bi);
        }
    };

    const int nch = K >> 5;
    issue(0, 0); CP_COMMIT();
    issue(1, 1); CP_COMMIT();
    issue(2, 2); CP_COMMIT();

    for (int c = 0; c < nch; c++) {
        if (c + 3 < nch) issue((c + 3) & 3, c + 3);
        CP_COMMIT();
        CP_WAIT3();
        __syncthreads();

        const u32 s0  = sb + (u32)(c & 3) * STAGE;
        const u32 sAh = s0, sBh = s0 + 8192, sBl = s0 + 16384;
#pragma unroll
        for (int ks = 0; ks < 2; ks++) {
            const u32 kb = (u32)ks * 32 + kl;
            u32 Ah[4][4];
#pragma unroll
            for (int mt = 0; mt < 4; mt++)
                LDSM4(Ah[mt], sAh + aoff[mt] + (kb ^ axor[mt]));
            u32 Bh[2][4], Bl[2][4];
#pragma unroll
            for (int p = 0; p < 2; p++) {
                u32 o = boff[p] + (kb ^ bxor[p]);
                LDSM4(Bh[p], sBh + o);
                if (TERMS == 2) LDSM4(Bl[p], sBl + o);
            }
#pragma unroll
            for (int mt = 0; mt < 4; mt++)
#pragma unroll
                for (int nt = 0; nt < 4; nt++) {
                    const int p = nt >> 1, q = nt & 1;
                    MMA_F16(acc[mt][nt], Ah[mt], Bh[p][q], Bh[p][q + 2]);
                    if (TERMS == 2)
                        MMA_F16(acc[mt][nt], Ah[mt], Bl[p][q], Bl[p][q + 2]);
                }
        }
        __syncthreads();
    }

    const int rl = lid >> 2;
    const int cl = (lid & 3) * 2;
#pragma unroll
    for (int mt = 0; mt < 4; mt++) {
#pragma unroll
        for (int nt = 0; nt < 4; nt++) {
            const int row0 = bm + warp_m * 64 + mt * 16 + rl;
            const int col  = bn + warp_n * 32 + nt * 8 + cl;
#pragma unroll
            for (int half = 0; half < 2; half++) {
                const int row = row0 + half * 8;
                float vx = acc[mt][nt][half * 2];
                float vy = acc[mt][nt][half * 2 + 1];
                const size_t gi = (size_t)row * N + col;
                if (Cin) { float2 c2 = *(const float2*)(Cin + gi); vx += c2.x; vy += c2.y; }
                if (bias1) { float2 b2 = *(const float2*)(bias1 + col); vx += b2.x; vy += b2.y; }
                if (C16) *(u32*)(C16 + gi) = f16hi(vx, vy);
                else     *(float2*)(C + gi) = make_float2(vx, vy);
            }
        }
    }
}

// ============================================================================
// Persistent LSTM recurrence, 1-TERM fp16 (fp16(h) @ fp16(W_hh)).
// 128 CTAs x 512 threads. SMEM: pinned Wh chunks 0,1 (16KB each, loaded ONCE)
// + 3 rotating stages of (Ah 16KB, Wh 16KB) = 128KB total.
// Chunk c: A from rot(c%3); W from P0 (c==0), P1 (c==1), rot(c%3) (c>=2).
// Xg (fp16) prefetched to registers; c in registers; one device barrier/step.
// ============================================================================
#define LP_SMEM (32768 + 3 * 32768)   // 131072

__global__ __launch_bounds__(512) void lstm_persist(const u16* __restrict__ Xg,
                                                    float* __restrict__ hs_out)
{
    extern __shared__ char smem[];
    const u32 sb = smem_to_u32(smem);
    const int tid = threadIdx.x;
    const int wid = tid >> 5;
    const int lid = tid & 31;
    const int warp_m = wid & 3;
    const int warp_q = wid >> 2;
    const int bm   = (blockIdx.x & 3) * 128;
    const int sidx = blockIdx.x >> 2;
    const int bn   = sidx * 128;

    const int lrow8 = (lid & 7) + ((lid >> 3) & 1) * 8;
    const u32 kl = ((lid >> 4) & 1) * 16;
    u32 aoff[2], axor[2], boff[2], bxor[2];
#pragma unroll
    for (int mt = 0; mt < 2; mt++) {
        int r = warp_m * 32 + mt * 16 + lrow8;
        aoff[mt] = (u32)r * 128;
        axor[mt] = (u32)(r & 7) << 4;
    }
#pragma unroll
    for (int p = 0; p < 2; p++) {
        int r = warp_q * 32 + p * 16 + lrow8;
        boff[p] = (u32)r * 128;
        bxor[p] = (u32)(r & 7) << 4;
    }
    const int rl = lid >> 2;
    const int cl = (lid & 3) * 2;
    const int colb = bn + warp_q * 32 + cl;
    const int kidx = sidx * 32 + warp_q * 8 + cl;

    auto RB = [&](int s) -> u32 { return sb + 32768 + (u32)s * 32768; };

    // ---- load pinned Wh chunks 0,1 ONCE (completes during t=0) ----
#pragma unroll
    for (int p = 0; p < 2; p++) {
#pragma unroll
        for (int pp = 0; pp < 2; pp++) {
            int ch  = tid + pp * 512;       // 0..1023
            int row = ch >> 3;
            int seg = ch & 7;
            u32 doff = (u32)row * 128 + (((u32)seg * 16) ^ ((u32)(row & 7) << 4));
            size_t bi = (size_t)(bn + row) * HID + p * 64 + seg * 8;
            CP16(sb + (u32)p * 16384 + doff, g_Whhh + bi);
        }
    }
    CP_COMMIT();

    float c_[2][4];
#pragma unroll
    for (int i = 0; i < 2; i++)
#pragma unroll
        for (int j = 0; j < 4; j++) c_[i][j] = 0.f;

    for (int t = 0; t < TS; t++) {
        // ---- prefetch Xg[t] (fp16) into registers ----
        float2 xi[2][2], xf[2][2], xg[2][2], xo[2][2];
#pragma unroll
        for (int mt = 0; mt < 2; mt++)
#pragma unroll
            for (int half = 0; half < 2; half++) {
                const int n = bm + warp_m * 32 + mt * 16 + rl + half * 8;
                const u16* xr = Xg + ((size_t)t * NQ + n) * G4 + colb;
                xi[mt][half] = __half22float2(*(const __half2*)(xr + 0));
                xf[mt][half] = __half22float2(*(const __half2*)(xr + 8));
                xg[mt][half] = __half22float2(*(const __half2*)(xr + 16));
                xo[mt][half] = __half22float2(*(const __half2*)(xr + 24));
            }

        float acc[2][4][4];
#pragma unroll
        for (int i = 0; i < 2; i++)
#pragma unroll
            for (int j = 0; j < 4; j++)
#pragma unroll
                for (int k = 0; k < 4; k++) acc[i][j][k] = 0.f;

        if (t > 0) {
            const u16* Ahi_ = ((t - 1) & 1) ? g_hh1 : g_hh0;

            auto issue_A = [&](int s, int c) {
                const u32 s0 = RB(s);
                const int k0 = c * 64;
#pragma unroll
                for (int pp = 0; pp < 2; pp++) {
                    int ch  = tid + pp * 512;
                    int row = ch >> 3;
                    int seg = ch & 7;
                    u32 doff = (u32)row * 128 +
                               (((u32)seg * 16) ^ ((u32)(row & 7) << 4));
                    CP16(s0 + doff, Ahi_ + (size_t)(bm + row) * HID + k0 + seg * 8);
                }
            };
            auto issue_full = [&](int s, int c) {
                const u32 s0 = RB(s);
                const int k0 = c * 64;
#pragma unroll
                for (int pp = 0; pp < 2; pp++) {
                    int ch  = tid + pp * 512;
                    int row = ch >> 3;
                    int seg = ch & 7;
                    u32 doff = (u32)row * 128 +
                               (((u32)seg * 16) ^ ((u32)(row & 7) << 4));
                    size_t ai = (size_t)(bm + row) * HID + k0 + seg * 8;
                    size_t bi = (size_t)(bn + row) * HID + k0 + seg * 8;
                    CP16(s0 +         doff, Ahi_ + ai);
                    CP16(s0 + 16384 + doff, g_Whhh + bi);
                }
            };

            issue_A(0, 0);    CP_COMMIT();
            issue_A(1, 1);    CP_COMMIT();
            issue_full(2, 2); CP_COMMIT();

#pragma unroll 1
            for (int c = 0; c < 16; c++) {
                CP_WAIT2();
                __syncthreads();
                const u32 sAh = RB(c % 3);
                u32 sBh;
                if (c == 0)      sBh = sb;
                else if (c == 1) sBh = sb + 16384;
                else             sBh = sAh + 16384;
#pragma unroll
                for (int ks = 0; ks < 4; ks++) {
                    const u32 kb = (u32)ks * 32 + kl;
                    u32 Ah[2][4];
#pragma unroll
                    for (int mt = 0; mt < 2; mt++)
                        LDSM4(Ah[mt], sAh + aoff[mt] + (kb ^ axor[mt]));
                    u32 Bh[2][4];
#pragma unroll
                    for (int p = 0; p < 2; p++)
                        LDSM4(Bh[p], sBh + boff[p] + (kb ^ bxor[p]));
#pragma unroll
                    for (int mt = 0; mt < 2; mt++)
#pragma unroll
                        for (int nt = 0; nt < 4; nt++) {
                            const int p = nt >> 1, q = nt & 1;
                            MMA_F16(acc[mt][nt], Ah[mt], Bh[p][q], Bh[p][q + 2]);
                        }
                }
                __syncthreads();
                if (c + 3 < 16) issue_full((c + 3) % 3, c + 3);
                CP_COMMIT();
            }
        }

        // ---- in-register LSTM cell ----
        u16* Hh = (t & 1) ? g_hh1 : g_hh0;
#pragma unroll
        for (int mt = 0; mt < 2; mt++) {
#pragma unroll
            for (int half = 0; half < 2; half++) {
                const int n = bm + warp_m * 32 + mt * 16 + rl + half * 8;
                float hv[2];
#pragma unroll
                for (int cp = 0; cp < 2; cp++) {
                    const int e = half * 2 + cp;
                    float gi = acc[mt][0][e] + (cp ? xi[mt][half].y : xi[mt][half].x);
                    float gf = acc[mt][1][e] + (cp ? xf[mt][half].y : xf[mt][half].x);
                    float gg = acc[mt][2][e] + (cp ? xg[mt][half].y : xg[mt][half].x);
                    float go = acc[mt][3][e] + (cp ? xo[mt][half].y : xo[mt][half].x);
                    float i_ = 1.f / (1.f + expf(-gi));
                    float f_ = 1.f / (1.f + expf(-gf));
                    float g_ = tanhf(gg);
                    float o_ = 1.f / (1.f + expf(-go));
                    float cc = f_ * c_[mt][e] + i_ * g_;
                    c_[mt][e] = cc;
                    hv[cp] = o_ * tanhf(cc);
                }
                *(u32*)(Hh + (size_t)n * HID + kidx) = f16hi(hv[0], hv[1]);
                *(float2*)(hs_out + ((size_t)n * TS + t) * HID + kidx) =
                    make_float2(hv[0], hv[1]);
            }
        }

        // ---- device-wide barrier (skip after last step) ----
        if (t < TS - 1) {
            __threadfence();
            __syncthreads();
            if (tid == 0) {
                atomicAdd(&g_bar, 1u);
                const unsigned target = 128u * (unsigned)(t + 1);
                unsigned v;
                do {
                    asm volatile("ld.global.acquire.gpu.b32 %0, [%1];"
                                 : "=r"(v) : "l"(&g_bar));
                    if (v < target) __nanosleep(64);
                } while (v < target);
            }
            __syncthreads();
        }
    }
}

// ===================== small kernels =====================
__global__ void conv_split(const float* __restrict__ x, u16* __restrict__ hi,
                           u16* __restrict__ lo, int n4)
{
    int i = blockIdx.x * blockDim.x + threadIdx.x;
    if (i >= n4) return;
    float4 v = ((const float4*)x)[i];
    ((uint2*)hi)[i] = make_uint2(f16hi(v.x, v.y), f16hi(v.z, v.w));
    if (lo) ((uint2*)lo)[i] = make_uint2(f16lo(v.x, v.y), f16lo(v.z, v.w));
}

// fp16 (+ optional lo) + gate-interleave permute of a [4096][1024] weight
__global__ void convp(const float* __restrict__ src, u16* __restrict__ hi,
                      u16* __restrict__ lo)
{
    int p = blockIdx.x;
    int orig = perm_orig(p);
    float4 v = ((const float4*)(src + (size_t)orig * 1024))[threadIdx.x];
    size_t o4 = (size_t)p * 256 + threadIdx.x;
    ((uint2*)hi)[o4] = make_uint2(f16hi(v.x, v.y), f16hi(v.z, v.w));
    if (lo) ((uint2*)lo)[o4] = make_uint2(f16lo(v.x, v.y), f16lo(v.z, v.w));
}

__global__ void gather_emb(const int* __restrict__ q, const float* __restrict__ emb,
                           const float* __restrict__ b_ih,
                           const float* __restrict__ b_hh)
{
    int row = blockIdx.x;
    if (row >= TQ * NQ) {
        int p = (row - TQ * NQ) * 256 + threadIdx.x;
        int orig = perm_orig(p);
        g_pbias[p] = b_ih[orig] + b_hh[orig];
        return;
    }
    int t = row / NQ + 1;
    int n = row % NQ;
    int qi = q[n * TQ + (t - 1)];
    float4 v = ((const float4*)(emb + (size_t)qi * EMBED))[threadIdx.x];
    size_t base4 = ((size_t)t * NQ + n) * (EMBED / 4) + threadIdx.x;
    ((uint2*)g_Xhi)[base4] = make_uint2(f16hi(v.x, v.y), f16hi(v.z, v.w));
}

__global__ void reduce_img(const float* __restrict__ b_img)
{
    int i = blockIdx.x * blockDim.x + threadIdx.x;   // pairs
    int row = i >> 9;
    int c2 = (i & 511) * 2;
    size_t o = (size_t)row * EMBED + c2;
    const size_t P = (size_t)NQ * EMBED;
    float x = g_part[o] + g_part[o + P] + g_part[o + 2 * P] + g_part[o + 3 * P]
              + b_img[c2];
    float y = g_part[o + 1] + g_part[o + 1 + P] + g_part[o + 1 + 2 * P]
              + g_part[o + 1 + 3 * P] + b_img[c2 + 1];
    ((u32*)g_Xhi)[o >> 1] = f16hi(x, y);
}

__global__ void zero_bar() { g_bar = 0u; }

// ===================== host =====================
extern "C" void kernel_launch(void* const* d_in, const int* in_sizes, int n_in,
                              void* d_out, int out_size)
{
    (void)in_sizes; (void)n_in; (void)out_size;
    const int*   questions = (const int*)  d_in[0];
    const float* img       = (const float*)d_in[1];
    const float* emb       = (const float*)d_in[2];
    const float* W_img     = (const float*)d_in[3];
    const float* b_img     = (const float*)d_in[4];
    const float* W_ih      = (const float*)d_in[5];
    const float* W_hh      = (const float*)d_in[6];
    const float* b_ih      = (const float*)d_in[7];
    const float* b_hh      = (const float*)d_in[8];
    const float* W_out     = (const float*)d_in[9];
    const float* b_out     = (const float*)d_in[10];

    float* out_logits = (float*)d_out;                        // [512, 32000]
    float* out_hs     = out_logits + (size_t)NQ * VOCAB;      // [512, 49, 1024]

    u16 *Xhi, *imgh, *Wimgh, *Wimgl, *Wihh, *Whhh, *Wouth, *hh0, *Xg16;
    float *pbias, *part;
    cudaGetSymbolAddress((void**)&Xhi,   g_Xhi);
    cudaGetSymbolAddress((void**)&imgh,  g_imgh);
    cudaGetSymbolAddress((void**)&Wimgh, g_Wimgh);
    cudaGetSymbolAddress((void**)&Wimgl, g_Wimgl);
    cudaGetSymbolAddress((void**)&Wihh,  g_Wihh);
    cudaGetSymbolAddress((void**)&Whhh,  g_Whhh);
    cudaGetSymbolAddress((void**)&Wouth, g_Wouth);
    cudaGetSymbolAddress((void**)&hh0,   g_hh0);
    cudaGetSymbolAddress((void**)&Xg16,  g_Xg16);
    cudaGetSymbolAddress((void**)&pbias, g_pbias);
    cudaGetSymbolAddress((void**)&part,  g_part);

    cudaFuncSetAttribute(tgemm<1>, cudaFuncAttributeMaxDynamicSharedMemorySize,
                         TG1_SMEM);
    cudaFuncSetAttribute(tgemm<2>, cudaFuncAttributeMaxDynamicSharedMemorySize,
                         TG2_SMEM);
    cudaFuncSetAttribute(lstm_persist,
                         cudaFuncAttributeMaxDynamicSharedMemorySize, LP_SMEM);

    // #0: gather embeddings (fp16) + permuted bias
    gather_emb<<<TQ * NQ + 16, 256>>>(questions, emb, b_ih, b_hh);

    // #1-2: conversions for the img GEMM
    conv_split<<<(NQ * IMG / 4 + 255) / 256, 256>>>(img, imgh, nullptr,
                                                    NQ * IMG / 4);
    conv_split<<<(HID * IMG / 4 + 255) / 256, 256>>>(W_img, Wimgh, Wimgl,
                                                     HID * IMG / 4);

    // #3 (ncu capture slot): img GEMM, 2-term, split-K=4 -> fp32 partials
    tgemm<2><<<dim3(EMBED / 128, NQ / 128, 4), 256, TG2_SMEM>>>(
        imgh, Wimgh, Wimgl, part, nullptr,
        NQ, EMBED, IMG / 4, IMG, nullptr, nullptr);

    // #4: reduce partials + b_img -> fp16 X[0]
    reduce_img<<<(NQ * EMBED / 2) / 256, 256>>>(b_img);

    // #5: permuted fp16 W_ih
    convp<<<G4, 256>>>(W_ih, Wihh, nullptr);

    // #6: Xg = X @ W_ihP^T + pbias  (1-term, fp16 output)
    tgemm<1><<<dim3(G4 / 128, (TS * NQ) / 128, 1), 256, TG1_SMEM>>>(
        Xhi, Wihh, nullptr, nullptr, Xg16,
        TS * NQ, G4, EMBED, EMBED, nullptr, pbias);

    // #7-8: permuted fp16 W_hh (hi only); reset device barrier
    convp<<<G4, 256>>>(W_hh, Whhh, nullptr);
    zero_bar<<<1, 1>>>();

    // #9: the whole recurrence in one persistent kernel (1-term)
    lstm_persist<<<128, 512, LP_SMEM>>>(Xg16, out_hs);

    // #10-11: logits = h_last @ W_out^T + b_out  (1-term; h_48 in buffer 0)
    conv_split<<<(VOCAB * HID / 4 + 255) / 256, 256>>>(W_out, Wouth, nullptr,
                                                       VOCAB * HID / 4);
    tgemm<1><<<dim3(VOCAB / 128, NQ / 128, 1), 256, TG1_SMEM>>>(
        hh0, Wouth, nullptr, out_logits, nullptr,
        NQ, VOCAB, HID, HID, nullptr, b_out);
}